// round 10
// baseline (speedup 1.0000x reference)
#include <cuda_runtime.h>
#include <cuda_bf16.h>
#include <cstdint>

// ============================================================================
// Problem constants
// ============================================================================
constexpr int B_    = 4;
constexpr int T_    = 2048;
constexpr int C_    = 1024;
constexpr int H_    = 16;
constexpr int DH_   = 64;
constexpr int M_    = B_ * T_;        // 8192
constexpr int N_QKV = 3 * C_;         // 3072
constexpr int K3_   = 3 * C_;         // 3072
constexpr int BH_   = B_ * H_;        // 64

// ============================================================================
// Scratch (__device__ globals; no cudaMalloc allowed)
// ============================================================================
__device__ __nv_bfloat16  g_x3[(size_t)M_ * K3_];         // [8192,3072] hi|lo|hi
__device__ __nv_bfloat16  g_att3[(size_t)M_ * K3_];       // [8192,3072] hi|lo|hi
__device__ __nv_bfloat16  g_wqkv3[(size_t)N_QKV * K3_];   // hi|hi|lo
__device__ __nv_bfloat16  g_wout3[(size_t)C_ * K3_];      // hi|hi|lo
__device__ __nv_bfloat16  g_qhi[(size_t)BH_ * T_ * DH_];  // [bh][t][d], pre-scaled
__device__ __nv_bfloat16  g_qlo[(size_t)BH_ * T_ * DH_];
__device__ __nv_bfloat16  g_khi[(size_t)BH_ * T_ * DH_];
__device__ __nv_bfloat16  g_klo[(size_t)BH_ * T_ * DH_];
__device__ __nv_bfloat16  g_vthi[(size_t)BH_ * DH_ * T_]; // [bh][d][t]
__device__ __nv_bfloat16  g_vtlo[(size_t)BH_ * DH_ * T_];

// ============================================================================
// PTX helpers (base-ISA only)
// ============================================================================
__device__ __forceinline__ uint32_t smem_to_u32(const void* smem_ptr) {
    uint32_t addr;
    asm("{ .reg .u64 tmp; cvta.to.shared.u64 tmp, %1; cvt.u32.u64 %0, tmp; }"
        : "=r"(addr) : "l"(smem_ptr));
    return addr;
}
__device__ __forceinline__ void ldsm_x4(uint32_t (&r)[4], uint32_t addr) {
    asm volatile("ldmatrix.sync.aligned.m8n8.x4.shared.b16 {%0,%1,%2,%3}, [%4];"
        : "=r"(r[0]), "=r"(r[1]), "=r"(r[2]), "=r"(r[3]) : "r"(addr));
}
__device__ __forceinline__ void mma_bf16(float (&d)[4],
                                         const uint32_t (&a)[4],
                                         const uint32_t (&b)[2]) {
    asm volatile(
        "mma.sync.aligned.m16n8k16.row.col.f32.bf16.bf16.f32 "
        "{%0,%1,%2,%3}, {%4,%5,%6,%7}, {%8,%9}, {%0,%1,%2,%3};"
        : "+f"(d[0]), "+f"(d[1]), "+f"(d[2]), "+f"(d[3])
        : "r"(a[0]), "r"(a[1]), "r"(a[2]), "r"(a[3]), "r"(b[0]), "r"(b[1]));
}
#define CP_ASYNC_16(dst_u32, src_ptr) \
    asm volatile("cp.async.cg.shared.global [%0], [%1], 16;" \
        :: "r"(dst_u32), "l"(src_ptr))
#define CP_ASYNC_COMMIT() asm volatile("cp.async.commit_group;" ::: "memory")
#define CP_ASYNC_WAIT_1() asm volatile("cp.async.wait_group 1;" ::: "memory")
#define CP_ASYNC_WAIT_0() asm volatile("cp.async.wait_group 0;" ::: "memory")

__device__ __forceinline__ uint32_t sw128(uint32_t off) {
    return off ^ ((off >> 3) & 0x70);
}

// ============================================================================
// Split fp32 -> 3-slab bf16 along K (hi|lo|hi for A, hi|hi|lo for B)
// ============================================================================
__global__ __launch_bounds__(256)
void split3_kernel(const float* __restrict__ in,
                   __nv_bfloat16* __restrict__ out3,
                   int K, int n4, int lo_slab)
{
    int i = blockIdx.x * blockDim.x + threadIdx.x;
    if (i >= n4) return;
    int e   = i * 4;
    int row = e / K;
    int col = e - row * K;
    float4 v = reinterpret_cast<const float4*>(in)[i];

    __nv_bfloat16 h0 = __float2bfloat16(v.x), h1 = __float2bfloat16(v.y);
    __nv_bfloat16 h2 = __float2bfloat16(v.z), h3 = __float2bfloat16(v.w);
    __nv_bfloat16 l0 = __float2bfloat16(v.x - __bfloat162float(h0));
    __nv_bfloat16 l1 = __float2bfloat16(v.y - __bfloat162float(h1));
    __nv_bfloat16 l2 = __float2bfloat16(v.z - __bfloat162float(h2));
    __nv_bfloat16 l3 = __float2bfloat16(v.w - __bfloat162float(h3));

    __nv_bfloat162 hA; hA.x = h0; hA.y = h1;
    __nv_bfloat162 hB; hB.x = h2; hB.y = h3;
    __nv_bfloat162 lA; lA.x = l0; lA.y = l1;
    __nv_bfloat162 lB; lB.x = l2; lB.y = l3;

    size_t base = (size_t)row * (3 * K) + col;
#pragma unroll
    for (int slab = 0; slab < 3; slab++) {
        __nv_bfloat162* p =
            reinterpret_cast<__nv_bfloat162*>(out3 + base + (size_t)slab * K);
        if (slab == lo_slab) { p[0] = lA; p[1] = lB; }
        else                 { p[0] = hA; p[1] = hB; }
    }
}

// ============================================================================
// GEMM: CTA tile 128x256, BK=64, 8 warps of 64x64 (MMA:LDSM = 4.0).
// 3-stage cp.async at 144KB smem, ONE barrier per K-chunk, 1 CTA/SM.
// ============================================================================
constexpr int BM = 128, BN = 256, BK = 64;
constexpr int TILEA     = BM * 128;            // 16 KB
constexpr int TILEB_B   = BN * 128;            // 32 KB
constexpr int STAGEB    = TILEA + TILEB_B;     // 48 KB
constexpr int GEMM_SMEM = 3 * STAGEB;          // 144 KB

__device__ __forceinline__ void gemm_issue_loads(
    const __nv_bfloat16* __restrict__ A, const __nv_bfloat16* __restrict__ Bm,
    int K, int m0, int n0, int kc, uint32_t abase, uint32_t bbase, int tid)
{
#pragma unroll
    for (int s = 0; s < 4; s++) {          // A: 128 rows x 8 chunks = 1024
        const int idx = tid + s * 256;
        const int r = idx >> 3;
        const int c = idx & 7;
        const uint32_t so = sw128((uint32_t)(r * 128 + c * 16));
        CP_ASYNC_16(abase + so, A + (size_t)(m0 + r) * K + kc + c * 8);
    }
#pragma unroll
    for (int s = 0; s < 8; s++) {          // B: 256 rows x 8 chunks = 2048
        const int idx = tid + s * 256;
        const int r = idx >> 3;
        const int c = idx & 7;
        const uint32_t so = sw128((uint32_t)(r * 128 + c * 16));
        CP_ASYNC_16(bbase + so, Bm + (size_t)(n0 + r) * K + kc + c * 8);
    }
}

__device__ __forceinline__ void gemm_mainloop(
    const __nv_bfloat16* __restrict__ A, const __nv_bfloat16* __restrict__ Bm,
    int K, int m0, int n0, uint32_t sbase, int tid, int wm, int wn, int lane,
    float (&acc)[4][8][4])
{
    const int NC = K / BK;

    gemm_issue_loads(A, Bm, K, m0, n0, 0, sbase, sbase + TILEA, tid);
    CP_ASYNC_COMMIT();
    if (NC > 1) {
        gemm_issue_loads(A, Bm, K, m0, n0, BK,
                         sbase + STAGEB, sbase + STAGEB + TILEA, tid);
    }
    CP_ASYNC_COMMIT();

    int stage = 0;
    for (int ch = 0; ch < NC; ch++) {
        if (ch < NC - 1) { CP_ASYNC_WAIT_1(); }
        else             { CP_ASYNC_WAIT_0(); }
        __syncthreads();

        if (ch + 2 < NC) {
            const int ns = (ch + 2) % 3;
            gemm_issue_loads(A, Bm, K, m0, n0, (ch + 2) * BK,
                             sbase + ns * STAGEB, sbase + ns * STAGEB + TILEA, tid);
            CP_ASYNC_COMMIT();
        }

        const uint32_t abase = sbase + stage * STAGEB;
        const uint32_t bbase = abase + TILEA;

#pragma unroll
        for (int ks = 0; ks < 4; ks++) {
            uint32_t afr[4][4];
#pragma unroll
            for (int mi = 0; mi < 4; mi++) {
                const int row = wm + mi * 16 + (lane & 15);
                const uint32_t off =
                    sw128((uint32_t)(row * 128 + ks * 32 + ((lane >> 4) & 1) * 16));
                ldsm_x4(afr[mi], abase + off);
            }
            uint32_t bfr[8][2];
#pragma unroll
            for (int np = 0; np < 4; np++) {
                const int row = wn + np * 16 + ((lane >> 4) & 1) * 8 + (lane & 7);
                const uint32_t off =
                    sw128((uint32_t)(row * 128 + ks * 32 + ((lane >> 3) & 1) * 16));
                uint32_t r4[4];
                ldsm_x4(r4, bbase + off);
                bfr[2 * np][0]     = r4[0]; bfr[2 * np][1]     = r4[1];
                bfr[2 * np + 1][0] = r4[2]; bfr[2 * np + 1][1] = r4[3];
            }
#pragma unroll
            for (int mi = 0; mi < 4; mi++)
#pragma unroll
                for (int ni = 0; ni < 8; ni++)
                    mma_bf16(acc[mi][ni], afr[mi], bfr[ni]);
        }
        stage = (stage + 1) % 3;
    }
    __syncthreads();   // protect smem reuse by epilogues
}

// ============================================================================
// Plain GEMM (fp32 output) — output projection.
// ============================================================================
__global__ __launch_bounds__(256, 1)
void gemm_mma_kernel(const __nv_bfloat16* __restrict__ A,
                     const __nv_bfloat16* __restrict__ Bm,
                     float* __restrict__ Cm,
                     int M, int N, int K)
{
    extern __shared__ char sm[];
    const int tid  = threadIdx.x;
    const int wid  = tid >> 5;
    const int lane = tid & 31;
    const int m0 = blockIdx.y * BM;
    const int n0 = blockIdx.x * BN;
    const int wm = (wid >> 2) * 64;      // 2 warp-rows
    const int wn = (wid & 3) * 64;       // 4 warp-cols

    float acc[4][8][4];
#pragma unroll
    for (int mi = 0; mi < 4; mi++)
#pragma unroll
        for (int ni = 0; ni < 8; ni++)
#pragma unroll
            for (int e = 0; e < 4; e++) acc[mi][ni][e] = 0.f;

    gemm_mainloop(A, Bm, K, m0, n0, smem_to_u32(sm), tid, wm, wn, lane, acc);

    const int g  = lane >> 2;
    const int tg = lane & 3;
#pragma unroll
    for (int mi = 0; mi < 4; mi++) {
#pragma unroll
        for (int ni = 0; ni < 8; ni++) {
            const int row = m0 + wm + mi * 16 + g;
            const int col = n0 + wn + ni * 8 + tg * 2;
            float2 p0; p0.x = acc[mi][ni][0]; p0.y = acc[mi][ni][1];
            float2 p1; p1.x = acc[mi][ni][2]; p1.y = acc[mi][ni][3];
            *reinterpret_cast<float2*>(&Cm[(size_t)row * N + col])       = p0;
            *reinterpret_cast<float2*>(&Cm[(size_t)(row + 8) * N + col]) = p1;
        }
    }
}

// ============================================================================
// QKV GEMM with fused attention-prep epilogue (two 128-col halves).
// ============================================================================
constexpr int SFS = 130;   // fp32 staging stride (even => float2 aligned)

__global__ __launch_bounds__(256, 1)
void gemm_qkv_fused_kernel(const __nv_bfloat16* __restrict__ A,
                           const __nv_bfloat16* __restrict__ Bm)
{
    extern __shared__ char sm[];
    const int tid  = threadIdx.x;
    const int wid  = tid >> 5;
    const int lane = tid & 31;
    const int m0 = blockIdx.y * BM;
    const int n0 = blockIdx.x * BN;
    const int wm = (wid >> 2) * 64;
    const int wn = (wid & 3) * 64;

    float acc[4][8][4];
#pragma unroll
    for (int mi = 0; mi < 4; mi++)
#pragma unroll
        for (int ni = 0; ni < 8; ni++)
#pragma unroll
            for (int e = 0; e < 4; e++) acc[mi][ni][e] = 0.f;

    gemm_mainloop(A, Bm, K3_, m0, n0, smem_to_u32(sm), tid, wm, wn, lane, acc);

    float* sf = reinterpret_cast<float*>(sm);
    const int g  = lane >> 2;
    const int tg = lane & 3;
    const int b  = m0 >> 11;
    const int t0 = m0 & 2047;

#pragma unroll
    for (int nh = 0; nh < 2; nh++) {
        // ---- stage this 128-col half into fp32 smem [128][SFS]
        if (((wid & 3) >> 1) == nh) {
            const int wn_loc = ((wid & 3) & 1) * 64;
#pragma unroll
            for (int mi = 0; mi < 4; mi++) {
#pragma unroll
                for (int ni = 0; ni < 8; ni++) {
                    const int row = wm + mi * 16 + g;
                    const int col = wn_loc + ni * 8 + tg * 2;
                    sf[row * SFS + col]           = acc[mi][ni][0];
                    sf[row * SFS + col + 1]       = acc[mi][ni][1];
                    sf[(row + 8) * SFS + col]     = acc[mi][ni][2];
                    sf[(row + 8) * SFS + col + 1] = acc[mi][ni][3];
                }
            }
        }
        __syncthreads();

        const int n0h    = n0 + nh * 128;
        const int region = n0h >> 10;          // 0=Q, 1=K, 2=V
        const int h2     = (n0h & 1023) >> 6;  // first of 2 heads in half
        const int w      = wid;

        if (region < 2) {
            __nv_bfloat16* dhi = (region == 0) ? g_qhi : g_khi;
            __nv_bfloat16* dlo = (region == 0) ? g_qlo : g_klo;
            const float scl = (region == 0) ? 0.125f : 1.0f;
#pragma unroll
            for (int i = 0; i < 16; i++) {
                const int t = w * 16 + i;
#pragma unroll
                for (int hh = 0; hh < 2; hh++) {
                    float2 v = *reinterpret_cast<float2*>(
                        &sf[t * SFS + hh * 64 + lane * 2]);
                    v.x *= scl; v.y *= scl;
                    __nv_bfloat162 hi2 = __floats2bfloat162_rn(v.x, v.y);
                    __nv_bfloat162 lo2 = __floats2bfloat162_rn(
                        v.x - __bfloat162float(hi2.x), v.y - __bfloat162float(hi2.y));
                    const int bh = b * 16 + h2 + hh;
                    const size_t off = ((size_t)bh * T_ + t0 + t) * DH_ + lane * 2;
                    *reinterpret_cast<__nv_bfloat162*>(dhi + off) = hi2;
                    *reinterpret_cast<__nv_bfloat162*>(dlo + off) = lo2;
                }
            }
        } else {
            // V: write transposed [bh][d][t]
#pragma unroll
            for (int i = 0; i < 16; i++) {
                const int fd = w * 16 + i;
                const int hh = fd >> 6;
                const int d  = fd & 63;
                const int bh = b * 16 + h2 + hh;
                const size_t rowbase = ((size_t)bh * DH_ + d) * T_ + t0;
#pragma unroll
                for (int j = 0; j < 4; j++) {
                    const int t = lane + 32 * j;
                    float v = sf[t * SFS + fd];
                    __nv_bfloat16 hv = __float2bfloat16(v);
                    __nv_bfloat16 lv = __float2bfloat16(v - __bfloat162float(hv));
                    g_vthi[rowbase + t] = hv;
                    g_vtlo[rowbase + t] = lv;
                }
            }
        }
        __syncthreads();
    }
}

// ============================================================================
// Tensor-core flash attention (causal), double-buffered K/V (unchanged R9).
// ============================================================================
constexpr int ATT_SMEM = 96 * 1024;
constexpr uint32_t OQHI = 0, OQLO = 16384, OKV = 32768, KVSTAGE = 32768;

__global__ __launch_bounds__(256, 2)
void attn_mma_kernel()
{
    extern __shared__ char sm[];
    const uint32_t sb = smem_to_u32(sm);

    const int tid  = threadIdx.x;
    const int w    = tid >> 5;
    const int lane = tid & 31;
    const int g    = lane >> 2;
    const int tq   = lane & 3;

    const int bh = blockIdx.y;
    const int b  = bh >> 4;
    const int h  = bh & 15;
    const int qt = gridDim.x - 1 - blockIdx.x;
    const int q0 = qt * 128;

    const __nv_bfloat16* khg = g_khi + (size_t)bh * T_ * DH_;
    const __nv_bfloat16* klg = g_klo + (size_t)bh * T_ * DH_;
    const __nv_bfloat16* vhg = g_vthi + (size_t)bh * DH_ * T_;
    const __nv_bfloat16* vlg = g_vtlo + (size_t)bh * DH_ * T_;

    {
        const __nv_bfloat16* qh = g_qhi + (size_t)(bh * T_ + q0) * DH_;
        const __nv_bfloat16* ql = g_qlo + (size_t)(bh * T_ + q0) * DH_;
#pragma unroll
        for (int it = 0; it < 4; it++) {
            const int idx = tid + it * 256;
            const int r = idx >> 3;
            const int c = idx & 7;
            const uint32_t so = sw128((uint32_t)(r * 128 + c * 16));
            CP_ASYNC_16(sb + OQHI + so, qh + (size_t)r * DH_ + c * 8);
            CP_ASYNC_16(sb + OQLO + so, ql + (size_t)r * DH_ + c * 8);
        }
        CP_ASYNC_COMMIT();
    }
    {
        const uint32_t kvb = sb + OKV;
#pragma unroll
        for (int it = 0; it < 2; it++) {
            const int idx = tid + it * 256;
            const int r = idx >> 3;
            const int c = idx & 7;
            const uint32_t so = sw128((uint32_t)(r * 128 + c * 16));
            CP_ASYNC_16(kvb + so,         khg + (size_t)r * DH_ + c * 8);
            CP_ASYNC_16(kvb + 8192 + so,  klg + (size_t)r * DH_ + c * 8);
            CP_ASYNC_16(kvb + 16384 + so, vhg + (size_t)r * T_ + c * 8);
            CP_ASYNC_16(kvb + 24576 + so, vlg + (size_t)r * T_ + c * 8);
        }
        CP_ASYNC_COMMIT();
    }

    float o[8][4];
#pragma unroll
    for (int ni = 0; ni < 8; ni++)
#pragma unroll
        for (int e = 0; e < 4; e++) o[ni][e] = 0.f;
    float m0 = -1e30f, m1 = -1e30f, l0 = 0.f, l1 = 0.f;

    const int row0 = q0 + 16 * w + g;
    const int kt_max = (q0 + 127) >> 6;

    for (int kt = 0; kt <= kt_max; kt++) {
        const int k0 = kt * 64;

        CP_ASYNC_WAIT_0();
        __syncthreads();

        if (kt + 1 <= kt_max) {
            const int nk0 = (kt + 1) * 64;
            const uint32_t kvb = sb + OKV + ((kt + 1) & 1) * KVSTAGE;
#pragma unroll
            for (int it = 0; it < 2; it++) {
                const int idx = tid + it * 256;
                const int r = idx >> 3;
                const int c = idx & 7;
                const uint32_t so = sw128((uint32_t)(r * 128 + c * 16));
                CP_ASYNC_16(kvb + so,         khg + (size_t)(nk0 + r) * DH_ + c * 8);
                CP_ASYNC_16(kvb + 8192 + so,  klg + (size_t)(nk0 + r) * DH_ + c * 8);
                CP_ASYNC_16(kvb + 16384 + so, vhg + (size_t)r * T_ + nk0 + c * 8);
                CP_ASYNC_16(kvb + 24576 + so, vlg + (size_t)r * T_ + nk0 + c * 8);
            }
            CP_ASYNC_COMMIT();
        }

        const uint32_t kvb = sb + OKV + (kt & 1) * KVSTAGE;
        const uint32_t okh = kvb, okl = kvb + 8192,
                       ovh = kvb + 16384, ovl = kvb + 24576;

        const bool active = (k0 <= q0 + 16 * w + 15);
        if (active) {
            float s[8][4];
#pragma unroll
            for (int ni = 0; ni < 8; ni++)
#pragma unroll
                for (int e = 0; e < 4; e++) s[ni][e] = 0.f;

#pragma unroll
            for (int ks = 0; ks < 4; ks++) {
                uint32_t aqh[4], aql[4];
                {
                    const int qr = 16 * w + (lane & 15);
                    const uint32_t off = sw128(
                        (uint32_t)(qr * 128 + ks * 32 + ((lane >> 4) & 1) * 16));
                    ldsm_x4(aqh, sb + OQHI + off);
                    ldsm_x4(aql, sb + OQLO + off);
                }
                uint32_t bkh[8][2], bkl[8][2];
#pragma unroll
                for (int p = 0; p < 4; p++) {
                    const int kr = p * 16 + ((lane >> 4) & 1) * 8 + (lane & 7);
                    const uint32_t off = sw128(
                        (uint32_t)(kr * 128 + ks * 32 + ((lane >> 3) & 1) * 16));
                    uint32_t r4[4];
                    ldsm_x4(r4, okh + off);
                    bkh[2 * p][0] = r4[0]; bkh[2 * p][1] = r4[1];
                    bkh[2 * p + 1][0] = r4[2]; bkh[2 * p + 1][1] = r4[3];
                    ldsm_x4(r4, okl + off);
                    bkl[2 * p][0] = r4[0]; bkl[2 * p][1] = r4[1];
                    bkl[2 * p + 1][0] = r4[2]; bkl[2 * p + 1][1] = r4[3];
                }
#pragma unroll
                for (int ni = 0; ni < 8; ni++) {
                    mma_bf16(s[ni], aqh, bkh[ni]);
                    mma_bf16(s[ni], aqh, bkl[ni]);
                    mma_bf16(s[ni], aql, bkh[ni]);
                }
            }

            if (k0 + 63 > q0 + 16 * w) {
#pragma unroll
                for (int ni = 0; ni < 8; ni++) {
                    const int kb = k0 + 8 * ni + 2 * tq;
                    if (kb     > row0)     s[ni][0] = -1e30f;
                    if (kb + 1 > row0)     s[ni][1] = -1e30f;
                    if (kb     > row0 + 8) s[ni][2] = -1e30f;
                    if (kb + 1 > row0 + 8) s[ni][3] = -1e30f;
                }
            }

            float mx0 = -1e30f, mx1 = -1e30f;
#pragma unroll
            for (int ni = 0; ni < 8; ni++) {
                mx0 = fmaxf(mx0, fmaxf(s[ni][0], s[ni][1]));
                mx1 = fmaxf(mx1, fmaxf(s[ni][2], s[ni][3]));
            }
            mx0 = fmaxf(mx0, __shfl_xor_sync(0xffffffffu, mx0, 1));
            mx0 = fmaxf(mx0, __shfl_xor_sync(0xffffffffu, mx0, 2));
            mx1 = fmaxf(mx1, __shfl_xor_sync(0xffffffffu, mx1, 1));
            mx1 = fmaxf(mx1, __shfl_xor_sync(0xffffffffu, mx1, 2));

            const float mn0 = fmaxf(m0, mx0);
            const float mn1 = fmaxf(m1, mx1);
            const float sc0 = __expf(m0 - mn0);
            const float sc1 = __expf(m1 - mn1);
            m0 = mn0; m1 = mn1;
            l0 *= sc0; l1 *= sc1;
#pragma unroll
            for (int ni = 0; ni < 8; ni++) {
                o[ni][0] *= sc0; o[ni][1] *= sc0;
                o[ni][2] *= sc1; o[ni][3] *= sc1;
            }

            uint32_t pH01[8], pH23[8], pL01[8], pL23[8];
#pragma unroll
            for (int ni = 0; ni < 8; ni++) {
                float p0 = __expf(s[ni][0] - mn0);
                float p1 = __expf(s[ni][1] - mn0);
                float p2 = __expf(s[ni][2] - mn1);
                float p3 = __expf(s[ni][3] - mn1);
                l0 += p0 + p1;
                l1 += p2 + p3;
                __nv_bfloat162 h01 = __floats2bfloat162_rn(p0, p1);
                __nv_bfloat162 h23 = __floats2bfloat162_rn(p2, p3);
                pH01[ni] = *reinterpret_cast<uint32_t*>(&h01);
                pH23[ni] = *reinterpret_cast<uint32_t*>(&h23);
                __nv_bfloat162 l01 = __floats2bfloat162_rn(
                    p0 - __bfloat162float(h01.x), p1 - __bfloat162float(h01.y));
                __nv_bfloat162 l23 = __floats2bfloat162_rn(
                    p2 - __bfloat162float(h23.x), p3 - __bfloat162float(h23.y));
                pL01[ni] = *reinterpret_cast<uint32_t*>(&l01);
                pL23[ni] = *reinterpret_cast<uint32_t*>(&l23);
            }

#pragma unroll
            for (int kg = 0; kg < 4; kg++) {
                uint32_t aph[4], apl[4];
                aph[0] = pH01[2 * kg];     aph[1] = pH23[2 * kg];
                aph[2] = pH01[2 * kg + 1]; aph[3] = pH23[2 * kg + 1];
                apl[0] = pL01[2 * kg];     apl[1] = pL23[2 * kg];
                apl[2] = pL01[2 * kg + 1]; apl[3] = pL23[2 * kg + 1];

                uint32_t bvh[8][2], bvl[8][2];
#pragma unroll
                for (int p = 0; p < 4; p++) {
                    const int dr = p * 16 + ((lane >> 4) & 1) * 8 + (lane & 7);
                    const uint32_t off = sw128(
                        (uint32_t)(dr * 128 + kg * 32 + ((lane >> 3) & 1) * 16));
                    uint32_t r4[4];
                    ldsm_x4(r4, ovh + off);
                    bvh[2 * p][0] = r4[0]; bvh[2 * p][1] = r4[1];
                    bvh[2 * p + 1][0] = r4[2]; bvh[2 * p + 1][1] = r4[3];
                    ldsm_x4(r4, ovl + off);
                    bvl[2 * p][0] = r4[0]; bvl[2 * p][1] = r4[1];
                    bvl[2 * p + 1][0] = r4[2]; bvl[2 * p + 1][1] = r4[3];
                }
#pragma unroll
                for (int ni = 0; ni < 8; ni++) {
                    mma_bf16(o[ni], aph, bvh[ni]);
                    mma_bf16(o[ni], apl, bvh[ni]);
                    mma_bf16(o[ni], aph, bvl[ni]);
                }
            }
        }
    }

    // ---- finalize: normalize, write 3-slab att3 (hi|lo|hi)
    l0 += __shfl_xor_sync(0xffffffffu, l0, 1);
    l0 += __shfl_xor_sync(0xffffffffu, l0, 2);
    l1 += __shfl_xor_sync(0xffffffffu, l1, 1);
    l1 += __shfl_xor_sync(0xffffffffu, l1, 2);
    const float inv0 = 1.f / l0;
    const float inv1 = 1.f / l1;

    const size_t rbase0 = (size_t)(b * T_ + row0) * K3_ + h * DH_;
    const size_t rbase1 = rbase0 + (size_t)8 * K3_;
#pragma unroll
    for (int ni = 0; ni < 8; ni++) {
        const int col = 8 * ni + 2 * tq;
        float p0 = o[ni][0] * inv0, p1 = o[ni][1] * inv0;
        float p2 = o[ni][2] * inv1, p3 = o[ni][3] * inv1;

        __nv_bfloat162 h01 = __floats2bfloat162_rn(p0, p1);
        __nv_bfloat162 l01 = __floats2bfloat162_rn(
            p0 - __bfloat162float(h01.x), p1 - __bfloat162float(h01.y));
        *reinterpret_cast<__nv_bfloat162*>(g_att3 + rbase0 + col)            = h01;
        *reinterpret_cast<__nv_bfloat162*>(g_att3 + rbase0 + C_ + col)       = l01;
        *reinterpret_cast<__nv_bfloat162*>(g_att3 + rbase0 + 2 * C_ + col)   = h01;

        __nv_bfloat162 h23 = __floats2bfloat162_rn(p2, p3);
        __nv_bfloat162 l23 = __floats2bfloat162_rn(
            p2 - __bfloat162float(h23.x), p3 - __bfloat162float(h23.y));
        *reinterpret_cast<__nv_bfloat162*>(g_att3 + rbase1 + col)            = h23;
        *reinterpret_cast<__nv_bfloat162*>(g_att3 + rbase1 + C_ + col)       = l23;
        *reinterpret_cast<__nv_bfloat162*>(g_att3 + rbase1 + 2 * C_ + col)   = h23;
    }
}

// ============================================================================
extern "C" void kernel_launch(void* const* d_in, const int* in_sizes, int n_in,
                              void* d_out, int out_size)
{
    const float* x     = (const float*)d_in[0];
    const float* w_qkv = (const float*)d_in[1];
    const float* w_out = (const float*)d_in[2];
    float*       out   = (float*)d_out;

    __nv_bfloat16 *x3, *att3, *wqkv3, *wout3;
    cudaGetSymbolAddress((void**)&x3,    g_x3);
    cudaGetSymbolAddress((void**)&att3,  g_att3);
    cudaGetSymbolAddress((void**)&wqkv3, g_wqkv3);
    cudaGetSymbolAddress((void**)&wout3, g_wout3);

    cudaFuncSetAttribute(gemm_mma_kernel,
                         cudaFuncAttributeMaxDynamicSharedMemorySize, GEMM_SMEM);
    cudaFuncSetAttribute(gemm_qkv_fused_kernel,
                         cudaFuncAttributeMaxDynamicSharedMemorySize, GEMM_SMEM);
    cudaFuncSetAttribute(attn_mma_kernel,
                         cudaFuncAttributeMaxDynamicSharedMemorySize, ATT_SMEM);

    // 0) split x and weights into 3-slab bf16
    {
        int n4 = (M_ * C_) / 4;
        split3_kernel<<<(n4 + 255) / 256, 256>>>(x, x3, C_, n4, 1);
        n4 = (N_QKV * C_) / 4;
        split3_kernel<<<(n4 + 255) / 256, 256>>>(w_qkv, wqkv3, C_, n4, 2);
        n4 = (C_ * C_) / 4;
        split3_kernel<<<(n4 + 255) / 256, 256>>>(w_out, wout3, C_, n4, 2);
    }
    // 1) QKV projection + fused attention prep
    {
        dim3 grid(N_QKV / BN, M_ / BM);
        gemm_qkv_fused_kernel<<<grid, 256, GEMM_SMEM>>>(x3, wqkv3);
    }
    // 2) tensor-core causal attention -> att3
    {
        dim3 grid(T_ / 128, BH_);
        attn_mma_kernel<<<grid, 256, ATT_SMEM>>>();
    }
    // 3) output projection
    {
        dim3 grid(C_ / BN, M_ / BM);
        gemm_mma_kernel<<<grid, 256, GEMM_SMEM>>>(att3, wout3, out, M_, C_, K3_);
    }
}

// round 11
// speedup vs baseline: 1.3685x; 1.3685x over previous
#include <cuda_runtime.h>
#include <cuda_fp16.h>
#include <cstdint>

// ============================================================================
// Problem constants
// ============================================================================
constexpr int B_    = 4;
constexpr int T_    = 2048;
constexpr int C_    = 1024;
constexpr int H_    = 16;
constexpr int DH_   = 64;
constexpr int M_    = B_ * T_;        // 8192
constexpr int N_QKV = 3 * C_;         // 3072
constexpr int K2_   = 2 * C_;         // 2048 (2-slab concatenated K)
constexpr int BH_   = B_ * H_;        // 64

// ============================================================================
// Scratch (__device__ globals; no cudaMalloc allowed)
// ============================================================================
__device__ __half  g_x2[(size_t)M_ * K2_];        // [8192,2048] hi|lo
__device__ __half  g_att2[(size_t)M_ * K2_];      // [8192,2048] hi|lo
__device__ __half  g_wqkv2[(size_t)N_QKV * K2_];  // hi|hi (dup)
__device__ __half  g_wout2[(size_t)C_ * K2_];     // hi|hi (dup)
__device__ __half  g_qhi[(size_t)BH_ * T_ * DH_]; // [bh][t][d], pre-scaled
__device__ __half  g_qlo[(size_t)BH_ * T_ * DH_];
__device__ __half  g_khi[(size_t)BH_ * T_ * DH_];
__device__ __half  g_klo[(size_t)BH_ * T_ * DH_];
__device__ __half  g_vthi[(size_t)BH_ * DH_ * T_]; // [bh][d][t]
__device__ __half  g_vtlo[(size_t)BH_ * DH_ * T_];

// ============================================================================
// PTX helpers (base-ISA only)
// ============================================================================
__device__ __forceinline__ uint32_t smem_to_u32(const void* smem_ptr) {
    uint32_t addr;
    asm("{ .reg .u64 tmp; cvta.to.shared.u64 tmp, %1; cvt.u32.u64 %0, tmp; }"
        : "=r"(addr) : "l"(smem_ptr));
    return addr;
}
__device__ __forceinline__ void ldsm_x4(uint32_t (&r)[4], uint32_t addr) {
    asm volatile("ldmatrix.sync.aligned.m8n8.x4.shared.b16 {%0,%1,%2,%3}, [%4];"
        : "=r"(r[0]), "=r"(r[1]), "=r"(r[2]), "=r"(r[3]) : "r"(addr));
}
__device__ __forceinline__ void mma_f16(float (&d)[4],
                                        const uint32_t (&a)[4],
                                        const uint32_t (&b)[2]) {
    asm volatile(
        "mma.sync.aligned.m16n8k16.row.col.f32.f16.f16.f32 "
        "{%0,%1,%2,%3}, {%4,%5,%6,%7}, {%8,%9}, {%0,%1,%2,%3};"
        : "+f"(d[0]), "+f"(d[1]), "+f"(d[2]), "+f"(d[3])
        : "r"(a[0]), "r"(a[1]), "r"(a[2]), "r"(a[3]), "r"(b[0]), "r"(b[1]));
}
#define CP_ASYNC_16(dst_u32, src_ptr) \
    asm volatile("cp.async.cg.shared.global [%0], [%1], 16;" \
        :: "r"(dst_u32), "l"(src_ptr))
#define CP_ASYNC_COMMIT() asm volatile("cp.async.commit_group;" ::: "memory")
#define CP_ASYNC_WAIT_1() asm volatile("cp.async.wait_group 1;" ::: "memory")
#define CP_ASYNC_WAIT_0() asm volatile("cp.async.wait_group 0;" ::: "memory")

__device__ __forceinline__ uint32_t sw128(uint32_t off) {
    return off ^ ((off >> 3) & 0x70);
}

// ============================================================================
// Split fp32 -> 2-slab fp16 along K.
//   dup_hi = 0 (A-type): [hi | lo]   (a = hi + lo to ~2^-22)
//   dup_hi = 1 (B-type): [hi | hi]
// ============================================================================
__global__ __launch_bounds__(256)
void split2_kernel(const float* __restrict__ in,
                   __half* __restrict__ out2,
                   int K, int n4, int dup_hi)
{
    int i = blockIdx.x * blockDim.x + threadIdx.x;
    if (i >= n4) return;
    int e   = i * 4;
    int row = e / K;
    int col = e - row * K;
    float4 v = reinterpret_cast<const float4*>(in)[i];

    __half h0 = __float2half_rn(v.x), h1 = __float2half_rn(v.y);
    __half h2 = __float2half_rn(v.z), h3 = __float2half_rn(v.w);

    __half2 hA; hA.x = h0; hA.y = h1;
    __half2 hB; hB.x = h2; hB.y = h3;

    size_t base = (size_t)row * (2 * K) + col;
    reinterpret_cast<__half2*>(out2 + base)[0] = hA;
    reinterpret_cast<__half2*>(out2 + base)[1] = hB;

    if (dup_hi) {
        reinterpret_cast<__half2*>(out2 + base + K)[0] = hA;
        reinterpret_cast<__half2*>(out2 + base + K)[1] = hB;
    } else {
        __half2 lA, lB;
        lA.x = __float2half_rn(v.x - __half2float(h0));
        lA.y = __float2half_rn(v.y - __half2float(h1));
        lB.x = __float2half_rn(v.z - __half2float(h2));
        lB.y = __float2half_rn(v.w - __half2float(h3));
        reinterpret_cast<__half2*>(out2 + base + K)[0] = lA;
        reinterpret_cast<__half2*>(out2 + base + K)[1] = lB;
    }
}

// ============================================================================
// GEMM mainloop (R8/R9 proven shape): 128x128 tile, BK=64, 3-stage cp.async,
// 8 warps of 64x32, one barrier per K-chunk, 2 CTAs/SM (128 regs).
// ============================================================================
constexpr int BM = 128, BN = 128, BK = 64;
constexpr int TILEB     = BM * 128;            // 16 KB
constexpr int STAGEB    = 2 * TILEB;           // 32 KB
constexpr int GEMM_SMEM = 3 * STAGEB;          // 96 KB

__device__ __forceinline__ void gemm_issue_loads(
    const __half* __restrict__ A, const __half* __restrict__ Bm,
    int K, int m0, int n0, int kc, uint32_t abase, uint32_t bbase, int tid)
{
#pragma unroll
    for (int s = 0; s < 4; s++) {
        const int idx = tid + s * 256;
        const int r = idx >> 3;
        const int c = idx & 7;
        const uint32_t so = sw128((uint32_t)(r * 128 + c * 16));
        CP_ASYNC_16(abase + so, A  + (size_t)(m0 + r) * K + kc + c * 8);
        CP_ASYNC_16(bbase + so, Bm + (size_t)(n0 + r) * K + kc + c * 8);
    }
}

__device__ __forceinline__ void gemm_mainloop(
    const __half* __restrict__ A, const __half* __restrict__ Bm,
    int K, int m0, int n0, uint32_t sbase, int tid, int wm, int wn, int lane,
    float (&acc)[4][4][4])
{
    const int NC = K / BK;

    gemm_issue_loads(A, Bm, K, m0, n0, 0, sbase, sbase + TILEB, tid);
    CP_ASYNC_COMMIT();
    if (NC > 1) {
        gemm_issue_loads(A, Bm, K, m0, n0, BK,
                         sbase + STAGEB, sbase + STAGEB + TILEB, tid);
    }
    CP_ASYNC_COMMIT();

    int stage = 0;
    for (int ch = 0; ch < NC; ch++) {
        if (ch < NC - 1) { CP_ASYNC_WAIT_1(); }
        else             { CP_ASYNC_WAIT_0(); }
        __syncthreads();

        if (ch + 2 < NC) {
            const int ns = (ch + 2) % 3;
            gemm_issue_loads(A, Bm, K, m0, n0, (ch + 2) * BK,
                             sbase + ns * STAGEB, sbase + ns * STAGEB + TILEB, tid);
            CP_ASYNC_COMMIT();
        }

        const uint32_t abase = sbase + stage * STAGEB;
        const uint32_t bbase = abase + TILEB;

#pragma unroll
        for (int ks = 0; ks < 4; ks++) {
            uint32_t afr[4][4];
#pragma unroll
            for (int mi = 0; mi < 4; mi++) {
                const int row = wm + mi * 16 + (lane & 15);
                const uint32_t off =
                    sw128((uint32_t)(row * 128 + ks * 32 + ((lane >> 4) & 1) * 16));
                ldsm_x4(afr[mi], abase + off);
            }
            uint32_t bfr[4][2];
#pragma unroll
            for (int np = 0; np < 2; np++) {
                const int row = wn + np * 16 + ((lane >> 4) & 1) * 8 + (lane & 7);
                const uint32_t off =
                    sw128((uint32_t)(row * 128 + ks * 32 + ((lane >> 3) & 1) * 16));
                uint32_t r4[4];
                ldsm_x4(r4, bbase + off);
                bfr[2 * np][0]     = r4[0]; bfr[2 * np][1]     = r4[1];
                bfr[2 * np + 1][0] = r4[2]; bfr[2 * np + 1][1] = r4[3];
            }
#pragma unroll
            for (int mi = 0; mi < 4; mi++)
#pragma unroll
                for (int ni = 0; ni < 4; ni++)
                    mma_f16(acc[mi][ni], afr[mi], bfr[ni]);
        }
        stage = (stage + 1) % 3;
    }
    __syncthreads();   // protect smem reuse by epilogues
}

// ============================================================================
// Plain GEMM (fp32 output) — output projection.
// ============================================================================
__global__ __launch_bounds__(256, 2)
void gemm_mma_kernel(const __half* __restrict__ A,
                     const __half* __restrict__ Bm,
                     float* __restrict__ Cm,
                     int M, int N, int K)
{
    extern __shared__ char sm[];
    const int tid  = threadIdx.x;
    const int wid  = tid >> 5;
    const int lane = tid & 31;
    const int m0 = blockIdx.y * BM;
    const int n0 = blockIdx.x * BN;
    const int wm = (wid & 1) * 64;
    const int wn = (wid >> 1) * 32;

    float acc[4][4][4];
#pragma unroll
    for (int mi = 0; mi < 4; mi++)
#pragma unroll
        for (int ni = 0; ni < 4; ni++)
#pragma unroll
            for (int e = 0; e < 4; e++) acc[mi][ni][e] = 0.f;

    gemm_mainloop(A, Bm, K, m0, n0, smem_to_u32(sm), tid, wm, wn, lane, acc);

    const int g  = lane >> 2;
    const int tg = lane & 3;
#pragma unroll
    for (int mi = 0; mi < 4; mi++) {
#pragma unroll
        for (int ni = 0; ni < 4; ni++) {
            const int row = m0 + wm + mi * 16 + g;
            const int col = n0 + wn + ni * 8 + tg * 2;
            float2 p0; p0.x = acc[mi][ni][0]; p0.y = acc[mi][ni][1];
            float2 p1; p1.x = acc[mi][ni][2]; p1.y = acc[mi][ni][3];
            *reinterpret_cast<float2*>(&Cm[(size_t)row * N + col])       = p0;
            *reinterpret_cast<float2*>(&Cm[(size_t)(row + 8) * N + col]) = p1;
        }
    }
}

// ============================================================================
// QKV GEMM with fused attention-prep epilogue (fp16 hi/lo outputs).
// Tile staged in smem fp32, stride 130 (even => float2 aligned).
// ============================================================================
constexpr int SFS = 130;

__global__ __launch_bounds__(256, 2)
void gemm_qkv_fused_kernel(const __half* __restrict__ A,
                           const __half* __restrict__ Bm)
{
    extern __shared__ char sm[];
    const int tid  = threadIdx.x;
    const int wid  = tid >> 5;
    const int lane = tid & 31;
    const int m0 = blockIdx.y * BM;
    const int n0 = blockIdx.x * BN;
    const int wm = (wid & 1) * 64;
    const int wn = (wid >> 1) * 32;

    float acc[4][4][4];
#pragma unroll
    for (int mi = 0; mi < 4; mi++)
#pragma unroll
        for (int ni = 0; ni < 4; ni++)
#pragma unroll
            for (int e = 0; e < 4; e++) acc[mi][ni][e] = 0.f;

    gemm_mainloop(A, Bm, K2_, m0, n0, smem_to_u32(sm), tid, wm, wn, lane, acc);

    float* sf = reinterpret_cast<float*>(sm);
    const int g  = lane >> 2;
    const int tg = lane & 3;
#pragma unroll
    for (int mi = 0; mi < 4; mi++) {
#pragma unroll
        for (int ni = 0; ni < 4; ni++) {
            const int row = wm + mi * 16 + g;
            const int col = wn + ni * 8 + tg * 2;
            sf[row * SFS + col]           = acc[mi][ni][0];
            sf[row * SFS + col + 1]       = acc[mi][ni][1];
            sf[(row + 8) * SFS + col]     = acc[mi][ni][2];
            sf[(row + 8) * SFS + col + 1] = acc[mi][ni][3];
        }
    }
    __syncthreads();

    const int region = n0 >> 10;          // 0=Q, 1=K, 2=V
    const int h2     = (n0 & 1023) >> 6;  // first of 2 heads in this tile
    const int b      = m0 >> 11;
    const int t0     = m0 & 2047;
    const int w      = wid;

    if (region < 2) {
        __half* dhi = (region == 0) ? g_qhi : g_khi;
        __half* dlo = (region == 0) ? g_qlo : g_klo;
        const float scl = (region == 0) ? 0.125f : 1.0f;
#pragma unroll
        for (int i = 0; i < 16; i++) {
            const int t = w * 16 + i;
#pragma unroll
            for (int hh = 0; hh < 2; hh++) {
                float2 v = *reinterpret_cast<float2*>(&sf[t * SFS + hh * 64 + lane * 2]);
                v.x *= scl; v.y *= scl;
                __half2 hi2 = __floats2half2_rn(v.x, v.y);
                __half2 lo2 = __floats2half2_rn(
                    v.x - __half2float(hi2.x), v.y - __half2float(hi2.y));
                const int bh = b * 16 + h2 + hh;
                const size_t off = ((size_t)bh * T_ + t0 + t) * DH_ + lane * 2;
                *reinterpret_cast<__half2*>(dhi + off) = hi2;
                *reinterpret_cast<__half2*>(dlo + off) = lo2;
            }
        }
    } else {
        // V: write transposed [bh][d][t]
#pragma unroll
        for (int i = 0; i < 16; i++) {
            const int fd = w * 16 + i;
            const int hh = fd >> 6;
            const int d  = fd & 63;
            const int bh = b * 16 + h2 + hh;
            const size_t rowbase = ((size_t)bh * DH_ + d) * T_ + t0;
#pragma unroll
            for (int j = 0; j < 4; j++) {
                const int t = lane + 32 * j;
                float v = sf[t * SFS + fd];
                __half hv = __float2half_rn(v);
                __half lv = __float2half_rn(v - __half2float(hv));
                g_vthi[rowbase + t] = hv;
                g_vtlo[rowbase + t] = lv;
            }
        }
    }
}

// ============================================================================
// Tensor-core flash attention (causal), fp16, 3-product, double-buffered K/V.
// Epilogue writes 2-slab att2 (hi|lo).
// ============================================================================
constexpr int ATT_SMEM = 96 * 1024;
constexpr uint32_t OQHI = 0, OQLO = 16384, OKV = 32768, KVSTAGE = 32768;

__global__ __launch_bounds__(256, 2)
void attn_mma_kernel()
{
    extern __shared__ char sm[];
    const uint32_t sb = smem_to_u32(sm);

    const int tid  = threadIdx.x;
    const int w    = tid >> 5;
    const int lane = tid & 31;
    const int g    = lane >> 2;
    const int tq   = lane & 3;

    const int bh = blockIdx.y;
    const int b  = bh >> 4;
    const int h  = bh & 15;
    const int qt = gridDim.x - 1 - blockIdx.x;
    const int q0 = qt * 128;

    const __half* khg = g_khi + (size_t)bh * T_ * DH_;
    const __half* klg = g_klo + (size_t)bh * T_ * DH_;
    const __half* vhg = g_vthi + (size_t)bh * DH_ * T_;
    const __half* vlg = g_vtlo + (size_t)bh * DH_ * T_;

    {
        const __half* qh = g_qhi + (size_t)(bh * T_ + q0) * DH_;
        const __half* ql = g_qlo + (size_t)(bh * T_ + q0) * DH_;
#pragma unroll
        for (int it = 0; it < 4; it++) {
            const int idx = tid + it * 256;
            const int r = idx >> 3;
            const int c = idx & 7;
            const uint32_t so = sw128((uint32_t)(r * 128 + c * 16));
            CP_ASYNC_16(sb + OQHI + so, qh + (size_t)r * DH_ + c * 8);
            CP_ASYNC_16(sb + OQLO + so, ql + (size_t)r * DH_ + c * 8);
        }
        CP_ASYNC_COMMIT();
    }
    {
        const uint32_t kvb = sb + OKV;
#pragma unroll
        for (int it = 0; it < 2; it++) {
            const int idx = tid + it * 256;
            const int r = idx >> 3;
            const int c = idx & 7;
            const uint32_t so = sw128((uint32_t)(r * 128 + c * 16));
            CP_ASYNC_16(kvb + so,         khg + (size_t)r * DH_ + c * 8);
            CP_ASYNC_16(kvb + 8192 + so,  klg + (size_t)r * DH_ + c * 8);
            CP_ASYNC_16(kvb + 16384 + so, vhg + (size_t)r * T_ + c * 8);
            CP_ASYNC_16(kvb + 24576 + so, vlg + (size_t)r * T_ + c * 8);
        }
        CP_ASYNC_COMMIT();
    }

    float o[8][4];
#pragma unroll
    for (int ni = 0; ni < 8; ni++)
#pragma unroll
        for (int e = 0; e < 4; e++) o[ni][e] = 0.f;
    float m0 = -1e30f, m1 = -1e30f, l0 = 0.f, l1 = 0.f;

    const int row0 = q0 + 16 * w + g;
    const int kt_max = (q0 + 127) >> 6;

    for (int kt = 0; kt <= kt_max; kt++) {
        const int k0 = kt * 64;

        CP_ASYNC_WAIT_0();
        __syncthreads();

        if (kt + 1 <= kt_max) {
            const int nk0 = (kt + 1) * 64;
            const uint32_t kvb = sb + OKV + ((kt + 1) & 1) * KVSTAGE;
#pragma unroll
            for (int it = 0; it < 2; it++) {
                const int idx = tid + it * 256;
                const int r = idx >> 3;
                const int c = idx & 7;
                const uint32_t so = sw128((uint32_t)(r * 128 + c * 16));
                CP_ASYNC_16(kvb + so,         khg + (size_t)(nk0 + r) * DH_ + c * 8);
                CP_ASYNC_16(kvb + 8192 + so,  klg + (size_t)(nk0 + r) * DH_ + c * 8);
                CP_ASYNC_16(kvb + 16384 + so, vhg + (size_t)r * T_ + nk0 + c * 8);
                CP_ASYNC_16(kvb + 24576 + so, vlg + (size_t)r * T_ + nk0 + c * 8);
            }
            CP_ASYNC_COMMIT();
        }

        const uint32_t kvb = sb + OKV + (kt & 1) * KVSTAGE;
        const uint32_t okh = kvb, okl = kvb + 8192,
                       ovh = kvb + 16384, ovl = kvb + 24576;

        const bool active = (k0 <= q0 + 16 * w + 15);
        if (active) {
            float s[8][4];
#pragma unroll
            for (int ni = 0; ni < 8; ni++)
#pragma unroll
                for (int e = 0; e < 4; e++) s[ni][e] = 0.f;

#pragma unroll
            for (int ks = 0; ks < 4; ks++) {
                uint32_t aqh[4], aql[4];
                {
                    const int qr = 16 * w + (lane & 15);
                    const uint32_t off = sw128(
                        (uint32_t)(qr * 128 + ks * 32 + ((lane >> 4) & 1) * 16));
                    ldsm_x4(aqh, sb + OQHI + off);
                    ldsm_x4(aql, sb + OQLO + off);
                }
                uint32_t bkh[8][2], bkl[8][2];
#pragma unroll
                for (int p = 0; p < 4; p++) {
                    const int kr = p * 16 + ((lane >> 4) & 1) * 8 + (lane & 7);
                    const uint32_t off = sw128(
                        (uint32_t)(kr * 128 + ks * 32 + ((lane >> 3) & 1) * 16));
                    uint32_t r4[4];
                    ldsm_x4(r4, okh + off);
                    bkh[2 * p][0] = r4[0]; bkh[2 * p][1] = r4[1];
                    bkh[2 * p + 1][0] = r4[2]; bkh[2 * p + 1][1] = r4[3];
                    ldsm_x4(r4, okl + off);
                    bkl[2 * p][0] = r4[0]; bkl[2 * p][1] = r4[1];
                    bkl[2 * p + 1][0] = r4[2]; bkl[2 * p + 1][1] = r4[3];
                }
#pragma unroll
                for (int ni = 0; ni < 8; ni++) {
                    mma_f16(s[ni], aqh, bkh[ni]);
                    mma_f16(s[ni], aqh, bkl[ni]);
                    mma_f16(s[ni], aql, bkh[ni]);
                }
            }

            if (k0 + 63 > q0 + 16 * w) {
#pragma unroll
                for (int ni = 0; ni < 8; ni++) {
                    const int kb = k0 + 8 * ni + 2 * tq;
                    if (kb     > row0)     s[ni][0] = -1e30f;
                    if (kb + 1 > row0)     s[ni][1] = -1e30f;
                    if (kb     > row0 + 8) s[ni][2] = -1e30f;
                    if (kb + 1 > row0 + 8) s[ni][3] = -1e30f;
                }
            }

            float mx0 = -1e30f, mx1 = -1e30f;
#pragma unroll
            for (int ni = 0; ni < 8; ni++) {
                mx0 = fmaxf(mx0, fmaxf(s[ni][0], s[ni][1]));
                mx1 = fmaxf(mx1, fmaxf(s[ni][2], s[ni][3]));
            }
            mx0 = fmaxf(mx0, __shfl_xor_sync(0xffffffffu, mx0, 1));
            mx0 = fmaxf(mx0, __shfl_xor_sync(0xffffffffu, mx0, 2));
            mx1 = fmaxf(mx1, __shfl_xor_sync(0xffffffffu, mx1, 1));
            mx1 = fmaxf(mx1, __shfl_xor_sync(0xffffffffu, mx1, 2));

            const float mn0 = fmaxf(m0, mx0);
            const float mn1 = fmaxf(m1, mx1);
            const float sc0 = __expf(m0 - mn0);
            const float sc1 = __expf(m1 - mn1);
            m0 = mn0; m1 = mn1;
            l0 *= sc0; l1 *= sc1;
#pragma unroll
            for (int ni = 0; ni < 8; ni++) {
                o[ni][0] *= sc0; o[ni][1] *= sc0;
                o[ni][2] *= sc1; o[ni][3] *= sc1;
            }

            uint32_t pH01[8], pH23[8], pL01[8], pL23[8];
#pragma unroll
            for (int ni = 0; ni < 8; ni++) {
                float p0 = __expf(s[ni][0] - mn0);
                float p1 = __expf(s[ni][1] - mn0);
                float p2 = __expf(s[ni][2] - mn1);
                float p3 = __expf(s[ni][3] - mn1);
                l0 += p0 + p1;
                l1 += p2 + p3;
                __half2 h01 = __floats2half2_rn(p0, p1);
                __half2 h23 = __floats2half2_rn(p2, p3);
                pH01[ni] = *reinterpret_cast<uint32_t*>(&h01);
                pH23[ni] = *reinterpret_cast<uint32_t*>(&h23);
                __half2 l01 = __floats2half2_rn(
                    p0 - __half2float(h01.x), p1 - __half2float(h01.y));
                __half2 l23 = __floats2half2_rn(
                    p2 - __half2float(h23.x), p3 - __half2float(h23.y));
                pL01[ni] = *reinterpret_cast<uint32_t*>(&l01);
                pL23[ni] = *reinterpret_cast<uint32_t*>(&l23);
            }

#pragma unroll
            for (int kg = 0; kg < 4; kg++) {
                uint32_t aph[4], apl[4];
                aph[0] = pH01[2 * kg];     aph[1] = pH23[2 * kg];
                aph[2] = pH01[2 * kg + 1]; aph[3] = pH23[2 * kg + 1];
                apl[0] = pL01[2 * kg];     apl[1] = pL23[2 * kg];
                apl[2] = pL01[2 * kg + 1]; apl[3] = pL23[2 * kg + 1];

                uint32_t bvh[8][2], bvl[8][2];
#pragma unroll
                for (int p = 0; p < 4; p++) {
                    const int dr = p * 16 + ((lane >> 4) & 1) * 8 + (lane & 7);
                    const uint32_t off = sw128(
                        (uint32_t)(dr * 128 + kg * 32 + ((lane >> 3) & 1) * 16));
                    uint32_t r4[4];
                    ldsm_x4(r4, ovh + off);
                    bvh[2 * p][0] = r4[0]; bvh[2 * p][1] = r4[1];
                    bvh[2 * p + 1][0] = r4[2]; bvh[2 * p + 1][1] = r4[3];
                    ldsm_x4(r4, ovl + off);
                    bvl[2 * p][0] = r4[0]; bvl[2 * p][1] = r4[1];
                    bvl[2 * p + 1][0] = r4[2]; bvl[2 * p + 1][1] = r4[3];
                }
#pragma unroll
                for (int ni = 0; ni < 8; ni++) {
                    mma_f16(o[ni], aph, bvh[ni]);
                    mma_f16(o[ni], apl, bvh[ni]);
                    mma_f16(o[ni], aph, bvl[ni]);
                }
            }
        }
    }

    // ---- finalize: normalize, write 2-slab att2 (hi|lo)
    l0 += __shfl_xor_sync(0xffffffffu, l0, 1);
    l0 += __shfl_xor_sync(0xffffffffu, l0, 2);
    l1 += __shfl_xor_sync(0xffffffffu, l1, 1);
    l1 += __shfl_xor_sync(0xffffffffu, l1, 2);
    const float inv0 = 1.f / l0;
    const float inv1 = 1.f / l1;

    const size_t rbase0 = (size_t)(b * T_ + row0) * K2_ + h * DH_;
    const size_t rbase1 = rbase0 + (size_t)8 * K2_;
#pragma unroll
    for (int ni = 0; ni < 8; ni++) {
        const int col = 8 * ni + 2 * tq;
        float p0 = o[ni][0] * inv0, p1 = o[ni][1] * inv0;
        float p2 = o[ni][2] * inv1, p3 = o[ni][3] * inv1;

        __half2 h01 = __floats2half2_rn(p0, p1);
        __half2 l01 = __floats2half2_rn(
            p0 - __half2float(h01.x), p1 - __half2float(h01.y));
        *reinterpret_cast<__half2*>(g_att2 + rbase0 + col)      = h01;
        *reinterpret_cast<__half2*>(g_att2 + rbase0 + C_ + col) = l01;

        __half2 h23 = __floats2half2_rn(p2, p3);
        __half2 l23 = __floats2half2_rn(
            p2 - __half2float(h23.x), p3 - __half2float(h23.y));
        *reinterpret_cast<__half2*>(g_att2 + rbase1 + col)      = h23;
        *reinterpret_cast<__half2*>(g_att2 + rbase1 + C_ + col) = l23;
    }
}

// ============================================================================
extern "C" void kernel_launch(void* const* d_in, const int* in_sizes, int n_in,
                              void* d_out, int out_size)
{
    const float* x     = (const float*)d_in[0];
    const float* w_qkv = (const float*)d_in[1];
    const float* w_out = (const float*)d_in[2];
    float*       out   = (float*)d_out;

    __half *x2, *att2, *wqkv2, *wout2;
    cudaGetSymbolAddress((void**)&x2,    g_x2);
    cudaGetSymbolAddress((void**)&att2,  g_att2);
    cudaGetSymbolAddress((void**)&wqkv2, g_wqkv2);
    cudaGetSymbolAddress((void**)&wout2, g_wout2);

    cudaFuncSetAttribute(gemm_mma_kernel,
                         cudaFuncAttributeMaxDynamicSharedMemorySize, GEMM_SMEM);
    cudaFuncSetAttribute(gemm_qkv_fused_kernel,
                         cudaFuncAttributeMaxDynamicSharedMemorySize, GEMM_SMEM);
    cudaFuncSetAttribute(attn_mma_kernel,
                         cudaFuncAttributeMaxDynamicSharedMemorySize, ATT_SMEM);

    // 0) split x (hi|lo) and weights (hi|hi) into 2-slab fp16
    {
        int n4 = (M_ * C_) / 4;
        split2_kernel<<<(n4 + 255) / 256, 256>>>(x, x2, C_, n4, 0);
        n4 = (N_QKV * C_) / 4;
        split2_kernel<<<(n4 + 255) / 256, 256>>>(w_qkv, wqkv2, C_, n4, 1);
        n4 = (C_ * C_) / 4;
        split2_kernel<<<(n4 + 255) / 256, 256>>>(w_out, wout2, C_, n4, 1);
    }
    // 1) QKV projection + fused attention prep
    {
        dim3 grid(N_QKV / BN, M_ / BM);
        gemm_qkv_fused_kernel<<<grid, 256, GEMM_SMEM>>>(x2, wqkv2);
    }
    // 2) tensor-core causal attention -> att2 (2-slab, fused split)
    {
        dim3 grid(T_ / 128, BH_);
        attn_mma_kernel<<<grid, 256, ATT_SMEM>>>();
    }
    // 3) output projection
    {
        dim3 grid(C_ / BN, M_ / BM);
        gemm_mma_kernel<<<grid, 256, GEMM_SMEM>>>(att2, wout2, out, M_, C_, K2_);
    }
}

// round 12
// speedup vs baseline: 1.5750x; 1.1509x over previous
#include <cuda_runtime.h>
#include <cuda_fp16.h>
#include <cstdint>

// ============================================================================
// Problem constants
// ============================================================================
constexpr int B_    = 4;
constexpr int T_    = 2048;
constexpr int C_    = 1024;
constexpr int H_    = 16;
constexpr int DH_   = 64;
constexpr int M_    = B_ * T_;        // 8192
constexpr int N_QKV = 3 * C_;         // 3072
constexpr int K2_   = 2 * C_;         // 2048 (2-slab concatenated K)
constexpr int BH_   = B_ * H_;        // 64

// ============================================================================
// Scratch (__device__ globals; no cudaMalloc allowed)
// ============================================================================
__device__ __half  g_x2[(size_t)M_ * K2_];        // [8192,2048] hi|lo
__device__ __half  g_att2[(size_t)M_ * K2_];      // [8192,2048] hi|lo
__device__ __half  g_wqkv2[(size_t)N_QKV * K2_];  // hi|hi (dup)
__device__ __half  g_wout2[(size_t)C_ * K2_];     // hi|hi (dup)
__device__ __half  g_qhi[(size_t)BH_ * T_ * DH_]; // [bh][t][d], pre-scaled
__device__ __half  g_qlo[(size_t)BH_ * T_ * DH_];
__device__ __half  g_khi[(size_t)BH_ * T_ * DH_]; // hi only (2-product QK^T)
__device__ __half  g_vthi[(size_t)BH_ * DH_ * T_]; // [bh][d][t], hi only

// ============================================================================
// PTX helpers (base-ISA only)
// ============================================================================
__device__ __forceinline__ uint32_t smem_to_u32(const void* smem_ptr) {
    uint32_t addr;
    asm("{ .reg .u64 tmp; cvta.to.shared.u64 tmp, %1; cvt.u32.u64 %0, tmp; }"
        : "=r"(addr) : "l"(smem_ptr));
    return addr;
}
__device__ __forceinline__ void ldsm_x4(uint32_t (&r)[4], uint32_t addr) {
    asm volatile("ldmatrix.sync.aligned.m8n8.x4.shared.b16 {%0,%1,%2,%3}, [%4];"
        : "=r"(r[0]), "=r"(r[1]), "=r"(r[2]), "=r"(r[3]) : "r"(addr));
}
__device__ __forceinline__ void mma_f16(float (&d)[4],
                                        const uint32_t (&a)[4],
                                        const uint32_t (&b)[2]) {
    asm volatile(
        "mma.sync.aligned.m16n8k16.row.col.f32.f16.f16.f32 "
        "{%0,%1,%2,%3}, {%4,%5,%6,%7}, {%8,%9}, {%0,%1,%2,%3};"
        : "+f"(d[0]), "+f"(d[1]), "+f"(d[2]), "+f"(d[3])
        : "r"(a[0]), "r"(a[1]), "r"(a[2]), "r"(a[3]), "r"(b[0]), "r"(b[1]));
}
#define CP_ASYNC_16(dst_u32, src_ptr) \
    asm volatile("cp.async.cg.shared.global [%0], [%1], 16;" \
        :: "r"(dst_u32), "l"(src_ptr))
#define CP_ASYNC_COMMIT() asm volatile("cp.async.commit_group;" ::: "memory")
#define CP_ASYNC_WAIT_1() asm volatile("cp.async.wait_group 1;" ::: "memory")
#define CP_ASYNC_WAIT_0() asm volatile("cp.async.wait_group 0;" ::: "memory")

__device__ __forceinline__ uint32_t sw128(uint32_t off) {
    return off ^ ((off >> 3) & 0x70);
}

// ============================================================================
// Split fp32 -> 2-slab fp16 along K. dup_hi=0: [hi|lo]; dup_hi=1: [hi|hi]
// ============================================================================
__global__ __launch_bounds__(256)
void split2_kernel(const float* __restrict__ in,
                   __half* __restrict__ out2,
                   int K, int n4, int dup_hi)
{
    int i = blockIdx.x * blockDim.x + threadIdx.x;
    if (i >= n4) return;
    int e   = i * 4;
    int row = e / K;
    int col = e - row * K;
    float4 v = reinterpret_cast<const float4*>(in)[i];

    __half h0 = __float2half_rn(v.x), h1 = __float2half_rn(v.y);
    __half h2 = __float2half_rn(v.z), h3 = __float2half_rn(v.w);

    __half2 hA; hA.x = h0; hA.y = h1;
    __half2 hB; hB.x = h2; hB.y = h3;

    size_t base = (size_t)row * (2 * K) + col;
    reinterpret_cast<__half2*>(out2 + base)[0] = hA;
    reinterpret_cast<__half2*>(out2 + base)[1] = hB;

    if (dup_hi) {
        reinterpret_cast<__half2*>(out2 + base + K)[0] = hA;
        reinterpret_cast<__half2*>(out2 + base + K)[1] = hB;
    } else {
        __half2 lA, lB;
        lA.x = __float2half_rn(v.x - __half2float(h0));
        lA.y = __float2half_rn(v.y - __half2float(h1));
        lB.x = __float2half_rn(v.z - __half2float(h2));
        lB.y = __float2half_rn(v.w - __half2float(h3));
        reinterpret_cast<__half2*>(out2 + base + K)[0] = lA;
        reinterpret_cast<__half2*>(out2 + base + K)[1] = lB;
    }
}

// ============================================================================
// GEMM mainloop: 128x128 tile, BK=64, 3-stage cp.async, 8 warps of 64x32,
// one barrier per K-chunk, 2 CTAs/SM (128 regs).
// ============================================================================
constexpr int BM = 128, BN = 128, BK = 64;
constexpr int TILEB     = BM * 128;            // 16 KB
constexpr int STAGEB    = 2 * TILEB;           // 32 KB
constexpr int GEMM_SMEM = 3 * STAGEB;          // 96 KB

__device__ __forceinline__ void gemm_issue_loads(
    const __half* __restrict__ A, const __half* __restrict__ Bm,
    int K, int m0, int n0, int kc, uint32_t abase, uint32_t bbase, int tid)
{
#pragma unroll
    for (int s = 0; s < 4; s++) {
        const int idx = tid + s * 256;
        const int r = idx >> 3;
        const int c = idx & 7;
        const uint32_t so = sw128((uint32_t)(r * 128 + c * 16));
        CP_ASYNC_16(abase + so, A  + (size_t)(m0 + r) * K + kc + c * 8);
        CP_ASYNC_16(bbase + so, Bm + (size_t)(n0 + r) * K + kc + c * 8);
    }
}

__device__ __forceinline__ void gemm_mainloop(
    const __half* __restrict__ A, const __half* __restrict__ Bm,
    int K, int m0, int n0, uint32_t sbase, int tid, int wm, int wn, int lane,
    float (&acc)[4][4][4])
{
    const int NC = K / BK;

    gemm_issue_loads(A, Bm, K, m0, n0, 0, sbase, sbase + TILEB, tid);
    CP_ASYNC_COMMIT();
    if (NC > 1) {
        gemm_issue_loads(A, Bm, K, m0, n0, BK,
                         sbase + STAGEB, sbase + STAGEB + TILEB, tid);
    }
    CP_ASYNC_COMMIT();

    int stage = 0;
    for (int ch = 0; ch < NC; ch++) {
        if (ch < NC - 1) { CP_ASYNC_WAIT_1(); }
        else             { CP_ASYNC_WAIT_0(); }
        __syncthreads();

        if (ch + 2 < NC) {
            const int ns = (ch + 2) % 3;
            gemm_issue_loads(A, Bm, K, m0, n0, (ch + 2) * BK,
                             sbase + ns * STAGEB, sbase + ns * STAGEB + TILEB, tid);
            CP_ASYNC_COMMIT();
        }

        const uint32_t abase = sbase + stage * STAGEB;
        const uint32_t bbase = abase + TILEB;

#pragma unroll
        for (int ks = 0; ks < 4; ks++) {
            uint32_t afr[4][4];
#pragma unroll
            for (int mi = 0; mi < 4; mi++) {
                const int row = wm + mi * 16 + (lane & 15);
                const uint32_t off =
                    sw128((uint32_t)(row * 128 + ks * 32 + ((lane >> 4) & 1) * 16));
                ldsm_x4(afr[mi], abase + off);
            }
            uint32_t bfr[4][2];
#pragma unroll
            for (int np = 0; np < 2; np++) {
                const int row = wn + np * 16 + ((lane >> 4) & 1) * 8 + (lane & 7);
                const uint32_t off =
                    sw128((uint32_t)(row * 128 + ks * 32 + ((lane >> 3) & 1) * 16));
                uint32_t r4[4];
                ldsm_x4(r4, bbase + off);
                bfr[2 * np][0]     = r4[0]; bfr[2 * np][1]     = r4[1];
                bfr[2 * np + 1][0] = r4[2]; bfr[2 * np + 1][1] = r4[3];
            }
#pragma unroll
            for (int mi = 0; mi < 4; mi++)
#pragma unroll
                for (int ni = 0; ni < 4; ni++)
                    mma_f16(acc[mi][ni], afr[mi], bfr[ni]);
        }
        stage = (stage + 1) % 3;
    }
    __syncthreads();   // protect smem reuse by epilogues
}

// ============================================================================
// Plain GEMM (fp32 output) — output projection.
// ============================================================================
__global__ __launch_bounds__(256, 2)
void gemm_mma_kernel(const __half* __restrict__ A,
                     const __half* __restrict__ Bm,
                     float* __restrict__ Cm,
                     int M, int N, int K)
{
    extern __shared__ char sm[];
    const int tid  = threadIdx.x;
    const int wid  = tid >> 5;
    const int lane = tid & 31;
    const int m0 = blockIdx.y * BM;
    const int n0 = blockIdx.x * BN;
    const int wm = (wid & 1) * 64;
    const int wn = (wid >> 1) * 32;

    float acc[4][4][4];
#pragma unroll
    for (int mi = 0; mi < 4; mi++)
#pragma unroll
        for (int ni = 0; ni < 4; ni++)
#pragma unroll
            for (int e = 0; e < 4; e++) acc[mi][ni][e] = 0.f;

    gemm_mainloop(A, Bm, K, m0, n0, smem_to_u32(sm), tid, wm, wn, lane, acc);

    const int g  = lane >> 2;
    const int tg = lane & 3;
#pragma unroll
    for (int mi = 0; mi < 4; mi++) {
#pragma unroll
        for (int ni = 0; ni < 4; ni++) {
            const int row = m0 + wm + mi * 16 + g;
            const int col = n0 + wn + ni * 8 + tg * 2;
            float2 p0; p0.x = acc[mi][ni][0]; p0.y = acc[mi][ni][1];
            float2 p1; p1.x = acc[mi][ni][2]; p1.y = acc[mi][ni][3];
            *reinterpret_cast<float2*>(&Cm[(size_t)row * N + col])       = p0;
            *reinterpret_cast<float2*>(&Cm[(size_t)(row + 8) * N + col]) = p1;
        }
    }
}

// ============================================================================
// QKV GEMM with fused attention-prep epilogue.
// Q -> hi+lo (scaled). K -> hi only. V -> transposed hi only.
// ============================================================================
constexpr int SFS = 130;

__global__ __launch_bounds__(256, 2)
void gemm_qkv_fused_kernel(const __half* __restrict__ A,
                           const __half* __restrict__ Bm)
{
    extern __shared__ char sm[];
    const int tid  = threadIdx.x;
    const int wid  = tid >> 5;
    const int lane = tid & 31;
    const int m0 = blockIdx.y * BM;
    const int n0 = blockIdx.x * BN;
    const int wm = (wid & 1) * 64;
    const int wn = (wid >> 1) * 32;

    float acc[4][4][4];
#pragma unroll
    for (int mi = 0; mi < 4; mi++)
#pragma unroll
        for (int ni = 0; ni < 4; ni++)
#pragma unroll
            for (int e = 0; e < 4; e++) acc[mi][ni][e] = 0.f;

    gemm_mainloop(A, Bm, K2_, m0, n0, smem_to_u32(sm), tid, wm, wn, lane, acc);

    float* sf = reinterpret_cast<float*>(sm);
    const int g  = lane >> 2;
    const int tg = lane & 3;
#pragma unroll
    for (int mi = 0; mi < 4; mi++) {
#pragma unroll
        for (int ni = 0; ni < 4; ni++) {
            const int row = wm + mi * 16 + g;
            const int col = wn + ni * 8 + tg * 2;
            sf[row * SFS + col]           = acc[mi][ni][0];
            sf[row * SFS + col + 1]       = acc[mi][ni][1];
            sf[(row + 8) * SFS + col]     = acc[mi][ni][2];
            sf[(row + 8) * SFS + col + 1] = acc[mi][ni][3];
        }
    }
    __syncthreads();

    const int region = n0 >> 10;          // 0=Q, 1=K, 2=V
    const int h2     = (n0 & 1023) >> 6;  // first of 2 heads in this tile
    const int b      = m0 >> 11;
    const int t0     = m0 & 2047;
    const int w      = wid;

    if (region == 0) {
        // Q: scaled hi + lo
#pragma unroll
        for (int i = 0; i < 16; i++) {
            const int t = w * 16 + i;
#pragma unroll
            for (int hh = 0; hh < 2; hh++) {
                float2 v = *reinterpret_cast<float2*>(&sf[t * SFS + hh * 64 + lane * 2]);
                v.x *= 0.125f; v.y *= 0.125f;
                __half2 hi2 = __floats2half2_rn(v.x, v.y);
                __half2 lo2 = __floats2half2_rn(
                    v.x - __half2float(hi2.x), v.y - __half2float(hi2.y));
                const int bh = b * 16 + h2 + hh;
                const size_t off = ((size_t)bh * T_ + t0 + t) * DH_ + lane * 2;
                *reinterpret_cast<__half2*>(g_qhi + off) = hi2;
                *reinterpret_cast<__half2*>(g_qlo + off) = lo2;
            }
        }
    } else if (region == 1) {
        // K: hi only
#pragma unroll
        for (int i = 0; i < 16; i++) {
            const int t = w * 16 + i;
#pragma unroll
            for (int hh = 0; hh < 2; hh++) {
                float2 v = *reinterpret_cast<float2*>(&sf[t * SFS + hh * 64 + lane * 2]);
                __half2 hi2 = __floats2half2_rn(v.x, v.y);
                const int bh = b * 16 + h2 + hh;
                const size_t off = ((size_t)bh * T_ + t0 + t) * DH_ + lane * 2;
                *reinterpret_cast<__half2*>(g_khi + off) = hi2;
            }
        }
    } else {
        // V: write transposed [bh][d][t], hi only
#pragma unroll
        for (int i = 0; i < 16; i++) {
            const int fd = w * 16 + i;
            const int hh = fd >> 6;
            const int d  = fd & 63;
            const int bh = b * 16 + h2 + hh;
            const size_t rowbase = ((size_t)bh * DH_ + d) * T_ + t0;
#pragma unroll
            for (int j = 0; j < 4; j++) {
                const int t = lane + 32 * j;
                g_vthi[rowbase + t] = __float2half_rn(sf[t * SFS + fd]);
            }
        }
    }
}

// ============================================================================
// Tensor-core flash attention (causal), fp16 2-product, double-buffered K/V.
// S = (Qhi+Qlo) Khi^T ; O = (Phi+Plo) Vhi. Epilogue writes 2-slab att2.
// smem: Q 32KB + 2 stages x (Khi 8KB + Vhi 8KB) = 64KB.
// ============================================================================
constexpr int ATT_SMEM = 64 * 1024;
constexpr uint32_t OQHI = 0, OQLO = 16384, OKV = 32768, KVSTAGE = 16384;

__global__ __launch_bounds__(256, 2)
void attn_mma_kernel()
{
    extern __shared__ char sm[];
    const uint32_t sb = smem_to_u32(sm);

    const int tid  = threadIdx.x;
    const int w    = tid >> 5;
    const int lane = tid & 31;
    const int g    = lane >> 2;
    const int tq   = lane & 3;

    const int bh = blockIdx.y;
    const int b  = bh >> 4;
    const int h  = bh & 15;
    const int qt = gridDim.x - 1 - blockIdx.x;
    const int q0 = qt * 128;

    const __half* khg = g_khi + (size_t)bh * T_ * DH_;
    const __half* vhg = g_vthi + (size_t)bh * DH_ * T_;

    // prologue: Q (group 0), KV tile 0 (group 1)
    {
        const __half* qh = g_qhi + (size_t)(bh * T_ + q0) * DH_;
        const __half* ql = g_qlo + (size_t)(bh * T_ + q0) * DH_;
#pragma unroll
        for (int it = 0; it < 4; it++) {
            const int idx = tid + it * 256;
            const int r = idx >> 3;
            const int c = idx & 7;
            const uint32_t so = sw128((uint32_t)(r * 128 + c * 16));
            CP_ASYNC_16(sb + OQHI + so, qh + (size_t)r * DH_ + c * 8);
            CP_ASYNC_16(sb + OQLO + so, ql + (size_t)r * DH_ + c * 8);
        }
        CP_ASYNC_COMMIT();
    }
    {
        const uint32_t kvb = sb + OKV;
#pragma unroll
        for (int it = 0; it < 2; it++) {
            const int idx = tid + it * 256;
            const int r = idx >> 3;
            const int c = idx & 7;
            const uint32_t so = sw128((uint32_t)(r * 128 + c * 16));
            CP_ASYNC_16(kvb + so,        khg + (size_t)r * DH_ + c * 8);
            CP_ASYNC_16(kvb + 8192 + so, vhg + (size_t)r * T_ + c * 8);
        }
        CP_ASYNC_COMMIT();
    }

    float o[8][4];
#pragma unroll
    for (int ni = 0; ni < 8; ni++)
#pragma unroll
        for (int e = 0; e < 4; e++) o[ni][e] = 0.f;
    float m0 = -1e30f, m1 = -1e30f, l0 = 0.f, l1 = 0.f;

    const int row0 = q0 + 16 * w + g;
    const int kt_max = (q0 + 127) >> 6;

    for (int kt = 0; kt <= kt_max; kt++) {
        const int k0 = kt * 64;

        CP_ASYNC_WAIT_0();
        __syncthreads();

        if (kt + 1 <= kt_max) {
            const int nk0 = (kt + 1) * 64;
            const uint32_t kvb = sb + OKV + ((kt + 1) & 1) * KVSTAGE;
#pragma unroll
            for (int it = 0; it < 2; it++) {
                const int idx = tid + it * 256;
                const int r = idx >> 3;
                const int c = idx & 7;
                const uint32_t so = sw128((uint32_t)(r * 128 + c * 16));
                CP_ASYNC_16(kvb + so,        khg + (size_t)(nk0 + r) * DH_ + c * 8);
                CP_ASYNC_16(kvb + 8192 + so, vhg + (size_t)r * T_ + nk0 + c * 8);
            }
            CP_ASYNC_COMMIT();
        }

        const uint32_t kvb = sb + OKV + (kt & 1) * KVSTAGE;
        const uint32_t okh = kvb, ovh = kvb + 8192;

        const bool active = (k0 <= q0 + 16 * w + 15);
        if (active) {
            float s[8][4];
#pragma unroll
            for (int ni = 0; ni < 8; ni++)
#pragma unroll
                for (int e = 0; e < 4; e++) s[ni][e] = 0.f;

#pragma unroll
            for (int ks = 0; ks < 4; ks++) {
                uint32_t aqh[4], aql[4];
                {
                    const int qr = 16 * w + (lane & 15);
                    const uint32_t off = sw128(
                        (uint32_t)(qr * 128 + ks * 32 + ((lane >> 4) & 1) * 16));
                    ldsm_x4(aqh, sb + OQHI + off);
                    ldsm_x4(aql, sb + OQLO + off);
                }
                uint32_t bkh[8][2];
#pragma unroll
                for (int p = 0; p < 4; p++) {
                    const int kr = p * 16 + ((lane >> 4) & 1) * 8 + (lane & 7);
                    const uint32_t off = sw128(
                        (uint32_t)(kr * 128 + ks * 32 + ((lane >> 3) & 1) * 16));
                    uint32_t r4[4];
                    ldsm_x4(r4, okh + off);
                    bkh[2 * p][0] = r4[0]; bkh[2 * p][1] = r4[1];
                    bkh[2 * p + 1][0] = r4[2]; bkh[2 * p + 1][1] = r4[3];
                }
#pragma unroll
                for (int ni = 0; ni < 8; ni++) {
                    mma_f16(s[ni], aqh, bkh[ni]);
                    mma_f16(s[ni], aql, bkh[ni]);
                }
            }

            if (k0 + 63 > q0 + 16 * w) {
#pragma unroll
                for (int ni = 0; ni < 8; ni++) {
                    const int kb = k0 + 8 * ni + 2 * tq;
                    if (kb     > row0)     s[ni][0] = -1e30f;
                    if (kb + 1 > row0)     s[ni][1] = -1e30f;
                    if (kb     > row0 + 8) s[ni][2] = -1e30f;
                    if (kb + 1 > row0 + 8) s[ni][3] = -1e30f;
                }
            }

            float mx0 = -1e30f, mx1 = -1e30f;
#pragma unroll
            for (int ni = 0; ni < 8; ni++) {
                mx0 = fmaxf(mx0, fmaxf(s[ni][0], s[ni][1]));
                mx1 = fmaxf(mx1, fmaxf(s[ni][2], s[ni][3]));
            }
            mx0 = fmaxf(mx0, __shfl_xor_sync(0xffffffffu, mx0, 1));
            mx0 = fmaxf(mx0, __shfl_xor_sync(0xffffffffu, mx0, 2));
            mx1 = fmaxf(mx1, __shfl_xor_sync(0xffffffffu, mx1, 1));
            mx1 = fmaxf(mx1, __shfl_xor_sync(0xffffffffu, mx1, 2));

            const float mn0 = fmaxf(m0, mx0);
            const float mn1 = fmaxf(m1, mx1);
            const float sc0 = __expf(m0 - mn0);
            const float sc1 = __expf(m1 - mn1);
            m0 = mn0; m1 = mn1;
            l0 *= sc0; l1 *= sc1;
#pragma unroll
            for (int ni = 0; ni < 8; ni++) {
                o[ni][0] *= sc0; o[ni][1] *= sc0;
                o[ni][2] *= sc1; o[ni][3] *= sc1;
            }

            uint32_t pH01[8], pH23[8], pL01[8], pL23[8];
#pragma unroll
            for (int ni = 0; ni < 8; ni++) {
                float p0 = __expf(s[ni][0] - mn0);
                float p1 = __expf(s[ni][1] - mn0);
                float p2 = __expf(s[ni][2] - mn1);
                float p3 = __expf(s[ni][3] - mn1);
                l0 += p0 + p1;
                l1 += p2 + p3;
                __half2 h01 = __floats2half2_rn(p0, p1);
                __half2 h23 = __floats2half2_rn(p2, p3);
                pH01[ni] = *reinterpret_cast<uint32_t*>(&h01);
                pH23[ni] = *reinterpret_cast<uint32_t*>(&h23);
                __half2 l01 = __floats2half2_rn(
                    p0 - __half2float(h01.x), p1 - __half2float(h01.y));
                __half2 l23 = __floats2half2_rn(
                    p2 - __half2float(h23.x), p3 - __half2float(h23.y));
                pL01[ni] = *reinterpret_cast<uint32_t*>(&l01);
                pL23[ni] = *reinterpret_cast<uint32_t*>(&l23);
            }

#pragma unroll
            for (int kg = 0; kg < 4; kg++) {
                uint32_t aph[4], apl[4];
                aph[0] = pH01[2 * kg];     aph[1] = pH23[2 * kg];
                aph[2] = pH01[2 * kg + 1]; aph[3] = pH23[2 * kg + 1];
                apl[0] = pL01[2 * kg];     apl[1] = pL23[2 * kg];
                apl[2] = pL01[2 * kg + 1]; apl[3] = pL23[2 * kg + 1];

                uint32_t bvh[8][2];
#pragma unroll
                for (int p = 0; p < 4; p++) {
                    const int dr = p * 16 + ((lane >> 4) & 1) * 8 + (lane & 7);
                    const uint32_t off = sw128(
                        (uint32_t)(dr * 128 + kg * 32 + ((lane >> 3) & 1) * 16));
                    uint32_t r4[4];
                    ldsm_x4(r4, ovh + off);
                    bvh[2 * p][0] = r4[0]; bvh[2 * p][1] = r4[1];
                    bvh[2 * p + 1][0] = r4[2]; bvh[2 * p + 1][1] = r4[3];
                }
#pragma unroll
                for (int ni = 0; ni < 8; ni++) {
                    mma_f16(o[ni], aph, bvh[ni]);
                    mma_f16(o[ni], apl, bvh[ni]);
                }
            }
        }
    }

    // ---- finalize: normalize, write 2-slab att2 (hi|lo)
    l0 += __shfl_xor_sync(0xffffffffu, l0, 1);
    l0 += __shfl_xor_sync(0xffffffffu, l0, 2);
    l1 += __shfl_xor_sync(0xffffffffu, l1, 1);
    l1 += __shfl_xor_sync(0xffffffffu, l1, 2);
    const float inv0 = 1.f / l0;
    const float inv1 = 1.f / l1;

    const size_t rbase0 = (size_t)(b * T_ + row0) * K2_ + h * DH_;
    const size_t rbase1 = rbase0 + (size_t)8 * K2_;
#pragma unroll
    for (int ni = 0; ni < 8; ni++) {
        const int col = 8 * ni + 2 * tq;
        float p0 = o[ni][0] * inv0, p1 = o[ni][1] * inv0;
        float p2 = o[ni][2] * inv1, p3 = o[ni][3] * inv1;

        __half2 h01 = __floats2half2_rn(p0, p1);
        __half2 l01 = __floats2half2_rn(
            p0 - __half2float(h01.x), p1 - __half2float(h01.y));
        *reinterpret_cast<__half2*>(g_att2 + rbase0 + col)      = h01;
        *reinterpret_cast<__half2*>(g_att2 + rbase0 + C_ + col) = l01;

        __half2 h23 = __floats2half2_rn(p2, p3);
        __half2 l23 = __floats2half2_rn(
            p2 - __half2float(h23.x), p3 - __half2float(h23.y));
        *reinterpret_cast<__half2*>(g_att2 + rbase1 + col)      = h23;
        *reinterpret_cast<__half2*>(g_att2 + rbase1 + C_ + col) = l23;
    }
}

// ============================================================================
extern "C" void kernel_launch(void* const* d_in, const int* in_sizes, int n_in,
                              void* d_out, int out_size)
{
    const float* x     = (const float*)d_in[0];
    const float* w_qkv = (const float*)d_in[1];
    const float* w_out = (const float*)d_in[2];
    float*       out   = (float*)d_out;

    __half *x2, *att2, *wqkv2, *wout2;
    cudaGetSymbolAddress((void**)&x2,    g_x2);
    cudaGetSymbolAddress((void**)&att2,  g_att2);
    cudaGetSymbolAddress((void**)&wqkv2, g_wqkv2);
    cudaGetSymbolAddress((void**)&wout2, g_wout2);

    cudaFuncSetAttribute(gemm_mma_kernel,
                         cudaFuncAttributeMaxDynamicSharedMemorySize, GEMM_SMEM);
    cudaFuncSetAttribute(gemm_qkv_fused_kernel,
                         cudaFuncAttributeMaxDynamicSharedMemorySize, GEMM_SMEM);
    cudaFuncSetAttribute(attn_mma_kernel,
                         cudaFuncAttributeMaxDynamicSharedMemorySize, ATT_SMEM);

    // 0) split x (hi|lo) and weights (hi|hi) into 2-slab fp16
    {
        int n4 = (M_ * C_) / 4;
        split2_kernel<<<(n4 + 255) / 256, 256>>>(x, x2, C_, n4, 0);
        n4 = (N_QKV * C_) / 4;
        split2_kernel<<<(n4 + 255) / 256, 256>>>(w_qkv, wqkv2, C_, n4, 1);
        n4 = (C_ * C_) / 4;
        split2_kernel<<<(n4 + 255) / 256, 256>>>(w_out, wout2, C_, n4, 1);
    }
    // 1) QKV projection + fused attention prep
    {
        dim3 grid(N_QKV / BN, M_ / BM);
        gemm_qkv_fused_kernel<<<grid, 256, GEMM_SMEM>>>(x2, wqkv2);
    }
    // 2) tensor-core causal attention -> att2 (2-slab, fused split)
    {
        dim3 grid(T_ / 128, BH_);
        attn_mma_kernel<<<grid, 256, ATT_SMEM>>>();
    }
    // 3) output projection
    {
        dim3 grid(C_ / BN, M_ / BM);
        gemm_mma_kernel<<<grid, 256, GEMM_SMEM>>>(att2, wout2, out, M_, C_, K2_);
    }
}

// round 13
// speedup vs baseline: 1.7740x; 1.1264x over previous
#include <cuda_runtime.h>
#include <cuda_fp16.h>
#include <cstdint>

// ============================================================================
// Problem constants
// ============================================================================
constexpr int B_    = 4;
constexpr int T_    = 2048;
constexpr int C_    = 1024;
constexpr int H_    = 16;
constexpr int DH_   = 64;
constexpr int M_    = B_ * T_;        // 8192
constexpr int N_QKV = 3 * C_;         // 3072
constexpr int K2_   = 2 * C_;         // 2048 (2-slab concatenated K)
constexpr int BH_   = B_ * H_;        // 64

// ============================================================================
// Scratch (__device__ globals; no cudaMalloc allowed)
// ============================================================================
__device__ __half  g_x2[(size_t)M_ * K2_];        // [8192,2048] hi|lo
__device__ __half  g_att2[(size_t)M_ * K2_];      // [8192,2048] hi|lo
__device__ __half  g_wqkv2[(size_t)N_QKV * K2_];  // hi|hi (dup)
__device__ __half  g_wout2[(size_t)C_ * K2_];     // hi|hi (dup)
__device__ __half  g_qhi[(size_t)BH_ * T_ * DH_]; // [bh][t][d], pre-scaled
__device__ __half  g_qlo[(size_t)BH_ * T_ * DH_];
__device__ __half  g_khi[(size_t)BH_ * T_ * DH_]; // hi only
__device__ __half  g_vthi[(size_t)BH_ * DH_ * T_]; // [bh][d][t], hi only

// ============================================================================
// PTX helpers (base-ISA only)
// ============================================================================
__device__ __forceinline__ uint32_t smem_to_u32(const void* smem_ptr) {
    uint32_t addr;
    asm("{ .reg .u64 tmp; cvta.to.shared.u64 tmp, %1; cvt.u32.u64 %0, tmp; }"
        : "=r"(addr) : "l"(smem_ptr));
    return addr;
}
__device__ __forceinline__ void ldsm_x4(uint32_t (&r)[4], uint32_t addr) {
    asm volatile("ldmatrix.sync.aligned.m8n8.x4.shared.b16 {%0,%1,%2,%3}, [%4];"
        : "=r"(r[0]), "=r"(r[1]), "=r"(r[2]), "=r"(r[3]) : "r"(addr));
}
__device__ __forceinline__ void mma_f16(float (&d)[4],
                                        const uint32_t (&a)[4],
                                        const uint32_t (&b)[2]) {
    asm volatile(
        "mma.sync.aligned.m16n8k16.row.col.f32.f16.f16.f32 "
        "{%0,%1,%2,%3}, {%4,%5,%6,%7}, {%8,%9}, {%0,%1,%2,%3};"
        : "+f"(d[0]), "+f"(d[1]), "+f"(d[2]), "+f"(d[3])
        : "r"(a[0]), "r"(a[1]), "r"(a[2]), "r"(a[3]), "r"(b[0]), "r"(b[1]));
}
#define CP_ASYNC_16(dst_u32, src_ptr) \
    asm volatile("cp.async.cg.shared.global [%0], [%1], 16;" \
        :: "r"(dst_u32), "l"(src_ptr))
#define CP_ASYNC_COMMIT() asm volatile("cp.async.commit_group;" ::: "memory")
#define CP_ASYNC_WAIT_1() asm volatile("cp.async.wait_group 1;" ::: "memory")
#define CP_ASYNC_WAIT_0() asm volatile("cp.async.wait_group 0;" ::: "memory")

__device__ __forceinline__ uint32_t sw128(uint32_t off) {
    return off ^ ((off >> 3) & 0x70);
}

// ============================================================================
// Split fp32 -> 2-slab fp16 along K. dup_hi=0: [hi|lo]; dup_hi=1: [hi|hi]
// ============================================================================
__global__ __launch_bounds__(256)
void split2_kernel(const float* __restrict__ in,
                   __half* __restrict__ out2,
                   int K, int n4, int dup_hi)
{
    int i = blockIdx.x * blockDim.x + threadIdx.x;
    if (i >= n4) return;
    int e   = i * 4;
    int row = e / K;
    int col = e - row * K;
    float4 v = reinterpret_cast<const float4*>(in)[i];

    __half h0 = __float2half_rn(v.x), h1 = __float2half_rn(v.y);
    __half h2 = __float2half_rn(v.z), h3 = __float2half_rn(v.w);

    __half2 hA; hA.x = h0; hA.y = h1;
    __half2 hB; hB.x = h2; hB.y = h3;

    size_t base = (size_t)row * (2 * K) + col;
    reinterpret_cast<__half2*>(out2 + base)[0] = hA;
    reinterpret_cast<__half2*>(out2 + base)[1] = hB;

    if (dup_hi) {
        reinterpret_cast<__half2*>(out2 + base + K)[0] = hA;
        reinterpret_cast<__half2*>(out2 + base + K)[1] = hB;
    } else {
        __half2 lA, lB;
        lA.x = __float2half_rn(v.x - __half2float(h0));
        lA.y = __float2half_rn(v.y - __half2float(h1));
        lB.x = __float2half_rn(v.z - __half2float(h2));
        lB.y = __float2half_rn(v.w - __half2float(h3));
        reinterpret_cast<__half2*>(out2 + base + K)[0] = lA;
        reinterpret_cast<__half2*>(out2 + base + K)[1] = lB;
    }
}

// ============================================================================
// GEMM mainloop: 128x128 tile, BK=64, 3-stage cp.async, 8 warps of 64x32,
// one barrier per K-chunk, 2 CTAs/SM. lda/ldb decoupled from K-extent so
// callers can run K=1024 sub-GEMMs over the hi slab of 2048-stride buffers.
// ============================================================================
constexpr int BM = 128, BN = 128, BK = 64;
constexpr int TILEB     = BM * 128;            // 16 KB
constexpr int STAGEB    = 2 * TILEB;           // 32 KB
constexpr int GEMM_SMEM = 3 * STAGEB;          // 96 KB

__device__ __forceinline__ void gemm_issue_loads(
    const __half* __restrict__ A, int lda,
    const __half* __restrict__ Bm, int ldb,
    int m0, int n0, int kc, uint32_t abase, uint32_t bbase, int tid)
{
#pragma unroll
    for (int s = 0; s < 4; s++) {
        const int idx = tid + s * 256;
        const int r = idx >> 3;
        const int c = idx & 7;
        const uint32_t so = sw128((uint32_t)(r * 128 + c * 16));
        CP_ASYNC_16(abase + so, A  + (size_t)(m0 + r) * lda + kc + c * 8);
        CP_ASYNC_16(bbase + so, Bm + (size_t)(n0 + r) * ldb + kc + c * 8);
    }
}

__device__ __forceinline__ void gemm_mainloop(
    const __half* __restrict__ A, int lda,
    const __half* __restrict__ Bm, int ldb,
    int Kext, int m0, int n0, uint32_t sbase, int tid, int wm, int wn, int lane,
    float (&acc)[4][4][4])
{
    const int NC = Kext / BK;

    gemm_issue_loads(A, lda, Bm, ldb, m0, n0, 0, sbase, sbase + TILEB, tid);
    CP_ASYNC_COMMIT();
    if (NC > 1) {
        gemm_issue_loads(A, lda, Bm, ldb, m0, n0, BK,
                         sbase + STAGEB, sbase + STAGEB + TILEB, tid);
    }
    CP_ASYNC_COMMIT();

    int stage = 0;
    for (int ch = 0; ch < NC; ch++) {
        if (ch < NC - 1) { CP_ASYNC_WAIT_1(); }
        else             { CP_ASYNC_WAIT_0(); }
        __syncthreads();

        if (ch + 2 < NC) {
            const int ns = (ch + 2) % 3;
            gemm_issue_loads(A, lda, Bm, ldb, m0, n0, (ch + 2) * BK,
                             sbase + ns * STAGEB, sbase + ns * STAGEB + TILEB, tid);
            CP_ASYNC_COMMIT();
        }

        const uint32_t abase = sbase + stage * STAGEB;
        const uint32_t bbase = abase + TILEB;

#pragma unroll
        for (int ks = 0; ks < 4; ks++) {
            uint32_t afr[4][4];
#pragma unroll
            for (int mi = 0; mi < 4; mi++) {
                const int row = wm + mi * 16 + (lane & 15);
                const uint32_t off =
                    sw128((uint32_t)(row * 128 + ks * 32 + ((lane >> 4) & 1) * 16));
                ldsm_x4(afr[mi], abase + off);
            }
            uint32_t bfr[4][2];
#pragma unroll
            for (int np = 0; np < 2; np++) {
                const int row = wn + np * 16 + ((lane >> 4) & 1) * 8 + (lane & 7);
                const uint32_t off =
                    sw128((uint32_t)(row * 128 + ks * 32 + ((lane >> 3) & 1) * 16));
                uint32_t r4[4];
                ldsm_x4(r4, bbase + off);
                bfr[2 * np][0]     = r4[0]; bfr[2 * np][1]     = r4[1];
                bfr[2 * np + 1][0] = r4[2]; bfr[2 * np + 1][1] = r4[3];
            }
#pragma unroll
            for (int mi = 0; mi < 4; mi++)
#pragma unroll
                for (int ni = 0; ni < 4; ni++)
                    mma_f16(acc[mi][ni], afr[mi], bfr[ni]);
        }
        stage = (stage + 1) % 3;
    }
    __syncthreads();   // protect smem reuse by epilogues
}

// ============================================================================
// Plain GEMM (fp32 output) — output projection (2-slab, K=2048).
// ============================================================================
__global__ __launch_bounds__(256, 2)
void gemm_mma_kernel(const __half* __restrict__ A,
                     const __half* __restrict__ Bm,
                     float* __restrict__ Cm,
                     int M, int N, int K)
{
    extern __shared__ char sm[];
    const int tid  = threadIdx.x;
    const int wid  = tid >> 5;
    const int lane = tid & 31;
    const int m0 = blockIdx.y * BM;
    const int n0 = blockIdx.x * BN;
    const int wm = (wid & 1) * 64;
    const int wn = (wid >> 1) * 32;

    float acc[4][4][4];
#pragma unroll
    for (int mi = 0; mi < 4; mi++)
#pragma unroll
        for (int ni = 0; ni < 4; ni++)
#pragma unroll
            for (int e = 0; e < 4; e++) acc[mi][ni][e] = 0.f;

    gemm_mainloop(A, K, Bm, K, K, m0, n0, smem_to_u32(sm), tid, wm, wn, lane, acc);

    const int g  = lane >> 2;
    const int tg = lane & 3;
#pragma unroll
    for (int mi = 0; mi < 4; mi++) {
#pragma unroll
        for (int ni = 0; ni < 4; ni++) {
            const int row = m0 + wm + mi * 16 + g;
            const int col = n0 + wn + ni * 8 + tg * 2;
            float2 p0; p0.x = acc[mi][ni][0]; p0.y = acc[mi][ni][1];
            float2 p1; p1.x = acc[mi][ni][2]; p1.y = acc[mi][ni][3];
            *reinterpret_cast<float2*>(&Cm[(size_t)row * N + col])       = p0;
            *reinterpret_cast<float2*>(&Cm[(size_t)(row + 8) * N + col]) = p1;
        }
    }
}

// ============================================================================
// Q projection (N=1024, K=2048 2-slab) with fused Q hi/lo epilogue.
// ============================================================================
constexpr int SFS = 130;

__global__ __launch_bounds__(256, 2)
void gemm_q_fused_kernel(const __half* __restrict__ A,
                         const __half* __restrict__ Bm)
{
    extern __shared__ char sm[];
    const int tid  = threadIdx.x;
    const int wid  = tid >> 5;
    const int lane = tid & 31;
    const int m0 = blockIdx.y * BM;
    const int n0 = blockIdx.x * BN;          // 0..1023
    const int wm = (wid & 1) * 64;
    const int wn = (wid >> 1) * 32;

    float acc[4][4][4];
#pragma unroll
    for (int mi = 0; mi < 4; mi++)
#pragma unroll
        for (int ni = 0; ni < 4; ni++)
#pragma unroll
            for (int e = 0; e < 4; e++) acc[mi][ni][e] = 0.f;

    gemm_mainloop(A, K2_, Bm, K2_, K2_, m0, n0, smem_to_u32(sm),
                  tid, wm, wn, lane, acc);

    float* sf = reinterpret_cast<float*>(sm);
    const int g  = lane >> 2;
    const int tg = lane & 3;
#pragma unroll
    for (int mi = 0; mi < 4; mi++) {
#pragma unroll
        for (int ni = 0; ni < 4; ni++) {
            const int row = wm + mi * 16 + g;
            const int col = wn + ni * 8 + tg * 2;
            sf[row * SFS + col]           = acc[mi][ni][0];
            sf[row * SFS + col + 1]       = acc[mi][ni][1];
            sf[(row + 8) * SFS + col]     = acc[mi][ni][2];
            sf[(row + 8) * SFS + col + 1] = acc[mi][ni][3];
        }
    }
    __syncthreads();

    const int h2 = n0 >> 6;                 // first of 2 heads in this tile
    const int b  = m0 >> 11;
    const int t0 = m0 & 2047;
    const int w  = wid;

#pragma unroll
    for (int i = 0; i < 16; i++) {
        const int t = w * 16 + i;
#pragma unroll
        for (int hh = 0; hh < 2; hh++) {
            float2 v = *reinterpret_cast<float2*>(&sf[t * SFS + hh * 64 + lane * 2]);
            v.x *= 0.125f; v.y *= 0.125f;
            __half2 hi2 = __floats2half2_rn(v.x, v.y);
            __half2 lo2 = __floats2half2_rn(
                v.x - __half2float(hi2.x), v.y - __half2float(hi2.y));
            const int bh = b * 16 + h2 + hh;
            const size_t off = ((size_t)bh * T_ + t0 + t) * DH_ + lane * 2;
            *reinterpret_cast<__half2*>(g_qhi + off) = hi2;
            *reinterpret_cast<__half2*>(g_qlo + off) = lo2;
        }
    }
}

// ============================================================================
// K/V projection (N=2048, K=1024 hi-only) with fused K-hi / V^T-hi epilogue.
// A = x2 hi slab (lda=2048), B = wqkv2 rows 1024.. hi slab (ldb=2048).
// ============================================================================
__global__ __launch_bounds__(256, 2)
void gemm_kv_fused_kernel(const __half* __restrict__ A,
                          const __half* __restrict__ Bm)
{
    extern __shared__ char sm[];
    const int tid  = threadIdx.x;
    const int wid  = tid >> 5;
    const int lane = tid & 31;
    const int m0 = blockIdx.y * BM;
    const int n0 = blockIdx.x * BN;          // 0..2047 within KV space
    const int wm = (wid & 1) * 64;
    const int wn = (wid >> 1) * 32;

    float acc[4][4][4];
#pragma unroll
    for (int mi = 0; mi < 4; mi++)
#pragma unroll
        for (int ni = 0; ni < 4; ni++)
#pragma unroll
            for (int e = 0; e < 4; e++) acc[mi][ni][e] = 0.f;

    // K-extent 1024; strides 2048 (hi slabs only)
    gemm_mainloop(A, K2_, Bm, K2_, C_, m0, n0, smem_to_u32(sm),
                  tid, wm, wn, lane, acc);

    float* sf = reinterpret_cast<float*>(sm);
    const int g  = lane >> 2;
    const int tg = lane & 3;
#pragma unroll
    for (int mi = 0; mi < 4; mi++) {
#pragma unroll
        for (int ni = 0; ni < 4; ni++) {
            const int row = wm + mi * 16 + g;
            const int col = wn + ni * 8 + tg * 2;
            sf[row * SFS + col]           = acc[mi][ni][0];
            sf[row * SFS + col + 1]       = acc[mi][ni][1];
            sf[(row + 8) * SFS + col]     = acc[mi][ni][2];
            sf[(row + 8) * SFS + col + 1] = acc[mi][ni][3];
        }
    }
    __syncthreads();

    const int region = n0 >> 10;            // 0=K, 1=V
    const int h2     = (n0 & 1023) >> 6;
    const int b      = m0 >> 11;
    const int t0     = m0 & 2047;
    const int w      = wid;

    if (region == 0) {
        // K: hi only
#pragma unroll
        for (int i = 0; i < 16; i++) {
            const int t = w * 16 + i;
#pragma unroll
            for (int hh = 0; hh < 2; hh++) {
                float2 v = *reinterpret_cast<float2*>(&sf[t * SFS + hh * 64 + lane * 2]);
                __half2 hi2 = __floats2half2_rn(v.x, v.y);
                const int bh = b * 16 + h2 + hh;
                const size_t off = ((size_t)bh * T_ + t0 + t) * DH_ + lane * 2;
                *reinterpret_cast<__half2*>(g_khi + off) = hi2;
            }
        }
    } else {
        // V: transposed [bh][d][t], hi only
#pragma unroll
        for (int i = 0; i < 16; i++) {
            const int fd = w * 16 + i;
            const int hh = fd >> 6;
            const int d  = fd & 63;
            const int bh = b * 16 + h2 + hh;
            const size_t rowbase = ((size_t)bh * DH_ + d) * T_ + t0;
#pragma unroll
            for (int j = 0; j < 4; j++) {
                const int t = lane + 32 * j;
                g_vthi[rowbase + t] = __float2half_rn(sf[t * SFS + fd]);
            }
        }
    }
}

// ============================================================================
// Tensor-core flash attention (causal), fp16 2-product, double-buffered K/V.
// ============================================================================
constexpr int ATT_SMEM = 64 * 1024;
constexpr uint32_t OQHI = 0, OQLO = 16384, OKV = 32768, KVSTAGE = 16384;

__global__ __launch_bounds__(256, 2)
void attn_mma_kernel()
{
    extern __shared__ char sm[];
    const uint32_t sb = smem_to_u32(sm);

    const int tid  = threadIdx.x;
    const int w    = tid >> 5;
    const int lane = tid & 31;
    const int g    = lane >> 2;
    const int tq   = lane & 3;

    const int bh = blockIdx.y;
    const int b  = bh >> 4;
    const int h  = bh & 15;
    const int qt = gridDim.x - 1 - blockIdx.x;
    const int q0 = qt * 128;

    const __half* khg = g_khi + (size_t)bh * T_ * DH_;
    const __half* vhg = g_vthi + (size_t)bh * DH_ * T_;

    {
        const __half* qh = g_qhi + (size_t)(bh * T_ + q0) * DH_;
        const __half* ql = g_qlo + (size_t)(bh * T_ + q0) * DH_;
#pragma unroll
        for (int it = 0; it < 4; it++) {
            const int idx = tid + it * 256;
            const int r = idx >> 3;
            const int c = idx & 7;
            const uint32_t so = sw128((uint32_t)(r * 128 + c * 16));
            CP_ASYNC_16(sb + OQHI + so, qh + (size_t)r * DH_ + c * 8);
            CP_ASYNC_16(sb + OQLO + so, ql + (size_t)r * DH_ + c * 8);
        }
        CP_ASYNC_COMMIT();
    }
    {
        const uint32_t kvb = sb + OKV;
#pragma unroll
        for (int it = 0; it < 2; it++) {
            const int idx = tid + it * 256;
            const int r = idx >> 3;
            const int c = idx & 7;
            const uint32_t so = sw128((uint32_t)(r * 128 + c * 16));
            CP_ASYNC_16(kvb + so,        khg + (size_t)r * DH_ + c * 8);
            CP_ASYNC_16(kvb + 8192 + so, vhg + (size_t)r * T_ + c * 8);
        }
        CP_ASYNC_COMMIT();
    }

    float o[8][4];
#pragma unroll
    for (int ni = 0; ni < 8; ni++)
#pragma unroll
        for (int e = 0; e < 4; e++) o[ni][e] = 0.f;
    float m0 = -1e30f, m1 = -1e30f, l0 = 0.f, l1 = 0.f;

    const int row0 = q0 + 16 * w + g;
    const int kt_max = (q0 + 127) >> 6;

    for (int kt = 0; kt <= kt_max; kt++) {
        const int k0 = kt * 64;

        CP_ASYNC_WAIT_0();
        __syncthreads();

        if (kt + 1 <= kt_max) {
            const int nk0 = (kt + 1) * 64;
            const uint32_t kvb = sb + OKV + ((kt + 1) & 1) * KVSTAGE;
#pragma unroll
            for (int it = 0; it < 2; it++) {
                const int idx = tid + it * 256;
                const int r = idx >> 3;
                const int c = idx & 7;
                const uint32_t so = sw128((uint32_t)(r * 128 + c * 16));
                CP_ASYNC_16(kvb + so,        khg + (size_t)(nk0 + r) * DH_ + c * 8);
                CP_ASYNC_16(kvb + 8192 + so, vhg + (size_t)r * T_ + nk0 + c * 8);
            }
            CP_ASYNC_COMMIT();
        }

        const uint32_t kvb = sb + OKV + (kt & 1) * KVSTAGE;
        const uint32_t okh = kvb, ovh = kvb + 8192;

        const bool active = (k0 <= q0 + 16 * w + 15);
        if (active) {
            float s[8][4];
#pragma unroll
            for (int ni = 0; ni < 8; ni++)
#pragma unroll
                for (int e = 0; e < 4; e++) s[ni][e] = 0.f;

#pragma unroll
            for (int ks = 0; ks < 4; ks++) {
                uint32_t aqh[4], aql[4];
                {
                    const int qr = 16 * w + (lane & 15);
                    const uint32_t off = sw128(
                        (uint32_t)(qr * 128 + ks * 32 + ((lane >> 4) & 1) * 16));
                    ldsm_x4(aqh, sb + OQHI + off);
                    ldsm_x4(aql, sb + OQLO + off);
                }
                uint32_t bkh[8][2];
#pragma unroll
                for (int p = 0; p < 4; p++) {
                    const int kr = p * 16 + ((lane >> 4) & 1) * 8 + (lane & 7);
                    const uint32_t off = sw128(
                        (uint32_t)(kr * 128 + ks * 32 + ((lane >> 3) & 1) * 16));
                    uint32_t r4[4];
                    ldsm_x4(r4, okh + off);
                    bkh[2 * p][0] = r4[0]; bkh[2 * p][1] = r4[1];
                    bkh[2 * p + 1][0] = r4[2]; bkh[2 * p + 1][1] = r4[3];
                }
#pragma unroll
                for (int ni = 0; ni < 8; ni++) {
                    mma_f16(s[ni], aqh, bkh[ni]);
                    mma_f16(s[ni], aql, bkh[ni]);
                }
            }

            if (k0 + 63 > q0 + 16 * w) {
#pragma unroll
                for (int ni = 0; ni < 8; ni++) {
                    const int kb = k0 + 8 * ni + 2 * tq;
                    if (kb     > row0)     s[ni][0] = -1e30f;
                    if (kb + 1 > row0)     s[ni][1] = -1e30f;
                    if (kb     > row0 + 8) s[ni][2] = -1e30f;
                    if (kb + 1 > row0 + 8) s[ni][3] = -1e30f;
                }
            }

            float mx0 = -1e30f, mx1 = -1e30f;
#pragma unroll
            for (int ni = 0; ni < 8; ni++) {
                mx0 = fmaxf(mx0, fmaxf(s[ni][0], s[ni][1]));
                mx1 = fmaxf(mx1, fmaxf(s[ni][2], s[ni][3]));
            }
            mx0 = fmaxf(mx0, __shfl_xor_sync(0xffffffffu, mx0, 1));
            mx0 = fmaxf(mx0, __shfl_xor_sync(0xffffffffu, mx0, 2));
            mx1 = fmaxf(mx1, __shfl_xor_sync(0xffffffffu, mx1, 1));
            mx1 = fmaxf(mx1, __shfl_xor_sync(0xffffffffu, mx1, 2));

            const float mn0 = fmaxf(m0, mx0);
            const float mn1 = fmaxf(m1, mx1);
            const float sc0 = __expf(m0 - mn0);
            const float sc1 = __expf(m1 - mn1);
            m0 = mn0; m1 = mn1;
            l0 *= sc0; l1 *= sc1;
#pragma unroll
            for (int ni = 0; ni < 8; ni++) {
                o[ni][0] *= sc0; o[ni][1] *= sc0;
                o[ni][2] *= sc1; o[ni][3] *= sc1;
            }

            uint32_t pH01[8], pH23[8], pL01[8], pL23[8];
#pragma unroll
            for (int ni = 0; ni < 8; ni++) {
                float p0 = __expf(s[ni][0] - mn0);
                float p1 = __expf(s[ni][1] - mn0);
                float p2 = __expf(s[ni][2] - mn1);
                float p3 = __expf(s[ni][3] - mn1);
                l0 += p0 + p1;
                l1 += p2 + p3;
                __half2 h01 = __floats2half2_rn(p0, p1);
                __half2 h23 = __floats2half2_rn(p2, p3);
                pH01[ni] = *reinterpret_cast<uint32_t*>(&h01);
                pH23[ni] = *reinterpret_cast<uint32_t*>(&h23);
                __half2 l01 = __floats2half2_rn(
                    p0 - __half2float(h01.x), p1 - __half2float(h01.y));
                __half2 l23 = __floats2half2_rn(
                    p2 - __half2float(h23.x), p3 - __half2float(h23.y));
                pL01[ni] = *reinterpret_cast<uint32_t*>(&l01);
                pL23[ni] = *reinterpret_cast<uint32_t*>(&l23);
            }

#pragma unroll
            for (int kg = 0; kg < 4; kg++) {
                uint32_t aph[4], apl[4];
                aph[0] = pH01[2 * kg];     aph[1] = pH23[2 * kg];
                aph[2] = pH01[2 * kg + 1]; aph[3] = pH23[2 * kg + 1];
                apl[0] = pL01[2 * kg];     apl[1] = pL23[2 * kg];
                apl[2] = pL01[2 * kg + 1]; apl[3] = pL23[2 * kg + 1];

                uint32_t bvh[8][2];
#pragma unroll
                for (int p = 0; p < 4; p++) {
                    const int dr = p * 16 + ((lane >> 4) & 1) * 8 + (lane & 7);
                    const uint32_t off = sw128(
                        (uint32_t)(dr * 128 + kg * 32 + ((lane >> 3) & 1) * 16));
                    uint32_t r4[4];
                    ldsm_x4(r4, ovh + off);
                    bvh[2 * p][0] = r4[0]; bvh[2 * p][1] = r4[1];
                    bvh[2 * p + 1][0] = r4[2]; bvh[2 * p + 1][1] = r4[3];
                }
#pragma unroll
                for (int ni = 0; ni < 8; ni++) {
                    mma_f16(o[ni], aph, bvh[ni]);
                    mma_f16(o[ni], apl, bvh[ni]);
                }
            }
        }
    }

    // ---- finalize: normalize, write 2-slab att2 (hi|lo)
    l0 += __shfl_xor_sync(0xffffffffu, l0, 1);
    l0 += __shfl_xor_sync(0xffffffffu, l0, 2);
    l1 += __shfl_xor_sync(0xffffffffu, l1, 1);
    l1 += __shfl_xor_sync(0xffffffffu, l1, 2);
    const float inv0 = 1.f / l0;
    const float inv1 = 1.f / l1;

    const size_t rbase0 = (size_t)(b * T_ + row0) * K2_ + h * DH_;
    const size_t rbase1 = rbase0 + (size_t)8 * K2_;
#pragma unroll
    for (int ni = 0; ni < 8; ni++) {
        const int col = 8 * ni + 2 * tq;
        float p0 = o[ni][0] * inv0, p1 = o[ni][1] * inv0;
        float p2 = o[ni][2] * inv1, p3 = o[ni][3] * inv1;

        __half2 h01 = __floats2half2_rn(p0, p1);
        __half2 l01 = __floats2half2_rn(
            p0 - __half2float(h01.x), p1 - __half2float(h01.y));
        *reinterpret_cast<__half2*>(g_att2 + rbase0 + col)      = h01;
        *reinterpret_cast<__half2*>(g_att2 + rbase0 + C_ + col) = l01;

        __half2 h23 = __floats2half2_rn(p2, p3);
        __half2 l23 = __floats2half2_rn(
            p2 - __half2float(h23.x), p3 - __half2float(h23.y));
        *reinterpret_cast<__half2*>(g_att2 + rbase1 + col)      = h23;
        *reinterpret_cast<__half2*>(g_att2 + rbase1 + C_ + col) = l23;
    }
}

// ============================================================================
extern "C" void kernel_launch(void* const* d_in, const int* in_sizes, int n_in,
                              void* d_out, int out_size)
{
    const float* x     = (const float*)d_in[0];
    const float* w_qkv = (const float*)d_in[1];
    const float* w_out = (const float*)d_in[2];
    float*       out   = (float*)d_out;

    __half *x2, *att2, *wqkv2, *wout2;
    cudaGetSymbolAddress((void**)&x2,    g_x2);
    cudaGetSymbolAddress((void**)&att2,  g_att2);
    cudaGetSymbolAddress((void**)&wqkv2, g_wqkv2);
    cudaGetSymbolAddress((void**)&wout2, g_wout2);

    cudaFuncSetAttribute(gemm_mma_kernel,
                         cudaFuncAttributeMaxDynamicSharedMemorySize, GEMM_SMEM);
    cudaFuncSetAttribute(gemm_q_fused_kernel,
                         cudaFuncAttributeMaxDynamicSharedMemorySize, GEMM_SMEM);
    cudaFuncSetAttribute(gemm_kv_fused_kernel,
                         cudaFuncAttributeMaxDynamicSharedMemorySize, GEMM_SMEM);
    cudaFuncSetAttribute(attn_mma_kernel,
                         cudaFuncAttributeMaxDynamicSharedMemorySize, ATT_SMEM);

    // 0) split x (hi|lo) and weights (hi|hi) into 2-slab fp16
    {
        int n4 = (M_ * C_) / 4;
        split2_kernel<<<(n4 + 255) / 256, 256>>>(x, x2, C_, n4, 0);
        n4 = (N_QKV * C_) / 4;
        split2_kernel<<<(n4 + 255) / 256, 256>>>(w_qkv, wqkv2, C_, n4, 1);
        n4 = (C_ * C_) / 4;
        split2_kernel<<<(n4 + 255) / 256, 256>>>(w_out, wout2, C_, n4, 1);
    }
    // 1a) Q projection (K=2048, 2-slab) + fused Q prep
    {
        dim3 grid(C_ / BN, M_ / BM);           // (8, 64)
        gemm_q_fused_kernel<<<grid, 256, GEMM_SMEM>>>(x2, wqkv2);
    }
    // 1b) K/V projection (K=1024, hi-only) + fused K/V prep
    {
        dim3 grid((2 * C_) / BN, M_ / BM);     // (16, 64)
        gemm_kv_fused_kernel<<<grid, 256, GEMM_SMEM>>>(
            x2, wqkv2 + (size_t)C_ * K2_);
    }
    // 2) tensor-core causal attention -> att2
    {
        dim3 grid(T_ / 128, BH_);
        attn_mma_kernel<<<grid, 256, ATT_SMEM>>>();
    }
    // 3) output projection (K=2048, 2-slab)
    {
        dim3 grid(C_ / BN, M_ / BM);
        gemm_mma_kernel<<<grid, 256, GEMM_SMEM>>>(att2, wout2, out, M_, C_, K2_);
    }
}

// round 14
// speedup vs baseline: 1.8957x; 1.0686x over previous
#include <cuda_runtime.h>
#include <cuda_fp16.h>
#include <cstdint>

// ============================================================================
// Problem constants
// ============================================================================
constexpr int B_    = 4;
constexpr int T_    = 2048;
constexpr int C_    = 1024;
constexpr int H_    = 16;
constexpr int DH_   = 64;
constexpr int M_    = B_ * T_;        // 8192
constexpr int N_QKV = 3 * C_;         // 3072
constexpr int K2_   = 2 * C_;         // 2048 (2-slab concatenated K)
constexpr int BH_   = B_ * H_;        // 64

// ============================================================================
// Scratch (__device__ globals; no cudaMalloc allowed)
// ============================================================================
__device__ __half  g_x2[(size_t)M_ * K2_];        // [8192,2048] hi|lo
__device__ __half  g_att2[(size_t)M_ * K2_];      // [8192,2048] hi|lo
__device__ __half  g_wqkv1[(size_t)N_QKV * C_];   // [3072,1024] hi only
__device__ __half  g_wout1[(size_t)C_ * C_];      // [1024,1024] hi only
__device__ __half  g_qhi[(size_t)BH_ * T_ * DH_]; // [bh][t][d], pre-scaled
__device__ __half  g_khi[(size_t)BH_ * T_ * DH_]; // hi only
__device__ __half  g_vthi[(size_t)BH_ * DH_ * T_]; // [bh][d][t], hi only

// ============================================================================
// PTX helpers (base-ISA only)
// ============================================================================
__device__ __forceinline__ uint32_t smem_to_u32(const void* smem_ptr) {
    uint32_t addr;
    asm("{ .reg .u64 tmp; cvta.to.shared.u64 tmp, %1; cvt.u32.u64 %0, tmp; }"
        : "=r"(addr) : "l"(smem_ptr));
    return addr;
}
__device__ __forceinline__ void ldsm_x4(uint32_t (&r)[4], uint32_t addr) {
    asm volatile("ldmatrix.sync.aligned.m8n8.x4.shared.b16 {%0,%1,%2,%3}, [%4];"
        : "=r"(r[0]), "=r"(r[1]), "=r"(r[2]), "=r"(r[3]) : "r"(addr));
}
__device__ __forceinline__ void mma_f16(float (&d)[4],
                                        const uint32_t (&a)[4],
                                        const uint32_t (&b)[2]) {
    asm volatile(
        "mma.sync.aligned.m16n8k16.row.col.f32.f16.f16.f32 "
        "{%0,%1,%2,%3}, {%4,%5,%6,%7}, {%8,%9}, {%0,%1,%2,%3};"
        : "+f"(d[0]), "+f"(d[1]), "+f"(d[2]), "+f"(d[3])
        : "r"(a[0]), "r"(a[1]), "r"(a[2]), "r"(a[3]), "r"(b[0]), "r"(b[1]));
}
#define CP_ASYNC_16(dst_u32, src_ptr) \
    asm volatile("cp.async.cg.shared.global [%0], [%1], 16;" \
        :: "r"(dst_u32), "l"(src_ptr))
#define CP_ASYNC_COMMIT() asm volatile("cp.async.commit_group;" ::: "memory")
#define CP_ASYNC_WAIT_1() asm volatile("cp.async.wait_group 1;" ::: "memory")
#define CP_ASYNC_WAIT_0() asm volatile("cp.async.wait_group 0;" ::: "memory")

__device__ __forceinline__ uint32_t sw128(uint32_t off) {
    return off ^ ((off >> 3) & 0x70);
}

// ============================================================================
// Split fp32 -> 2-slab fp16 along K: [hi | lo]
// ============================================================================
__global__ __launch_bounds__(256)
void split2_kernel(const float* __restrict__ in,
                   __half* __restrict__ out2,
                   int K, int n4)
{
    int i = blockIdx.x * blockDim.x + threadIdx.x;
    if (i >= n4) return;
    int e   = i * 4;
    int row = e / K;
    int col = e - row * K;
    float4 v = reinterpret_cast<const float4*>(in)[i];

    __half2 hA = __floats2half2_rn(v.x, v.y);
    __half2 hB = __floats2half2_rn(v.z, v.w);
    __half2 lA = __floats2half2_rn(v.x - __half2float(hA.x),
                                   v.y - __half2float(hA.y));
    __half2 lB = __floats2half2_rn(v.z - __half2float(hB.x),
                                   v.w - __half2float(hB.y));

    size_t base = (size_t)row * (2 * K) + col;
    reinterpret_cast<__half2*>(out2 + base)[0] = hA;
    reinterpret_cast<__half2*>(out2 + base)[1] = hB;
    reinterpret_cast<__half2*>(out2 + base + K)[0] = lA;
    reinterpret_cast<__half2*>(out2 + base + K)[1] = lB;
}

// Plain fp32 -> fp16 convert (weights, hi only)
__global__ __launch_bounds__(256)
void convert_h_kernel(const float* __restrict__ in,
                      __half* __restrict__ out, int n4)
{
    int i = blockIdx.x * blockDim.x + threadIdx.x;
    if (i >= n4) return;
    float4 v = reinterpret_cast<const float4*>(in)[i];
    __half2 hA = __floats2half2_rn(v.x, v.y);
    __half2 hB = __floats2half2_rn(v.z, v.w);
    reinterpret_cast<__half2*>(out)[i * 2 + 0] = hA;
    reinterpret_cast<__half2*>(out)[i * 2 + 1] = hB;
}

// ============================================================================
// GEMM mainloop: 128x128 tile, BK=64, 3-stage cp.async, 8 warps of 64x32,
// one barrier per K-chunk, 2 CTAs/SM. B's K index is wrapped by kbmask so the
// 2-slab A (hi|lo, K=2048) can multiply a single-copy B (K=1024):
//   acc = A[:,0:1024]*B + A[:,1024:2048]*B = (a_hi + a_lo) * b_hi.
// ============================================================================
constexpr int BM = 128, BN = 128, BK = 64;
constexpr int TILEB     = BM * 128;            // 16 KB
constexpr int STAGEB    = 2 * TILEB;           // 32 KB
constexpr int GEMM_SMEM = 3 * STAGEB;          // 96 KB

__device__ __forceinline__ void gemm_issue_loads(
    const __half* __restrict__ A, int lda,
    const __half* __restrict__ Bm, int ldb, int kbmask,
    int m0, int n0, int kc, uint32_t abase, uint32_t bbase, int tid)
{
    const int kb = kc & kbmask;
#pragma unroll
    for (int s = 0; s < 4; s++) {
        const int idx = tid + s * 256;
        const int r = idx >> 3;
        const int c = idx & 7;
        const uint32_t so = sw128((uint32_t)(r * 128 + c * 16));
        CP_ASYNC_16(abase + so, A  + (size_t)(m0 + r) * lda + kc + c * 8);
        CP_ASYNC_16(bbase + so, Bm + (size_t)(n0 + r) * ldb + kb + c * 8);
    }
}

__device__ __forceinline__ void gemm_mainloop(
    const __half* __restrict__ A, int lda,
    const __half* __restrict__ Bm, int ldb, int kbmask,
    int Kext, int m0, int n0, uint32_t sbase, int tid, int wm, int wn, int lane,
    float (&acc)[4][4][4])
{
    const int NC = Kext / BK;

    gemm_issue_loads(A, lda, Bm, ldb, kbmask, m0, n0, 0,
                     sbase, sbase + TILEB, tid);
    CP_ASYNC_COMMIT();
    if (NC > 1) {
        gemm_issue_loads(A, lda, Bm, ldb, kbmask, m0, n0, BK,
                         sbase + STAGEB, sbase + STAGEB + TILEB, tid);
    }
    CP_ASYNC_COMMIT();

    int stage = 0;
    for (int ch = 0; ch < NC; ch++) {
        if (ch < NC - 1) { CP_ASYNC_WAIT_1(); }
        else             { CP_ASYNC_WAIT_0(); }
        __syncthreads();

        if (ch + 2 < NC) {
            const int ns = (ch + 2) % 3;
            gemm_issue_loads(A, lda, Bm, ldb, kbmask, m0, n0, (ch + 2) * BK,
                             sbase + ns * STAGEB, sbase + ns * STAGEB + TILEB, tid);
            CP_ASYNC_COMMIT();
        }

        const uint32_t abase = sbase + stage * STAGEB;
        const uint32_t bbase = abase + TILEB;

#pragma unroll
        for (int ks = 0; ks < 4; ks++) {
            uint32_t afr[4][4];
#pragma unroll
            for (int mi = 0; mi < 4; mi++) {
                const int row = wm + mi * 16 + (lane & 15);
                const uint32_t off =
                    sw128((uint32_t)(row * 128 + ks * 32 + ((lane >> 4) & 1) * 16));
                ldsm_x4(afr[mi], abase + off);
            }
            uint32_t bfr[4][2];
#pragma unroll
            for (int np = 0; np < 2; np++) {
                const int row = wn + np * 16 + ((lane >> 4) & 1) * 8 + (lane & 7);
                const uint32_t off =
                    sw128((uint32_t)(row * 128 + ks * 32 + ((lane >> 3) & 1) * 16));
                uint32_t r4[4];
                ldsm_x4(r4, bbase + off);
                bfr[2 * np][0]     = r4[0]; bfr[2 * np][1]     = r4[1];
                bfr[2 * np + 1][0] = r4[2]; bfr[2 * np + 1][1] = r4[3];
            }
#pragma unroll
            for (int mi = 0; mi < 4; mi++)
#pragma unroll
                for (int ni = 0; ni < 4; ni++)
                    mma_f16(acc[mi][ni], afr[mi], bfr[ni]);
        }
        stage = (stage + 1) % 3;
    }
    __syncthreads();   // protect smem reuse by epilogues
}

// ============================================================================
// Output projection: att2 (hi|lo, K=2048) x wout1 (hi, wrapped) -> fp32 out.
// ============================================================================
__global__ __launch_bounds__(256, 2)
void gemm_mma_kernel(const __half* __restrict__ A,
                     const __half* __restrict__ Bm,
                     float* __restrict__ Cm,
                     int M, int N)
{
    extern __shared__ char sm[];
    const int tid  = threadIdx.x;
    const int wid  = tid >> 5;
    const int lane = tid & 31;
    const int m0 = blockIdx.y * BM;
    const int n0 = blockIdx.x * BN;
    const int wm = (wid & 1) * 64;
    const int wn = (wid >> 1) * 32;

    float acc[4][4][4];
#pragma unroll
    for (int mi = 0; mi < 4; mi++)
#pragma unroll
        for (int ni = 0; ni < 4; ni++)
#pragma unroll
            for (int e = 0; e < 4; e++) acc[mi][ni][e] = 0.f;

    gemm_mainloop(A, K2_, Bm, C_, C_ - 1, K2_, m0, n0,
                  smem_to_u32(sm), tid, wm, wn, lane, acc);

    const int g  = lane >> 2;
    const int tg = lane & 3;
#pragma unroll
    for (int mi = 0; mi < 4; mi++) {
#pragma unroll
        for (int ni = 0; ni < 4; ni++) {
            const int row = m0 + wm + mi * 16 + g;
            const int col = n0 + wn + ni * 8 + tg * 2;
            float2 p0; p0.x = acc[mi][ni][0]; p0.y = acc[mi][ni][1];
            float2 p1; p1.x = acc[mi][ni][2]; p1.y = acc[mi][ni][3];
            *reinterpret_cast<float2*>(&Cm[(size_t)row * N + col])       = p0;
            *reinterpret_cast<float2*>(&Cm[(size_t)(row + 8) * N + col]) = p1;
        }
    }
}

// ============================================================================
// Merged QKV projection + fused attention prep. grid (24, 64).
//   region 0 (n0<1024):  Q = (x_hi+x_lo)·w_hi  (Kext 2048, wrapped B)
//   region 1,2:          K,V = x_hi·w_hi       (Kext 1024)
// Epilogue: Q -> g_qhi (scaled, single fp16); K -> g_khi; V -> g_vthi (transposed)
// ============================================================================
constexpr int SFS = 130;

__global__ __launch_bounds__(256, 2)
void gemm_qkv_fused_kernel(const __half* __restrict__ A,
                           const __half* __restrict__ Bm)
{
    extern __shared__ char sm[];
    const int tid  = threadIdx.x;
    const int wid  = tid >> 5;
    const int lane = tid & 31;
    const int m0 = blockIdx.y * BM;
    const int n0 = blockIdx.x * BN;          // 0..3071
    const int wm = (wid & 1) * 64;
    const int wn = (wid >> 1) * 32;
    const int region = n0 >> 10;             // 0=Q, 1=K, 2=V
    const int Kext   = (region == 0) ? K2_ : C_;

    float acc[4][4][4];
#pragma unroll
    for (int mi = 0; mi < 4; mi++)
#pragma unroll
        for (int ni = 0; ni < 4; ni++)
#pragma unroll
            for (int e = 0; e < 4; e++) acc[mi][ni][e] = 0.f;

    gemm_mainloop(A, K2_, Bm, C_, C_ - 1, Kext, m0, n0,
                  smem_to_u32(sm), tid, wm, wn, lane, acc);

    float* sf = reinterpret_cast<float*>(sm);
    const int g  = lane >> 2;
    const int tg = lane & 3;
#pragma unroll
    for (int mi = 0; mi < 4; mi++) {
#pragma unroll
        for (int ni = 0; ni < 4; ni++) {
            const int row = wm + mi * 16 + g;
            const int col = wn + ni * 8 + tg * 2;
            sf[row * SFS + col]           = acc[mi][ni][0];
            sf[row * SFS + col + 1]       = acc[mi][ni][1];
            sf[(row + 8) * SFS + col]     = acc[mi][ni][2];
            sf[(row + 8) * SFS + col + 1] = acc[mi][ni][3];
        }
    }
    __syncthreads();

    const int h2 = (n0 & 1023) >> 6;
    const int b  = m0 >> 11;
    const int t0 = m0 & 2047;
    const int w  = wid;

    if (region < 2) {
        __half* dst = (region == 0) ? g_qhi : g_khi;
        const float scl = (region == 0) ? 0.125f : 1.0f;
#pragma unroll
        for (int i = 0; i < 16; i++) {
            const int t = w * 16 + i;
#pragma unroll
            for (int hh = 0; hh < 2; hh++) {
                float2 v = *reinterpret_cast<float2*>(&sf[t * SFS + hh * 64 + lane * 2]);
                __half2 hi2 = __floats2half2_rn(v.x * scl, v.y * scl);
                const int bh = b * 16 + h2 + hh;
                const size_t off = ((size_t)bh * T_ + t0 + t) * DH_ + lane * 2;
                *reinterpret_cast<__half2*>(dst + off) = hi2;
            }
        }
    } else {
        // V: transposed [bh][d][t]
#pragma unroll
        for (int i = 0; i < 16; i++) {
            const int fd = w * 16 + i;
            const int hh = fd >> 6;
            const int d  = fd & 63;
            const int bh = b * 16 + h2 + hh;
            const size_t rowbase = ((size_t)bh * DH_ + d) * T_ + t0;
#pragma unroll
            for (int j = 0; j < 4; j++) {
                const int t = lane + 32 * j;
                g_vthi[rowbase + t] = __float2half_rn(sf[t * SFS + fd]);
            }
        }
    }
}

// ============================================================================
// Tensor-core flash attention (causal): single-fp16 QK^T, 2-product PV.
// smem: Q 16KB + 2 stages x (K 8KB + V 8KB) = 48KB.
// ============================================================================
constexpr int ATT_SMEM = 48 * 1024;
constexpr uint32_t OQ = 0, OKV = 16384, KVSTAGE = 16384;

__global__ __launch_bounds__(256, 2)
void attn_mma_kernel()
{
    extern __shared__ char sm[];
    const uint32_t sb = smem_to_u32(sm);

    const int tid  = threadIdx.x;
    const int w    = tid >> 5;
    const int lane = tid & 31;
    const int g    = lane >> 2;
    const int tq   = lane & 3;

    const int bh = blockIdx.y;
    const int b  = bh >> 4;
    const int h  = bh & 15;
    const int qt = gridDim.x - 1 - blockIdx.x;
    const int q0 = qt * 128;

    const __half* khg = g_khi + (size_t)bh * T_ * DH_;
    const __half* vhg = g_vthi + (size_t)bh * DH_ * T_;

    {
        const __half* qh = g_qhi + (size_t)(bh * T_ + q0) * DH_;
#pragma unroll
        for (int it = 0; it < 4; it++) {
            const int idx = tid + it * 256;
            const int r = idx >> 3;
            const int c = idx & 7;
            const uint32_t so = sw128((uint32_t)(r * 128 + c * 16));
            CP_ASYNC_16(sb + OQ + so, qh + (size_t)r * DH_ + c * 8);
        }
        CP_ASYNC_COMMIT();
    }
    {
        const uint32_t kvb = sb + OKV;
#pragma unroll
        for (int it = 0; it < 2; it++) {
            const int idx = tid + it * 256;
            const int r = idx >> 3;
            const int c = idx & 7;
            const uint32_t so = sw128((uint32_t)(r * 128 + c * 16));
            CP_ASYNC_16(kvb + so,        khg + (size_t)r * DH_ + c * 8);
            CP_ASYNC_16(kvb + 8192 + so, vhg + (size_t)r * T_ + c * 8);
        }
        CP_ASYNC_COMMIT();
    }

    float o[8][4];
#pragma unroll
    for (int ni = 0; ni < 8; ni++)
#pragma unroll
        for (int e = 0; e < 4; e++) o[ni][e] = 0.f;
    float m0 = -1e30f, m1 = -1e30f, l0 = 0.f, l1 = 0.f;

    const int row0 = q0 + 16 * w + g;
    const int kt_max = (q0 + 127) >> 6;

    for (int kt = 0; kt <= kt_max; kt++) {
        const int k0 = kt * 64;

        CP_ASYNC_WAIT_0();
        __syncthreads();

        if (kt + 1 <= kt_max) {
            const int nk0 = (kt + 1) * 64;
            const uint32_t kvb = sb + OKV + ((kt + 1) & 1) * KVSTAGE;
#pragma unroll
            for (int it = 0; it < 2; it++) {
                const int idx = tid + it * 256;
                const int r = idx >> 3;
                const int c = idx & 7;
                const uint32_t so = sw128((uint32_t)(r * 128 + c * 16));
                CP_ASYNC_16(kvb + so,        khg + (size_t)(nk0 + r) * DH_ + c * 8);
                CP_ASYNC_16(kvb + 8192 + so, vhg + (size_t)r * T_ + nk0 + c * 8);
            }
            CP_ASYNC_COMMIT();
        }

        const uint32_t kvb = sb + OKV + (kt & 1) * KVSTAGE;
        const uint32_t okh = kvb, ovh = kvb + 8192;

        const bool active = (k0 <= q0 + 16 * w + 15);
        if (active) {
            float s[8][4];
#pragma unroll
            for (int ni = 0; ni < 8; ni++)
#pragma unroll
                for (int e = 0; e < 4; e++) s[ni][e] = 0.f;

#pragma unroll
            for (int ks = 0; ks < 4; ks++) {
                uint32_t aqh[4];
                {
                    const int qr = 16 * w + (lane & 15);
                    const uint32_t off = sw128(
                        (uint32_t)(qr * 128 + ks * 32 + ((lane >> 4) & 1) * 16));
                    ldsm_x4(aqh, sb + OQ + off);
                }
                uint32_t bkh[8][2];
#pragma unroll
                for (int p = 0; p < 4; p++) {
                    const int kr = p * 16 + ((lane >> 4) & 1) * 8 + (lane & 7);
                    const uint32_t off = sw128(
                        (uint32_t)(kr * 128 + ks * 32 + ((lane >> 3) & 1) * 16));
                    uint32_t r4[4];
                    ldsm_x4(r4, okh + off);
                    bkh[2 * p][0] = r4[0]; bkh[2 * p][1] = r4[1];
                    bkh[2 * p + 1][0] = r4[2]; bkh[2 * p + 1][1] = r4[3];
                }
#pragma unroll
                for (int ni = 0; ni < 8; ni++)
                    mma_f16(s[ni], aqh, bkh[ni]);
            }

            if (k0 + 63 > q0 + 16 * w) {
#pragma unroll
                for (int ni = 0; ni < 8; ni++) {
                    const int kb = k0 + 8 * ni + 2 * tq;
                    if (kb     > row0)     s[ni][0] = -1e30f;
                    if (kb + 1 > row0)     s[ni][1] = -1e30f;
                    if (kb     > row0 + 8) s[ni][2] = -1e30f;
                    if (kb + 1 > row0 + 8) s[ni][3] = -1e30f;
                }
            }

            float mx0 = -1e30f, mx1 = -1e30f;
#pragma unroll
            for (int ni = 0; ni < 8; ni++) {
                mx0 = fmaxf(mx0, fmaxf(s[ni][0], s[ni][1]));
                mx1 = fmaxf(mx1, fmaxf(s[ni][2], s[ni][3]));
            }
            mx0 = fmaxf(mx0, __shfl_xor_sync(0xffffffffu, mx0, 1));
            mx0 = fmaxf(mx0, __shfl_xor_sync(0xffffffffu, mx0, 2));
            mx1 = fmaxf(mx1, __shfl_xor_sync(0xffffffffu, mx1, 1));
            mx1 = fmaxf(mx1, __shfl_xor_sync(0xffffffffu, mx1, 2));

            const float mn0 = fmaxf(m0, mx0);
            const float mn1 = fmaxf(m1, mx1);
            const float sc0 = __expf(m0 - mn0);
            const float sc1 = __expf(m1 - mn1);
            m0 = mn0; m1 = mn1;
            l0 *= sc0; l1 *= sc1;
#pragma unroll
            for (int ni = 0; ni < 8; ni++) {
                o[ni][0] *= sc0; o[ni][1] *= sc0;
                o[ni][2] *= sc1; o[ni][3] *= sc1;
            }

            uint32_t pH01[8], pH23[8], pL01[8], pL23[8];
#pragma unroll
            for (int ni = 0; ni < 8; ni++) {
                float p0 = __expf(s[ni][0] - mn0);
                float p1 = __expf(s[ni][1] - mn0);
                float p2 = __expf(s[ni][2] - mn1);
                float p3 = __expf(s[ni][3] - mn1);
                l0 += p0 + p1;
                l1 += p2 + p3;
                __half2 h01 = __floats2half2_rn(p0, p1);
                __half2 h23 = __floats2half2_rn(p2, p3);
                pH01[ni] = *reinterpret_cast<uint32_t*>(&h01);
                pH23[ni] = *reinterpret_cast<uint32_t*>(&h23);
                __half2 l01 = __floats2half2_rn(
                    p0 - __half2float(h01.x), p1 - __half2float(h01.y));
                __half2 l23 = __floats2half2_rn(
                    p2 - __half2float(h23.x), p3 - __half2float(h23.y));
                pL01[ni] = *reinterpret_cast<uint32_t*>(&l01);
                pL23[ni] = *reinterpret_cast<uint32_t*>(&l23);
            }

#pragma unroll
            for (int kg = 0; kg < 4; kg++) {
                uint32_t aph[4], apl[4];
                aph[0] = pH01[2 * kg];     aph[1] = pH23[2 * kg];
                aph[2] = pH01[2 * kg + 1]; aph[3] = pH23[2 * kg + 1];
                apl[0] = pL01[2 * kg];     apl[1] = pL23[2 * kg];
                apl[2] = pL01[2 * kg + 1]; apl[3] = pL23[2 * kg + 1];

                uint32_t bvh[8][2];
#pragma unroll
                for (int p = 0; p < 4; p++) {
                    const int dr = p * 16 + ((lane >> 4) & 1) * 8 + (lane & 7);
                    const uint32_t off = sw128(
                        (uint32_t)(dr * 128 + kg * 32 + ((lane >> 3) & 1) * 16));
                    uint32_t r4[4];
                    ldsm_x4(r4, ovh + off);
                    bvh[2 * p][0] = r4[0]; bvh[2 * p][1] = r4[1];
                    bvh[2 * p + 1][0] = r4[2]; bvh[2 * p + 1][1] = r4[3];
                }
#pragma unroll
                for (int ni = 0; ni < 8; ni++) {
                    mma_f16(o[ni], aph, bvh[ni]);
                    mma_f16(o[ni], apl, bvh[ni]);
                }
            }
        }
    }

    // ---- finalize: normalize, write 2-slab att2 (hi|lo)
    l0 += __shfl_xor_sync(0xffffffffu, l0, 1);
    l0 += __shfl_xor_sync(0xffffffffu, l0, 2);
    l1 += __shfl_xor_sync(0xffffffffu, l1, 1);
    l1 += __shfl_xor_sync(0xffffffffu, l1, 2);
    const float inv0 = 1.f / l0;
    const float inv1 = 1.f / l1;

    const size_t rbase0 = (size_t)(b * T_ + row0) * K2_ + h * DH_;
    const size_t rbase1 = rbase0 + (size_t)8 * K2_;
#pragma unroll
    for (int ni = 0; ni < 8; ni++) {
        const int col = 8 * ni + 2 * tq;
        float p0 = o[ni][0] * inv0, p1 = o[ni][1] * inv0;
        float p2 = o[ni][2] * inv1, p3 = o[ni][3] * inv1;

        __half2 h01 = __floats2half2_rn(p0, p1);
        __half2 l01 = __floats2half2_rn(
            p0 - __half2float(h01.x), p1 - __half2float(h01.y));
        *reinterpret_cast<__half2*>(g_att2 + rbase0 + col)      = h01;
        *reinterpret_cast<__half2*>(g_att2 + rbase0 + C_ + col) = l01;

        __half2 h23 = __floats2half2_rn(p2, p3);
        __half2 l23 = __floats2half2_rn(
            p2 - __half2float(h23.x), p3 - __half2float(h23.y));
        *reinterpret_cast<__half2*>(g_att2 + rbase1 + col)      = h23;
        *reinterpret_cast<__half2*>(g_att2 + rbase1 + C_ + col) = l23;
    }
}

// ============================================================================
extern "C" void kernel_launch(void* const* d_in, const int* in_sizes, int n_in,
                              void* d_out, int out_size)
{
    const float* x     = (const float*)d_in[0];
    const float* w_qkv = (const float*)d_in[1];
    const float* w_out = (const float*)d_in[2];
    float*       out   = (float*)d_out;

    __half *x2, *att2, *wqkv1, *wout1;
    cudaGetSymbolAddress((void**)&x2,    g_x2);
    cudaGetSymbolAddress((void**)&att2,  g_att2);
    cudaGetSymbolAddress((void**)&wqkv1, g_wqkv1);
    cudaGetSymbolAddress((void**)&wout1, g_wout1);

    cudaFuncSetAttribute(gemm_mma_kernel,
                         cudaFuncAttributeMaxDynamicSharedMemorySize, GEMM_SMEM);
    cudaFuncSetAttribute(gemm_qkv_fused_kernel,
                         cudaFuncAttributeMaxDynamicSharedMemorySize, GEMM_SMEM);
    cudaFuncSetAttribute(attn_mma_kernel,
                         cudaFuncAttributeMaxDynamicSharedMemorySize, ATT_SMEM);

    // 0) split x (hi|lo); convert weights to fp16 (hi only, no duplication)
    {
        int n4 = (M_ * C_) / 4;
        split2_kernel<<<(n4 + 255) / 256, 256>>>(x, x2, C_, n4);
        n4 = (N_QKV * C_) / 4;
        convert_h_kernel<<<(n4 + 255) / 256, 256>>>(w_qkv, wqkv1, n4);
        n4 = (C_ * C_) / 4;
        convert_h_kernel<<<(n4 + 255) / 256, 256>>>(w_out, wout1, n4);
    }
    // 1) merged Q/K/V projection + fused attention prep
    {
        dim3 grid(N_QKV / BN, M_ / BM);        // (24, 64)
        gemm_qkv_fused_kernel<<<grid, 256, GEMM_SMEM>>>(x2, wqkv1);
    }
    // 2) tensor-core causal attention -> att2
    {
        dim3 grid(T_ / 128, BH_);
        attn_mma_kernel<<<grid, 256, ATT_SMEM>>>();
    }
    // 3) output projection
    {
        dim3 grid(C_ / BN, M_ / BM);
        gemm_mma_kernel<<<grid, 256, GEMM_SMEM>>>(att2, wout1, out, M_, C_);
    }
}

// round 15
// speedup vs baseline: 2.3543x; 1.2419x over previous
#include <cuda_runtime.h>
#include <cuda_fp16.h>
#include <cstdint>

// ============================================================================
// Problem constants
// ============================================================================
constexpr int B_    = 4;
constexpr int T_    = 2048;
constexpr int C_    = 1024;
constexpr int H_    = 16;
constexpr int DH_   = 64;
constexpr int M_    = B_ * T_;        // 8192
constexpr int N_QKV = 3 * C_;         // 3072
constexpr int K2_   = 2 * C_;         // 2048 (2-slab concatenated K)
constexpr int BH_   = B_ * H_;        // 64

// ============================================================================
// Scratch (__device__ globals; no cudaMalloc allowed)
// ============================================================================
__device__ __half  g_x2[(size_t)M_ * K2_];        // [8192,2048] hi|lo
__device__ __half  g_att1[(size_t)M_ * C_];       // [8192,1024] hi only
__device__ __half  g_wqkv1[(size_t)N_QKV * C_];   // [3072,1024] hi only
__device__ __half  g_wout1[(size_t)C_ * C_];      // [1024,1024] hi only
__device__ __half  g_qhi[(size_t)BH_ * T_ * DH_]; // [bh][t][d], pre-scaled
__device__ __half  g_khi[(size_t)BH_ * T_ * DH_]; // hi only
__device__ __half  g_vthi[(size_t)BH_ * DH_ * T_]; // [bh][d][t], hi only

// ============================================================================
// PTX helpers (base-ISA only)
// ============================================================================
__device__ __forceinline__ uint32_t smem_to_u32(const void* smem_ptr) {
    uint32_t addr;
    asm("{ .reg .u64 tmp; cvta.to.shared.u64 tmp, %1; cvt.u32.u64 %0, tmp; }"
        : "=r"(addr) : "l"(smem_ptr));
    return addr;
}
__device__ __forceinline__ void ldsm_x4(uint32_t (&r)[4], uint32_t addr) {
    asm volatile("ldmatrix.sync.aligned.m8n8.x4.shared.b16 {%0,%1,%2,%3}, [%4];"
        : "=r"(r[0]), "=r"(r[1]), "=r"(r[2]), "=r"(r[3]) : "r"(addr));
}
__device__ __forceinline__ void mma_f16(float (&d)[4],
                                        const uint32_t (&a)[4],
                                        const uint32_t (&b)[2]) {
    asm volatile(
        "mma.sync.aligned.m16n8k16.row.col.f32.f16.f16.f32 "
        "{%0,%1,%2,%3}, {%4,%5,%6,%7}, {%8,%9}, {%0,%1,%2,%3};"
        : "+f"(d[0]), "+f"(d[1]), "+f"(d[2]), "+f"(d[3])
        : "r"(a[0]), "r"(a[1]), "r"(a[2]), "r"(a[3]), "r"(b[0]), "r"(b[1]));
}
#define CP_ASYNC_16(dst_u32, src_ptr) \
    asm volatile("cp.async.cg.shared.global [%0], [%1], 16;" \
        :: "r"(dst_u32), "l"(src_ptr))
#define CP_ASYNC_COMMIT() asm volatile("cp.async.commit_group;" ::: "memory")
#define CP_ASYNC_WAIT_1() asm volatile("cp.async.wait_group 1;" ::: "memory")
#define CP_ASYNC_WAIT_0() asm volatile("cp.async.wait_group 0;" ::: "memory")

__device__ __forceinline__ uint32_t sw128(uint32_t off) {
    return off ^ ((off >> 3) & 0x70);
}

// ============================================================================
// Split fp32 -> 2-slab fp16 along K: [hi | lo]
// ============================================================================
__global__ __launch_bounds__(256)
void split2_kernel(const float* __restrict__ in,
                   __half* __restrict__ out2,
                   int K, int n4)
{
    int i = blockIdx.x * blockDim.x + threadIdx.x;
    if (i >= n4) return;
    int e   = i * 4;
    int row = e / K;
    int col = e - row * K;
    float4 v = reinterpret_cast<const float4*>(in)[i];

    __half2 hA = __floats2half2_rn(v.x, v.y);
    __half2 hB = __floats2half2_rn(v.z, v.w);
    __half2 lA = __floats2half2_rn(v.x - __half2float(hA.x),
                                   v.y - __half2float(hA.y));
    __half2 lB = __floats2half2_rn(v.z - __half2float(hB.x),
                                   v.w - __half2float(hB.y));

    size_t base = (size_t)row * (2 * K) + col;
    reinterpret_cast<__half2*>(out2 + base)[0] = hA;
    reinterpret_cast<__half2*>(out2 + base)[1] = hB;
    reinterpret_cast<__half2*>(out2 + base + K)[0] = lA;
    reinterpret_cast<__half2*>(out2 + base + K)[1] = lB;
}

// Plain fp32 -> fp16 convert (weights, hi only)
__global__ __launch_bounds__(256)
void convert_h_kernel(const float* __restrict__ in,
                      __half* __restrict__ out, int n4)
{
    int i = blockIdx.x * blockDim.x + threadIdx.x;
    if (i >= n4) return;
    float4 v = reinterpret_cast<const float4*>(in)[i];
    __half2 hA = __floats2half2_rn(v.x, v.y);
    __half2 hB = __floats2half2_rn(v.z, v.w);
    reinterpret_cast<__half2*>(out)[i * 2 + 0] = hA;
    reinterpret_cast<__half2*>(out)[i * 2 + 1] = hB;
}

// ============================================================================
// GEMM mainloop: 128x128 tile, BK=64, 3-stage cp.async, 8 warps of 64x32,
// one barrier per K-chunk, 2 CTAs/SM. B's K index wrapped by kbmask so a
// 2-slab A (hi|lo) can multiply a single-copy B: (a_hi + a_lo) * b_hi.
// ============================================================================
constexpr int BM = 128, BN = 128, BK = 64;
constexpr int TILEB     = BM * 128;            // 16 KB
constexpr int STAGEB    = 2 * TILEB;           // 32 KB
constexpr int GEMM_SMEM = 3 * STAGEB;          // 96 KB

__device__ __forceinline__ void gemm_issue_loads(
    const __half* __restrict__ A, int lda,
    const __half* __restrict__ Bm, int ldb, int kbmask,
    int m0, int n0, int kc, uint32_t abase, uint32_t bbase, int tid)
{
    const int kb = kc & kbmask;
#pragma unroll
    for (int s = 0; s < 4; s++) {
        const int idx = tid + s * 256;
        const int r = idx >> 3;
        const int c = idx & 7;
        const uint32_t so = sw128((uint32_t)(r * 128 + c * 16));
        CP_ASYNC_16(abase + so, A  + (size_t)(m0 + r) * lda + kc + c * 8);
        CP_ASYNC_16(bbase + so, Bm + (size_t)(n0 + r) * ldb + kb + c * 8);
    }
}

__device__ __forceinline__ void gemm_mainloop(
    const __half* __restrict__ A, int lda,
    const __half* __restrict__ Bm, int ldb, int kbmask,
    int Kext, int m0, int n0, uint32_t sbase, int tid, int wm, int wn, int lane,
    float (&acc)[4][4][4])
{
    const int NC = Kext / BK;

    gemm_issue_loads(A, lda, Bm, ldb, kbmask, m0, n0, 0,
                     sbase, sbase + TILEB, tid);
    CP_ASYNC_COMMIT();
    if (NC > 1) {
        gemm_issue_loads(A, lda, Bm, ldb, kbmask, m0, n0, BK,
                         sbase + STAGEB, sbase + STAGEB + TILEB, tid);
    }
    CP_ASYNC_COMMIT();

    int stage = 0;
    for (int ch = 0; ch < NC; ch++) {
        if (ch < NC - 1) { CP_ASYNC_WAIT_1(); }
        else             { CP_ASYNC_WAIT_0(); }
        __syncthreads();

        if (ch + 2 < NC) {
            const int ns = (ch + 2) % 3;
            gemm_issue_loads(A, lda, Bm, ldb, kbmask, m0, n0, (ch + 2) * BK,
                             sbase + ns * STAGEB, sbase + ns * STAGEB + TILEB, tid);
            CP_ASYNC_COMMIT();
        }

        const uint32_t abase = sbase + stage * STAGEB;
        const uint32_t bbase = abase + TILEB;

#pragma unroll
        for (int ks = 0; ks < 4; ks++) {
            uint32_t afr[4][4];
#pragma unroll
            for (int mi = 0; mi < 4; mi++) {
                const int row = wm + mi * 16 + (lane & 15);
                const uint32_t off =
                    sw128((uint32_t)(row * 128 + ks * 32 + ((lane >> 4) & 1) * 16));
                ldsm_x4(afr[mi], abase + off);
            }
            uint32_t bfr[4][2];
#pragma unroll
            for (int np = 0; np < 2; np++) {
                const int row = wn + np * 16 + ((lane >> 4) & 1) * 8 + (lane & 7);
                const uint32_t off =
                    sw128((uint32_t)(row * 128 + ks * 32 + ((lane >> 3) & 1) * 16));
                uint32_t r4[4];
                ldsm_x4(r4, bbase + off);
                bfr[2 * np][0]     = r4[0]; bfr[2 * np][1]     = r4[1];
                bfr[2 * np + 1][0] = r4[2]; bfr[2 * np + 1][1] = r4[3];
            }
#pragma unroll
            for (int mi = 0; mi < 4; mi++)
#pragma unroll
                for (int ni = 0; ni < 4; ni++)
                    mma_f16(acc[mi][ni], afr[mi], bfr[ni]);
        }
        stage = (stage + 1) % 3;
    }
    __syncthreads();   // protect smem reuse by epilogues
}

// ============================================================================
// Output projection: att1 (hi, K=1024) x wout1 (hi) -> fp32 out.
// ============================================================================
__global__ __launch_bounds__(256, 2)
void gemm_mma_kernel(const __half* __restrict__ A,
                     const __half* __restrict__ Bm,
                     float* __restrict__ Cm,
                     int M, int N)
{
    extern __shared__ char sm[];
    const int tid  = threadIdx.x;
    const int wid  = tid >> 5;
    const int lane = tid & 31;
    const int m0 = blockIdx.y * BM;
    const int n0 = blockIdx.x * BN;
    const int wm = (wid & 1) * 64;
    const int wn = (wid >> 1) * 32;

    float acc[4][4][4];
#pragma unroll
    for (int mi = 0; mi < 4; mi++)
#pragma unroll
        for (int ni = 0; ni < 4; ni++)
#pragma unroll
            for (int e = 0; e < 4; e++) acc[mi][ni][e] = 0.f;

    gemm_mainloop(A, C_, Bm, C_, C_ - 1, C_, m0, n0,
                  smem_to_u32(sm), tid, wm, wn, lane, acc);

    const int g  = lane >> 2;
    const int tg = lane & 3;
#pragma unroll
    for (int mi = 0; mi < 4; mi++) {
#pragma unroll
        for (int ni = 0; ni < 4; ni++) {
            const int row = m0 + wm + mi * 16 + g;
            const int col = n0 + wn + ni * 8 + tg * 2;
            float2 p0; p0.x = acc[mi][ni][0]; p0.y = acc[mi][ni][1];
            float2 p1; p1.x = acc[mi][ni][2]; p1.y = acc[mi][ni][3];
            *reinterpret_cast<float2*>(&Cm[(size_t)row * N + col])       = p0;
            *reinterpret_cast<float2*>(&Cm[(size_t)(row + 8) * N + col]) = p1;
        }
    }
}

// ============================================================================
// Merged QKV projection + fused attention prep. grid (24, 64).
//   region 0 (Q): Kext 2048 (2-slab, wrapped B); regions 1,2 (K,V): Kext 1024.
// ============================================================================
constexpr int SFS = 130;

__global__ __launch_bounds__(256, 2)
void gemm_qkv_fused_kernel(const __half* __restrict__ A,
                           const __half* __restrict__ Bm)
{
    extern __shared__ char sm[];
    const int tid  = threadIdx.x;
    const int wid  = tid >> 5;
    const int lane = tid & 31;
    const int m0 = blockIdx.y * BM;
    const int n0 = blockIdx.x * BN;          // 0..3071
    const int wm = (wid & 1) * 64;
    const int wn = (wid >> 1) * 32;
    const int region = n0 >> 10;             // 0=Q, 1=K, 2=V
    const int Kext   = (region == 0) ? K2_ : C_;

    float acc[4][4][4];
#pragma unroll
    for (int mi = 0; mi < 4; mi++)
#pragma unroll
        for (int ni = 0; ni < 4; ni++)
#pragma unroll
            for (int e = 0; e < 4; e++) acc[mi][ni][e] = 0.f;

    gemm_mainloop(A, K2_, Bm, C_, C_ - 1, Kext, m0, n0,
                  smem_to_u32(sm), tid, wm, wn, lane, acc);

    float* sf = reinterpret_cast<float*>(sm);
    const int g  = lane >> 2;
    const int tg = lane & 3;
#pragma unroll
    for (int mi = 0; mi < 4; mi++) {
#pragma unroll
        for (int ni = 0; ni < 4; ni++) {
            const int row = wm + mi * 16 + g;
            const int col = wn + ni * 8 + tg * 2;
            sf[row * SFS + col]           = acc[mi][ni][0];
            sf[row * SFS + col + 1]       = acc[mi][ni][1];
            sf[(row + 8) * SFS + col]     = acc[mi][ni][2];
            sf[(row + 8) * SFS + col + 1] = acc[mi][ni][3];
        }
    }
    __syncthreads();

    const int h2 = (n0 & 1023) >> 6;
    const int b  = m0 >> 11;
    const int t0 = m0 & 2047;
    const int w  = wid;

    if (region < 2) {
        __half* dst = (region == 0) ? g_qhi : g_khi;
        const float scl = (region == 0) ? 0.125f : 1.0f;
#pragma unroll
        for (int i = 0; i < 16; i++) {
            const int t = w * 16 + i;
#pragma unroll
            for (int hh = 0; hh < 2; hh++) {
                float2 v = *reinterpret_cast<float2*>(&sf[t * SFS + hh * 64 + lane * 2]);
                __half2 hi2 = __floats2half2_rn(v.x * scl, v.y * scl);
                const int bh = b * 16 + h2 + hh;
                const size_t off = ((size_t)bh * T_ + t0 + t) * DH_ + lane * 2;
                *reinterpret_cast<__half2*>(dst + off) = hi2;
            }
        }
    } else {
        // V: transposed [bh][d][t]
#pragma unroll
        for (int i = 0; i < 16; i++) {
            const int fd = w * 16 + i;
            const int hh = fd >> 6;
            const int d  = fd & 63;
            const int bh = b * 16 + h2 + hh;
            const size_t rowbase = ((size_t)bh * DH_ + d) * T_ + t0;
#pragma unroll
            for (int j = 0; j < 4; j++) {
                const int t = lane + 32 * j;
                g_vthi[rowbase + t] = __float2half_rn(sf[t * SFS + fd]);
            }
        }
    }
}

// ============================================================================
// Tensor-core flash attention (causal): single-fp16 QK^T and PV.
// smem: Q 16KB + 2 stages x (K 8KB + V 8KB) = 48KB.
// Epilogue writes single-fp16 att1 [M,1024].
// ============================================================================
constexpr int ATT_SMEM = 48 * 1024;
constexpr uint32_t OQ = 0, OKV = 16384, KVSTAGE = 16384;

__global__ __launch_bounds__(256, 2)
void attn_mma_kernel()
{
    extern __shared__ char sm[];
    const uint32_t sb = smem_to_u32(sm);

    const int tid  = threadIdx.x;
    const int w    = tid >> 5;
    const int lane = tid & 31;
    const int g    = lane >> 2;
    const int tq   = lane & 3;

    const int bh = blockIdx.y;
    const int b  = bh >> 4;
    const int h  = bh & 15;
    const int qt = gridDim.x - 1 - blockIdx.x;
    const int q0 = qt * 128;

    const __half* khg = g_khi + (size_t)bh * T_ * DH_;
    const __half* vhg = g_vthi + (size_t)bh * DH_ * T_;

    {
        const __half* qh = g_qhi + (size_t)(bh * T_ + q0) * DH_;
#pragma unroll
        for (int it = 0; it < 4; it++) {
            const int idx = tid + it * 256;
            const int r = idx >> 3;
            const int c = idx & 7;
            const uint32_t so = sw128((uint32_t)(r * 128 + c * 16));
            CP_ASYNC_16(sb + OQ + so, qh + (size_t)r * DH_ + c * 8);
        }
        CP_ASYNC_COMMIT();
    }
    {
        const uint32_t kvb = sb + OKV;
#pragma unroll
        for (int it = 0; it < 2; it++) {
            const int idx = tid + it * 256;
            const int r = idx >> 3;
            const int c = idx & 7;
            const uint32_t so = sw128((uint32_t)(r * 128 + c * 16));
            CP_ASYNC_16(kvb + so,        khg + (size_t)r * DH_ + c * 8);
            CP_ASYNC_16(kvb + 8192 + so, vhg + (size_t)r * T_ + c * 8);
        }
        CP_ASYNC_COMMIT();
    }

    float o[8][4];
#pragma unroll
    for (int ni = 0; ni < 8; ni++)
#pragma unroll
        for (int e = 0; e < 4; e++) o[ni][e] = 0.f;
    float m0 = -1e30f, m1 = -1e30f, l0 = 0.f, l1 = 0.f;

    const int row0 = q0 + 16 * w + g;
    const int kt_max = (q0 + 127) >> 6;

    for (int kt = 0; kt <= kt_max; kt++) {
        const int k0 = kt * 64;

        CP_ASYNC_WAIT_0();
        __syncthreads();

        if (kt + 1 <= kt_max) {
            const int nk0 = (kt + 1) * 64;
            const uint32_t kvb = sb + OKV + ((kt + 1) & 1) * KVSTAGE;
#pragma unroll
            for (int it = 0; it < 2; it++) {
                const int idx = tid + it * 256;
                const int r = idx >> 3;
                const int c = idx & 7;
                const uint32_t so = sw128((uint32_t)(r * 128 + c * 16));
                CP_ASYNC_16(kvb + so,        khg + (size_t)(nk0 + r) * DH_ + c * 8);
                CP_ASYNC_16(kvb + 8192 + so, vhg + (size_t)r * T_ + nk0 + c * 8);
            }
            CP_ASYNC_COMMIT();
        }

        const uint32_t kvb = sb + OKV + (kt & 1) * KVSTAGE;
        const uint32_t okh = kvb, ovh = kvb + 8192;

        const bool active = (k0 <= q0 + 16 * w + 15);
        if (active) {
            float s[8][4];
#pragma unroll
            for (int ni = 0; ni < 8; ni++)
#pragma unroll
                for (int e = 0; e < 4; e++) s[ni][e] = 0.f;

#pragma unroll
            for (int ks = 0; ks < 4; ks++) {
                uint32_t aqh[4];
                {
                    const int qr = 16 * w + (lane & 15);
                    const uint32_t off = sw128(
                        (uint32_t)(qr * 128 + ks * 32 + ((lane >> 4) & 1) * 16));
                    ldsm_x4(aqh, sb + OQ + off);
                }
                uint32_t bkh[8][2];
#pragma unroll
                for (int p = 0; p < 4; p++) {
                    const int kr = p * 16 + ((lane >> 4) & 1) * 8 + (lane & 7);
                    const uint32_t off = sw128(
                        (uint32_t)(kr * 128 + ks * 32 + ((lane >> 3) & 1) * 16));
                    uint32_t r4[4];
                    ldsm_x4(r4, okh + off);
                    bkh[2 * p][0] = r4[0]; bkh[2 * p][1] = r4[1];
                    bkh[2 * p + 1][0] = r4[2]; bkh[2 * p + 1][1] = r4[3];
                }
#pragma unroll
                for (int ni = 0; ni < 8; ni++)
                    mma_f16(s[ni], aqh, bkh[ni]);
            }

            if (k0 + 63 > q0 + 16 * w) {
#pragma unroll
                for (int ni = 0; ni < 8; ni++) {
                    const int kb = k0 + 8 * ni + 2 * tq;
                    if (kb     > row0)     s[ni][0] = -1e30f;
                    if (kb + 1 > row0)     s[ni][1] = -1e30f;
                    if (kb     > row0 + 8) s[ni][2] = -1e30f;
                    if (kb + 1 > row0 + 8) s[ni][3] = -1e30f;
                }
            }

            float mx0 = -1e30f, mx1 = -1e30f;
#pragma unroll
            for (int ni = 0; ni < 8; ni++) {
                mx0 = fmaxf(mx0, fmaxf(s[ni][0], s[ni][1]));
                mx1 = fmaxf(mx1, fmaxf(s[ni][2], s[ni][3]));
            }
            mx0 = fmaxf(mx0, __shfl_xor_sync(0xffffffffu, mx0, 1));
            mx0 = fmaxf(mx0, __shfl_xor_sync(0xffffffffu, mx0, 2));
            mx1 = fmaxf(mx1, __shfl_xor_sync(0xffffffffu, mx1, 1));
            mx1 = fmaxf(mx1, __shfl_xor_sync(0xffffffffu, mx1, 2));

            const float mn0 = fmaxf(m0, mx0);
            const float mn1 = fmaxf(m1, mx1);
            const float sc0 = __expf(m0 - mn0);
            const float sc1 = __expf(m1 - mn1);
            m0 = mn0; m1 = mn1;
            l0 *= sc0; l1 *= sc1;
#pragma unroll
            for (int ni = 0; ni < 8; ni++) {
                o[ni][0] *= sc0; o[ni][1] *= sc0;
                o[ni][2] *= sc1; o[ni][3] *= sc1;
            }

            uint32_t pH01[8], pH23[8];
#pragma unroll
            for (int ni = 0; ni < 8; ni++) {
                float p0 = __expf(s[ni][0] - mn0);
                float p1 = __expf(s[ni][1] - mn0);
                float p2 = __expf(s[ni][2] - mn1);
                float p3 = __expf(s[ni][3] - mn1);
                l0 += p0 + p1;
                l1 += p2 + p3;
                __half2 h01 = __floats2half2_rn(p0, p1);
                __half2 h23 = __floats2half2_rn(p2, p3);
                pH01[ni] = *reinterpret_cast<uint32_t*>(&h01);
                pH23[ni] = *reinterpret_cast<uint32_t*>(&h23);
            }

#pragma unroll
            for (int kg = 0; kg < 4; kg++) {
                uint32_t aph[4];
                aph[0] = pH01[2 * kg];     aph[1] = pH23[2 * kg];
                aph[2] = pH01[2 * kg + 1]; aph[3] = pH23[2 * kg + 1];

                uint32_t bvh[8][2];
#pragma unroll
                for (int p = 0; p < 4; p++) {
                    const int dr = p * 16 + ((lane >> 4) & 1) * 8 + (lane & 7);
                    const uint32_t off = sw128(
                        (uint32_t)(dr * 128 + kg * 32 + ((lane >> 3) & 1) * 16));
                    uint32_t r4[4];
                    ldsm_x4(r4, ovh + off);
                    bvh[2 * p][0] = r4[0]; bvh[2 * p][1] = r4[1];
                    bvh[2 * p + 1][0] = r4[2]; bvh[2 * p + 1][1] = r4[3];
                }
#pragma unroll
                for (int ni = 0; ni < 8; ni++)
                    mma_f16(o[ni], aph, bvh[ni]);
            }
        }
    }

    // ---- finalize: normalize, write single-fp16 att1
    l0 += __shfl_xor_sync(0xffffffffu, l0, 1);
    l0 += __shfl_xor_sync(0xffffffffu, l0, 2);
    l1 += __shfl_xor_sync(0xffffffffu, l1, 1);
    l1 += __shfl_xor_sync(0xffffffffu, l1, 2);
    const float inv0 = 1.f / l0;
    const float inv1 = 1.f / l1;

    const size_t rbase0 = (size_t)(b * T_ + row0) * C_ + h * DH_;
    const size_t rbase1 = rbase0 + (size_t)8 * C_;
#pragma unroll
    for (int ni = 0; ni < 8; ni++) {
        const int col = 8 * ni + 2 * tq;
        __half2 h01 = __floats2half2_rn(o[ni][0] * inv0, o[ni][1] * inv0);
        __half2 h23 = __floats2half2_rn(o[ni][2] * inv1, o[ni][3] * inv1);
        *reinterpret_cast<__half2*>(g_att1 + rbase0 + col) = h01;
        *reinterpret_cast<__half2*>(g_att1 + rbase1 + col) = h23;
    }
}

// ============================================================================
extern "C" void kernel_launch(void* const* d_in, const int* in_sizes, int n_in,
                              void* d_out, int out_size)
{
    const float* x     = (const float*)d_in[0];
    const float* w_qkv = (const float*)d_in[1];
    const float* w_out = (const float*)d_in[2];
    float*       out   = (float*)d_out;

    __half *x2, *att1, *wqkv1, *wout1;
    cudaGetSymbolAddress((void**)&x2,    g_x2);
    cudaGetSymbolAddress((void**)&att1,  g_att1);
    cudaGetSymbolAddress((void**)&wqkv1, g_wqkv1);
    cudaGetSymbolAddress((void**)&wout1, g_wout1);

    cudaFuncSetAttribute(gemm_mma_kernel,
                         cudaFuncAttributeMaxDynamicSharedMemorySize, GEMM_SMEM);
    cudaFuncSetAttribute(gemm_qkv_fused_kernel,
                         cudaFuncAttributeMaxDynamicSharedMemorySize, GEMM_SMEM);
    cudaFuncSetAttribute(attn_mma_kernel,
                         cudaFuncAttributeMaxDynamicSharedMemorySize, ATT_SMEM);

    // 0) split x (hi|lo); convert weights to fp16 (hi only)
    {
        int n4 = (M_ * C_) / 4;
        split2_kernel<<<(n4 + 255) / 256, 256>>>(x, x2, C_, n4);
        n4 = (N_QKV * C_) / 4;
        convert_h_kernel<<<(n4 + 255) / 256, 256>>>(w_qkv, wqkv1, n4);
        n4 = (C_ * C_) / 4;
        convert_h_kernel<<<(n4 + 255) / 256, 256>>>(w_out, wout1, n4);
    }
    // 1) merged Q/K/V projection + fused attention prep
    {
        dim3 grid(N_QKV / BN, M_ / BM);        // (24, 64)
        gemm_qkv_fused_kernel<<<grid, 256, GEMM_SMEM>>>(x2, wqkv1);
    }
    // 2) tensor-core causal attention -> att1 (single fp16)
    {
        dim3 grid(T_ / 128, BH_);
        attn_mma_kernel<<<grid, 256, ATT_SMEM>>>();
    }
    // 3) output projection (K=1024, hi only)
    {
        dim3 grid(C_ / BN, M_ / BM);
        gemm_mma_kernel<<<grid, 256, GEMM_SMEM>>>(att1, wout1, out, M_, C_);
    }
}

// round 16
// speedup vs baseline: 2.6835x; 1.1399x over previous
#include <cuda_runtime.h>
#include <cuda_fp16.h>
#include <cstdint>

// ============================================================================
// Problem constants
// ============================================================================
constexpr int B_    = 4;
constexpr int T_    = 2048;
constexpr int C_    = 1024;
constexpr int H_    = 16;
constexpr int DH_   = 64;
constexpr int M_    = B_ * T_;        // 8192
constexpr int N_QKV = 3 * C_;         // 3072
constexpr int BH_   = B_ * H_;        // 64

// ============================================================================
// Scratch (__device__ globals; no cudaMalloc allowed) — all single fp16
// ============================================================================
__device__ __half  g_x1[(size_t)M_ * C_];         // [8192,1024]
__device__ __half  g_att1[(size_t)M_ * C_];       // [8192,1024]
__device__ __half  g_wqkv1[(size_t)N_QKV * C_];   // [3072,1024]
__device__ __half  g_wout1[(size_t)C_ * C_];      // [1024,1024]
__device__ __half  g_qhi[(size_t)BH_ * T_ * DH_]; // [bh][t][d], pre-scaled
__device__ __half  g_khi[(size_t)BH_ * T_ * DH_];
__device__ __half  g_vthi[(size_t)BH_ * DH_ * T_]; // [bh][d][t]

// ============================================================================
// PTX helpers (base-ISA only)
// ============================================================================
__device__ __forceinline__ uint32_t smem_to_u32(const void* smem_ptr) {
    uint32_t addr;
    asm("{ .reg .u64 tmp; cvta.to.shared.u64 tmp, %1; cvt.u32.u64 %0, tmp; }"
        : "=r"(addr) : "l"(smem_ptr));
    return addr;
}
__device__ __forceinline__ void ldsm_x4(uint32_t (&r)[4], uint32_t addr) {
    asm volatile("ldmatrix.sync.aligned.m8n8.x4.shared.b16 {%0,%1,%2,%3}, [%4];"
        : "=r"(r[0]), "=r"(r[1]), "=r"(r[2]), "=r"(r[3]) : "r"(addr));
}
__device__ __forceinline__ void mma_f16(float (&d)[4],
                                        const uint32_t (&a)[4],
                                        const uint32_t (&b)[2]) {
    asm volatile(
        "mma.sync.aligned.m16n8k16.row.col.f32.f16.f16.f32 "
        "{%0,%1,%2,%3}, {%4,%5,%6,%7}, {%8,%9}, {%0,%1,%2,%3};"
        : "+f"(d[0]), "+f"(d[1]), "+f"(d[2]), "+f"(d[3])
        : "r"(a[0]), "r"(a[1]), "r"(a[2]), "r"(a[3]), "r"(b[0]), "r"(b[1]));
}
#define CP_ASYNC_16(dst_u32, src_ptr) \
    asm volatile("cp.async.cg.shared.global [%0], [%1], 16;" \
        :: "r"(dst_u32), "l"(src_ptr))
#define CP_ASYNC_COMMIT() asm volatile("cp.async.commit_group;" ::: "memory")
#define CP_ASYNC_WAIT_1() asm volatile("cp.async.wait_group 1;" ::: "memory")
#define CP_ASYNC_WAIT_0() asm volatile("cp.async.wait_group 0;" ::: "memory")

__device__ __forceinline__ uint32_t sw128(uint32_t off) {
    return off ^ ((off >> 3) & 0x70);
}

// ============================================================================
// Merged convert: x, w_qkv, w_out -> fp16 in ONE launch (by index range).
// n4x = 2M, n4wq = 768K, n4wo = 256K float4 groups.
// ============================================================================
__global__ __launch_bounds__(256)
void convert_all_kernel(const float* __restrict__ x,
                        const float* __restrict__ wq,
                        const float* __restrict__ wo,
                        __half* __restrict__ x1,
                        __half* __restrict__ wq1,
                        __half* __restrict__ wo1,
                        int n4x, int n4wq, int n4wo)
{
    int i = blockIdx.x * blockDim.x + threadIdx.x;
    const float* src;
    __half* dst;
    if (i < n4x)               { src = x;  dst = x1; }
    else if (i < n4x + n4wq)   { src = wq; dst = wq1; i -= n4x; }
    else if (i < n4x + n4wq + n4wo) { src = wo; dst = wo1; i -= n4x + n4wq; }
    else return;

    float4 v = reinterpret_cast<const float4*>(src)[i];
    __half2 hA = __floats2half2_rn(v.x, v.y);
    __half2 hB = __floats2half2_rn(v.z, v.w);
    reinterpret_cast<__half2*>(dst)[i * 2 + 0] = hA;
    reinterpret_cast<__half2*>(dst)[i * 2 + 1] = hB;
}

// ============================================================================
// GEMM mainloop: 128x128 tile, BK=64, 3-stage cp.async, 8 warps of 64x32,
// one barrier per K-chunk, 2 CTAs/SM.
// ============================================================================
constexpr int BM = 128, BN = 128, BK = 64;
constexpr int TILEB     = BM * 128;            // 16 KB
constexpr int STAGEB    = 2 * TILEB;           // 32 KB
constexpr int GEMM_SMEM = 3 * STAGEB;          // 96 KB

__device__ __forceinline__ void gemm_issue_loads(
    const __half* __restrict__ A,
    const __half* __restrict__ Bm,
    int m0, int n0, int kc, uint32_t abase, uint32_t bbase, int tid)
{
#pragma unroll
    for (int s = 0; s < 4; s++) {
        const int idx = tid + s * 256;
        const int r = idx >> 3;
        const int c = idx & 7;
        const uint32_t so = sw128((uint32_t)(r * 128 + c * 16));
        CP_ASYNC_16(abase + so, A  + (size_t)(m0 + r) * C_ + kc + c * 8);
        CP_ASYNC_16(bbase + so, Bm + (size_t)(n0 + r) * C_ + kc + c * 8);
    }
}

__device__ __forceinline__ void gemm_mainloop(
    const __half* __restrict__ A,
    const __half* __restrict__ Bm,
    int m0, int n0, uint32_t sbase, int tid, int wm, int wn, int lane,
    float (&acc)[4][4][4])
{
    const int NC = C_ / BK;   // 16

    gemm_issue_loads(A, Bm, m0, n0, 0, sbase, sbase + TILEB, tid);
    CP_ASYNC_COMMIT();
    gemm_issue_loads(A, Bm, m0, n0, BK,
                     sbase + STAGEB, sbase + STAGEB + TILEB, tid);
    CP_ASYNC_COMMIT();

    int stage = 0;
    for (int ch = 0; ch < NC; ch++) {
        if (ch < NC - 1) { CP_ASYNC_WAIT_1(); }
        else             { CP_ASYNC_WAIT_0(); }
        __syncthreads();

        if (ch + 2 < NC) {
            const int ns = (ch + 2) % 3;
            gemm_issue_loads(A, Bm, m0, n0, (ch + 2) * BK,
                             sbase + ns * STAGEB, sbase + ns * STAGEB + TILEB, tid);
            CP_ASYNC_COMMIT();
        }

        const uint32_t abase = sbase + stage * STAGEB;
        const uint32_t bbase = abase + TILEB;

#pragma unroll
        for (int ks = 0; ks < 4; ks++) {
            uint32_t afr[4][4];
#pragma unroll
            for (int mi = 0; mi < 4; mi++) {
                const int row = wm + mi * 16 + (lane & 15);
                const uint32_t off =
                    sw128((uint32_t)(row * 128 + ks * 32 + ((lane >> 4) & 1) * 16));
                ldsm_x4(afr[mi], abase + off);
            }
            uint32_t bfr[4][2];
#pragma unroll
            for (int np = 0; np < 2; np++) {
                const int row = wn + np * 16 + ((lane >> 4) & 1) * 8 + (lane & 7);
                const uint32_t off =
                    sw128((uint32_t)(row * 128 + ks * 32 + ((lane >> 3) & 1) * 16));
                uint32_t r4[4];
                ldsm_x4(r4, bbase + off);
                bfr[2 * np][0]     = r4[0]; bfr[2 * np][1]     = r4[1];
                bfr[2 * np + 1][0] = r4[2]; bfr[2 * np + 1][1] = r4[3];
            }
#pragma unroll
            for (int mi = 0; mi < 4; mi++)
#pragma unroll
                for (int ni = 0; ni < 4; ni++)
                    mma_f16(acc[mi][ni], afr[mi], bfr[ni]);
        }
        stage = (stage + 1) % 3;
    }
    __syncthreads();   // protect smem reuse by epilogues
}

// ============================================================================
// Output projection: att1 x wout1 -> fp32 out.
// ============================================================================
__global__ __launch_bounds__(256, 2)
void gemm_mma_kernel(const __half* __restrict__ A,
                     const __half* __restrict__ Bm,
                     float* __restrict__ Cm,
                     int M, int N)
{
    extern __shared__ char sm[];
    const int tid  = threadIdx.x;
    const int wid  = tid >> 5;
    const int lane = tid & 31;
    const int m0 = blockIdx.y * BM;
    const int n0 = blockIdx.x * BN;
    const int wm = (wid & 1) * 64;
    const int wn = (wid >> 1) * 32;

    float acc[4][4][4];
#pragma unroll
    for (int mi = 0; mi < 4; mi++)
#pragma unroll
        for (int ni = 0; ni < 4; ni++)
#pragma unroll
            for (int e = 0; e < 4; e++) acc[mi][ni][e] = 0.f;

    gemm_mainloop(A, Bm, m0, n0, smem_to_u32(sm), tid, wm, wn, lane, acc);

    const int g  = lane >> 2;
    const int tg = lane & 3;
#pragma unroll
    for (int mi = 0; mi < 4; mi++) {
#pragma unroll
        for (int ni = 0; ni < 4; ni++) {
            const int row = m0 + wm + mi * 16 + g;
            const int col = n0 + wn + ni * 8 + tg * 2;
            float2 p0; p0.x = acc[mi][ni][0]; p0.y = acc[mi][ni][1];
            float2 p1; p1.x = acc[mi][ni][2]; p1.y = acc[mi][ni][3];
            *reinterpret_cast<float2*>(&Cm[(size_t)row * N + col])       = p0;
            *reinterpret_cast<float2*>(&Cm[(size_t)(row + 8) * N + col]) = p1;
        }
    }
}

// ============================================================================
// Merged QKV projection (uniform K=1024) + fused attention prep. grid (24,64).
// ============================================================================
constexpr int SFS = 130;

__global__ __launch_bounds__(256, 2)
void gemm_qkv_fused_kernel(const __half* __restrict__ A,
                           const __half* __restrict__ Bm)
{
    extern __shared__ char sm[];
    const int tid  = threadIdx.x;
    const int wid  = tid >> 5;
    const int lane = tid & 31;
    const int m0 = blockIdx.y * BM;
    const int n0 = blockIdx.x * BN;          // 0..3071
    const int wm = (wid & 1) * 64;
    const int wn = (wid >> 1) * 32;
    const int region = n0 >> 10;             // 0=Q, 1=K, 2=V

    float acc[4][4][4];
#pragma unroll
    for (int mi = 0; mi < 4; mi++)
#pragma unroll
        for (int ni = 0; ni < 4; ni++)
#pragma unroll
            for (int e = 0; e < 4; e++) acc[mi][ni][e] = 0.f;

    gemm_mainloop(A, Bm, m0, n0, smem_to_u32(sm), tid, wm, wn, lane, acc);

    float* sf = reinterpret_cast<float*>(sm);
    const int g  = lane >> 2;
    const int tg = lane & 3;
#pragma unroll
    for (int mi = 0; mi < 4; mi++) {
#pragma unroll
        for (int ni = 0; ni < 4; ni++) {
            const int row = wm + mi * 16 + g;
            const int col = wn + ni * 8 + tg * 2;
            sf[row * SFS + col]           = acc[mi][ni][0];
            sf[row * SFS + col + 1]       = acc[mi][ni][1];
            sf[(row + 8) * SFS + col]     = acc[mi][ni][2];
            sf[(row + 8) * SFS + col + 1] = acc[mi][ni][3];
        }
    }
    __syncthreads();

    const int h2 = (n0 & 1023) >> 6;
    const int b  = m0 >> 11;
    const int t0 = m0 & 2047;
    const int w  = wid;

    if (region < 2) {
        __half* dst = (region == 0) ? g_qhi : g_khi;
        const float scl = (region == 0) ? 0.125f : 1.0f;
#pragma unroll
        for (int i = 0; i < 16; i++) {
            const int t = w * 16 + i;
#pragma unroll
            for (int hh = 0; hh < 2; hh++) {
                float2 v = *reinterpret_cast<float2*>(&sf[t * SFS + hh * 64 + lane * 2]);
                __half2 hi2 = __floats2half2_rn(v.x * scl, v.y * scl);
                const int bh = b * 16 + h2 + hh;
                const size_t off = ((size_t)bh * T_ + t0 + t) * DH_ + lane * 2;
                *reinterpret_cast<__half2*>(dst + off) = hi2;
            }
        }
    } else {
        // V: transposed [bh][d][t]
#pragma unroll
        for (int i = 0; i < 16; i++) {
            const int fd = w * 16 + i;
            const int hh = fd >> 6;
            const int d  = fd & 63;
            const int bh = b * 16 + h2 + hh;
            const size_t rowbase = ((size_t)bh * DH_ + d) * T_ + t0;
#pragma unroll
            for (int j = 0; j < 4; j++) {
                const int t = lane + 32 * j;
                g_vthi[rowbase + t] = __float2half_rn(sf[t * SFS + fd]);
            }
        }
    }
}

// ============================================================================
// Tensor-core flash attention (causal): single-fp16 QK^T and PV.
// smem: Q 16KB + 2 stages x (K 8KB + V 8KB) = 48KB.
// ============================================================================
constexpr int ATT_SMEM = 48 * 1024;
constexpr uint32_t OQ = 0, OKV = 16384, KVSTAGE = 16384;

__global__ __launch_bounds__(256, 2)
void attn_mma_kernel()
{
    extern __shared__ char sm[];
    const uint32_t sb = smem_to_u32(sm);

    const int tid  = threadIdx.x;
    const int w    = tid >> 5;
    const int lane = tid & 31;
    const int g    = lane >> 2;
    const int tq   = lane & 3;

    const int bh = blockIdx.y;
    const int b  = bh >> 4;
    const int h  = bh & 15;
    const int qt = gridDim.x - 1 - blockIdx.x;
    const int q0 = qt * 128;

    const __half* khg = g_khi + (size_t)bh * T_ * DH_;
    const __half* vhg = g_vthi + (size_t)bh * DH_ * T_;

    {
        const __half* qh = g_qhi + (size_t)(bh * T_ + q0) * DH_;
#pragma unroll
        for (int it = 0; it < 4; it++) {
            const int idx = tid + it * 256;
            const int r = idx >> 3;
            const int c = idx & 7;
            const uint32_t so = sw128((uint32_t)(r * 128 + c * 16));
            CP_ASYNC_16(sb + OQ + so, qh + (size_t)r * DH_ + c * 8);
        }
        CP_ASYNC_COMMIT();
    }
    {
        const uint32_t kvb = sb + OKV;
#pragma unroll
        for (int it = 0; it < 2; it++) {
            const int idx = tid + it * 256;
            const int r = idx >> 3;
            const int c = idx & 7;
            const uint32_t so = sw128((uint32_t)(r * 128 + c * 16));
            CP_ASYNC_16(kvb + so,        khg + (size_t)r * DH_ + c * 8);
            CP_ASYNC_16(kvb + 8192 + so, vhg + (size_t)r * T_ + c * 8);
        }
        CP_ASYNC_COMMIT();
    }

    float o[8][4];
#pragma unroll
    for (int ni = 0; ni < 8; ni++)
#pragma unroll
        for (int e = 0; e < 4; e++) o[ni][e] = 0.f;
    float m0 = -1e30f, m1 = -1e30f, l0 = 0.f, l1 = 0.f;

    const int row0 = q0 + 16 * w + g;
    const int kt_max = (q0 + 127) >> 6;

    for (int kt = 0; kt <= kt_max; kt++) {
        const int k0 = kt * 64;

        CP_ASYNC_WAIT_0();
        __syncthreads();

        if (kt + 1 <= kt_max) {
            const int nk0 = (kt + 1) * 64;
            const uint32_t kvb = sb + OKV + ((kt + 1) & 1) * KVSTAGE;
#pragma unroll
            for (int it = 0; it < 2; it++) {
                const int idx = tid + it * 256;
                const int r = idx >> 3;
                const int c = idx & 7;
                const uint32_t so = sw128((uint32_t)(r * 128 + c * 16));
                CP_ASYNC_16(kvb + so,        khg + (size_t)(nk0 + r) * DH_ + c * 8);
                CP_ASYNC_16(kvb + 8192 + so, vhg + (size_t)r * T_ + nk0 + c * 8);
            }
            CP_ASYNC_COMMIT();
        }

        const uint32_t kvb = sb + OKV + (kt & 1) * KVSTAGE;
        const uint32_t okh = kvb, ovh = kvb + 8192;

        const bool active = (k0 <= q0 + 16 * w + 15);
        if (active) {
            float s[8][4];
#pragma unroll
            for (int ni = 0; ni < 8; ni++)
#pragma unroll
                for (int e = 0; e < 4; e++) s[ni][e] = 0.f;

#pragma unroll
            for (int ks = 0; ks < 4; ks++) {
                uint32_t aqh[4];
                {
                    const int qr = 16 * w + (lane & 15);
                    const uint32_t off = sw128(
                        (uint32_t)(qr * 128 + ks * 32 + ((lane >> 4) & 1) * 16));
                    ldsm_x4(aqh, sb + OQ + off);
                }
                uint32_t bkh[8][2];
#pragma unroll
                for (int p = 0; p < 4; p++) {
                    const int kr = p * 16 + ((lane >> 4) & 1) * 8 + (lane & 7);
                    const uint32_t off = sw128(
                        (uint32_t)(kr * 128 + ks * 32 + ((lane >> 3) & 1) * 16));
                    uint32_t r4[4];
                    ldsm_x4(r4, okh + off);
                    bkh[2 * p][0] = r4[0]; bkh[2 * p][1] = r4[1];
                    bkh[2 * p + 1][0] = r4[2]; bkh[2 * p + 1][1] = r4[3];
                }
#pragma unroll
                for (int ni = 0; ni < 8; ni++)
                    mma_f16(s[ni], aqh, bkh[ni]);
            }

            if (k0 + 63 > q0 + 16 * w) {
#pragma unroll
                for (int ni = 0; ni < 8; ni++) {
                    const int kb = k0 + 8 * ni + 2 * tq;
                    if (kb     > row0)     s[ni][0] = -1e30f;
                    if (kb + 1 > row0)     s[ni][1] = -1e30f;
                    if (kb     > row0 + 8) s[ni][2] = -1e30f;
                    if (kb + 1 > row0 + 8) s[ni][3] = -1e30f;
                }
            }

            float mx0 = -1e30f, mx1 = -1e30f;
#pragma unroll
            for (int ni = 0; ni < 8; ni++) {
                mx0 = fmaxf(mx0, fmaxf(s[ni][0], s[ni][1]));
                mx1 = fmaxf(mx1, fmaxf(s[ni][2], s[ni][3]));
            }
            mx0 = fmaxf(mx0, __shfl_xor_sync(0xffffffffu, mx0, 1));
            mx0 = fmaxf(mx0, __shfl_xor_sync(0xffffffffu, mx0, 2));
            mx1 = fmaxf(mx1, __shfl_xor_sync(0xffffffffu, mx1, 1));
            mx1 = fmaxf(mx1, __shfl_xor_sync(0xffffffffu, mx1, 2));

            const float mn0 = fmaxf(m0, mx0);
            const float mn1 = fmaxf(m1, mx1);
            const float sc0 = __expf(m0 - mn0);
            const float sc1 = __expf(m1 - mn1);
            m0 = mn0; m1 = mn1;
            l0 *= sc0; l1 *= sc1;
#pragma unroll
            for (int ni = 0; ni < 8; ni++) {
                o[ni][0] *= sc0; o[ni][1] *= sc0;
                o[ni][2] *= sc1; o[ni][3] *= sc1;
            }

            uint32_t pH01[8], pH23[8];
#pragma unroll
            for (int ni = 0; ni < 8; ni++) {
                float p0 = __expf(s[ni][0] - mn0);
                float p1 = __expf(s[ni][1] - mn0);
                float p2 = __expf(s[ni][2] - mn1);
                float p3 = __expf(s[ni][3] - mn1);
                l0 += p0 + p1;
                l1 += p2 + p3;
                __half2 h01 = __floats2half2_rn(p0, p1);
                __half2 h23 = __floats2half2_rn(p2, p3);
                pH01[ni] = *reinterpret_cast<uint32_t*>(&h01);
                pH23[ni] = *reinterpret_cast<uint32_t*>(&h23);
            }

#pragma unroll
            for (int kg = 0; kg < 4; kg++) {
                uint32_t aph[4];
                aph[0] = pH01[2 * kg];     aph[1] = pH23[2 * kg];
                aph[2] = pH01[2 * kg + 1]; aph[3] = pH23[2 * kg + 1];

                uint32_t bvh[8][2];
#pragma unroll
                for (int p = 0; p < 4; p++) {
                    const int dr = p * 16 + ((lane >> 4) & 1) * 8 + (lane & 7);
                    const uint32_t off = sw128(
                        (uint32_t)(dr * 128 + kg * 32 + ((lane >> 3) & 1) * 16));
                    uint32_t r4[4];
                    ldsm_x4(r4, ovh + off);
                    bvh[2 * p][0] = r4[0]; bvh[2 * p][1] = r4[1];
                    bvh[2 * p + 1][0] = r4[2]; bvh[2 * p + 1][1] = r4[3];
                }
#pragma unroll
                for (int ni = 0; ni < 8; ni++)
                    mma_f16(o[ni], aph, bvh[ni]);
            }
        }
    }

    // ---- finalize: normalize, write single-fp16 att1
    l0 += __shfl_xor_sync(0xffffffffu, l0, 1);
    l0 += __shfl_xor_sync(0xffffffffu, l0, 2);
    l1 += __shfl_xor_sync(0xffffffffu, l1, 1);
    l1 += __shfl_xor_sync(0xffffffffu, l1, 2);
    const float inv0 = 1.f / l0;
    const float inv1 = 1.f / l1;

    const size_t rbase0 = (size_t)(b * T_ + row0) * C_ + h * DH_;
    const size_t rbase1 = rbase0 + (size_t)8 * C_;
#pragma unroll
    for (int ni = 0; ni < 8; ni++) {
        const int col = 8 * ni + 2 * tq;
        __half2 h01 = __floats2half2_rn(o[ni][0] * inv0, o[ni][1] * inv0);
        __half2 h23 = __floats2half2_rn(o[ni][2] * inv1, o[ni][3] * inv1);
        *reinterpret_cast<__half2*>(g_att1 + rbase0 + col) = h01;
        *reinterpret_cast<__half2*>(g_att1 + rbase1 + col) = h23;
    }
}

// ============================================================================
extern "C" void kernel_launch(void* const* d_in, const int* in_sizes, int n_in,
                              void* d_out, int out_size)
{
    const float* x     = (const float*)d_in[0];
    const float* w_qkv = (const float*)d_in[1];
    const float* w_out = (const float*)d_in[2];
    float*       out   = (float*)d_out;

    __half *x1, *att1, *wqkv1, *wout1;
    cudaGetSymbolAddress((void**)&x1,    g_x1);
    cudaGetSymbolAddress((void**)&att1,  g_att1);
    cudaGetSymbolAddress((void**)&wqkv1, g_wqkv1);
    cudaGetSymbolAddress((void**)&wout1, g_wout1);

    cudaFuncSetAttribute(gemm_mma_kernel,
                         cudaFuncAttributeMaxDynamicSharedMemorySize, GEMM_SMEM);
    cudaFuncSetAttribute(gemm_qkv_fused_kernel,
                         cudaFuncAttributeMaxDynamicSharedMemorySize, GEMM_SMEM);
    cudaFuncSetAttribute(attn_mma_kernel,
                         cudaFuncAttributeMaxDynamicSharedMemorySize, ATT_SMEM);

    // 0) single merged convert launch: x, w_qkv, w_out -> fp16
    {
        const int n4x  = (M_ * C_) / 4;
        const int n4wq = (N_QKV * C_) / 4;
        const int n4wo = (C_ * C_) / 4;
        const int total = n4x + n4wq + n4wo;
        convert_all_kernel<<<(total + 255) / 256, 256>>>(
            x, w_qkv, w_out, x1, wqkv1, wout1, n4x, n4wq, n4wo);
    }
    // 1) merged Q/K/V projection (uniform K=1024) + fused attention prep
    {
        dim3 grid(N_QKV / BN, M_ / BM);        // (24, 64)
        gemm_qkv_fused_kernel<<<grid, 256, GEMM_SMEM>>>(x1, wqkv1);
    }
    // 2) tensor-core causal attention -> att1 (single fp16)
    {
        dim3 grid(T_ / 128, BH_);
        attn_mma_kernel<<<grid, 256, ATT_SMEM>>>();
    }
    // 3) output projection (K=1024)
    {
        dim3 grid(C_ / BN, M_ / BM);
        gemm_mma_kernel<<<grid, 256, GEMM_SMEM>>>(att1, wout1, out, M_, C_);
    }
}

// round 17
// speedup vs baseline: 2.8894x; 1.0767x over previous
#include <cuda_runtime.h>
#include <cuda_fp16.h>
#include <cstdint>

// ============================================================================
// Problem constants
// ============================================================================
constexpr int B_    = 4;
constexpr int T_    = 2048;
constexpr int C_    = 1024;
constexpr int H_    = 16;
constexpr int DH_   = 64;
constexpr int M_    = B_ * T_;        // 8192
constexpr int N_QKV = 3 * C_;         // 3072
constexpr int BH_   = B_ * H_;        // 64

// ============================================================================
// Scratch (__device__ globals; no cudaMalloc allowed) — all single fp16
// ============================================================================
__device__ __half  g_x1[(size_t)M_ * C_];         // [8192,1024]
__device__ __half  g_att1[(size_t)M_ * C_];       // [8192,1024]
__device__ __half  g_wqkv1[(size_t)N_QKV * C_];   // [3072,1024]
__device__ __half  g_wout1[(size_t)C_ * C_];      // [1024,1024]
__device__ __half  g_qhi[(size_t)BH_ * T_ * DH_]; // [bh][t][d], pre-scaled
__device__ __half  g_khi[(size_t)BH_ * T_ * DH_];
__device__ __half  g_vthi[(size_t)BH_ * DH_ * T_]; // [bh][d][t]

// ============================================================================
// PTX helpers (base-ISA only)
// ============================================================================
__device__ __forceinline__ uint32_t smem_to_u32(const void* smem_ptr) {
    uint32_t addr;
    asm("{ .reg .u64 tmp; cvta.to.shared.u64 tmp, %1; cvt.u32.u64 %0, tmp; }"
        : "=r"(addr) : "l"(smem_ptr));
    return addr;
}
__device__ __forceinline__ void ldsm_x4(uint32_t (&r)[4], uint32_t addr) {
    asm volatile("ldmatrix.sync.aligned.m8n8.x4.shared.b16 {%0,%1,%2,%3}, [%4];"
        : "=r"(r[0]), "=r"(r[1]), "=r"(r[2]), "=r"(r[3]) : "r"(addr));
}
__device__ __forceinline__ void mma_f16(float (&d)[4],
                                        const uint32_t (&a)[4],
                                        const uint32_t (&b)[2]) {
    asm volatile(
        "mma.sync.aligned.m16n8k16.row.col.f32.f16.f16.f32 "
        "{%0,%1,%2,%3}, {%4,%5,%6,%7}, {%8,%9}, {%0,%1,%2,%3};"
        : "+f"(d[0]), "+f"(d[1]), "+f"(d[2]), "+f"(d[3])
        : "r"(a[0]), "r"(a[1]), "r"(a[2]), "r"(a[3]), "r"(b[0]), "r"(b[1]));
}
#define CP_ASYNC_16(dst_u32, src_ptr) \
    asm volatile("cp.async.cg.shared.global [%0], [%1], 16;" \
        :: "r"(dst_u32), "l"(src_ptr))
#define CP_ASYNC_COMMIT() asm volatile("cp.async.commit_group;" ::: "memory")
#define CP_ASYNC_WAIT_1() asm volatile("cp.async.wait_group 1;" ::: "memory")
#define CP_ASYNC_WAIT_0() asm volatile("cp.async.wait_group 0;" ::: "memory")

__device__ __forceinline__ uint32_t sw128(uint32_t off) {
    return off ^ ((off >> 3) & 0x70);
}

// ============================================================================
// Merged convert: x, w_qkv, w_out -> fp16 in ONE launch (by index range).
// ============================================================================
__global__ __launch_bounds__(256)
void convert_all_kernel(const float* __restrict__ x,
                        const float* __restrict__ wq,
                        const float* __restrict__ wo,
                        __half* __restrict__ x1,
                        __half* __restrict__ wq1,
                        __half* __restrict__ wo1,
                        int n4x, int n4wq, int n4wo)
{
    int i = blockIdx.x * blockDim.x + threadIdx.x;
    const float* src;
    __half* dst;
    if (i < n4x)               { src = x;  dst = x1; }
    else if (i < n4x + n4wq)   { src = wq; dst = wq1; i -= n4x; }
    else if (i < n4x + n4wq + n4wo) { src = wo; dst = wo1; i -= n4x + n4wq; }
    else return;

    float4 v = reinterpret_cast<const float4*>(src)[i];
    __half2 hA = __floats2half2_rn(v.x, v.y);
    __half2 hB = __floats2half2_rn(v.z, v.w);
    reinterpret_cast<__half2*>(dst)[i * 2 + 0] = hA;
    reinterpret_cast<__half2*>(dst)[i * 2 + 1] = hB;
}

// ============================================================================
// GEMM mainloop: 128x128 tile, BK=64, 3-stage cp.async, 8 warps of 64x32,
// one barrier per K-chunk, 2 CTAs/SM.
// ============================================================================
constexpr int BM = 128, BN = 128, BK = 64;
constexpr int TILEB     = BM * 128;            // 16 KB
constexpr int STAGEB    = 2 * TILEB;           // 32 KB
constexpr int GEMM_SMEM = 3 * STAGEB;          // 96 KB

__device__ __forceinline__ void gemm_issue_loads(
    const __half* __restrict__ A,
    const __half* __restrict__ Bm,
    int m0, int n0, int kc, uint32_t abase, uint32_t bbase, int tid)
{
#pragma unroll
    for (int s = 0; s < 4; s++) {
        const int idx = tid + s * 256;
        const int r = idx >> 3;
        const int c = idx & 7;
        const uint32_t so = sw128((uint32_t)(r * 128 + c * 16));
        CP_ASYNC_16(abase + so, A  + (size_t)(m0 + r) * C_ + kc + c * 8);
        CP_ASYNC_16(bbase + so, Bm + (size_t)(n0 + r) * C_ + kc + c * 8);
    }
}

__device__ __forceinline__ void gemm_mainloop(
    const __half* __restrict__ A,
    const __half* __restrict__ Bm,
    int m0, int n0, uint32_t sbase, int tid, int wm, int wn, int lane,
    float (&acc)[4][4][4])
{
    const int NC = C_ / BK;   // 16

    gemm_issue_loads(A, Bm, m0, n0, 0, sbase, sbase + TILEB, tid);
    CP_ASYNC_COMMIT();
    gemm_issue_loads(A, Bm, m0, n0, BK,
                     sbase + STAGEB, sbase + STAGEB + TILEB, tid);
    CP_ASYNC_COMMIT();

    int stage = 0;
    for (int ch = 0; ch < NC; ch++) {
        if (ch < NC - 1) { CP_ASYNC_WAIT_1(); }
        else             { CP_ASYNC_WAIT_0(); }
        __syncthreads();

        if (ch + 2 < NC) {
            const int ns = (ch + 2) % 3;
            gemm_issue_loads(A, Bm, m0, n0, (ch + 2) * BK,
                             sbase + ns * STAGEB, sbase + ns * STAGEB + TILEB, tid);
            CP_ASYNC_COMMIT();
        }

        const uint32_t abase = sbase + stage * STAGEB;
        const uint32_t bbase = abase + TILEB;

#pragma unroll
        for (int ks = 0; ks < 4; ks++) {
            uint32_t afr[4][4];
#pragma unroll
            for (int mi = 0; mi < 4; mi++) {
                const int row = wm + mi * 16 + (lane & 15);
                const uint32_t off =
                    sw128((uint32_t)(row * 128 + ks * 32 + ((lane >> 4) & 1) * 16));
                ldsm_x4(afr[mi], abase + off);
            }
            uint32_t bfr[4][2];
#pragma unroll
            for (int np = 0; np < 2; np++) {
                const int row = wn + np * 16 + ((lane >> 4) & 1) * 8 + (lane & 7);
                const uint32_t off =
                    sw128((uint32_t)(row * 128 + ks * 32 + ((lane >> 3) & 1) * 16));
                uint32_t r4[4];
                ldsm_x4(r4, bbase + off);
                bfr[2 * np][0]     = r4[0]; bfr[2 * np][1]     = r4[1];
                bfr[2 * np + 1][0] = r4[2]; bfr[2 * np + 1][1] = r4[3];
            }
#pragma unroll
            for (int mi = 0; mi < 4; mi++)
#pragma unroll
                for (int ni = 0; ni < 4; ni++)
                    mma_f16(acc[mi][ni], afr[mi], bfr[ni]);
        }
        stage = (stage + 1) % 3;
    }
    __syncthreads();   // protect smem reuse by epilogues
}

// ============================================================================
// Output projection: att1 x wout1 -> fp32 out.
// ============================================================================
__global__ __launch_bounds__(256, 2)
void gemm_mma_kernel(const __half* __restrict__ A,
                     const __half* __restrict__ Bm,
                     float* __restrict__ Cm,
                     int M, int N)
{
    extern __shared__ char sm[];
    const int tid  = threadIdx.x;
    const int wid  = tid >> 5;
    const int lane = tid & 31;
    const int m0 = blockIdx.y * BM;
    const int n0 = blockIdx.x * BN;
    const int wm = (wid & 1) * 64;
    const int wn = (wid >> 1) * 32;

    float acc[4][4][4];
#pragma unroll
    for (int mi = 0; mi < 4; mi++)
#pragma unroll
        for (int ni = 0; ni < 4; ni++)
#pragma unroll
            for (int e = 0; e < 4; e++) acc[mi][ni][e] = 0.f;

    gemm_mainloop(A, Bm, m0, n0, smem_to_u32(sm), tid, wm, wn, lane, acc);

    const int g  = lane >> 2;
    const int tg = lane & 3;
#pragma unroll
    for (int mi = 0; mi < 4; mi++) {
#pragma unroll
        for (int ni = 0; ni < 4; ni++) {
            const int row = m0 + wm + mi * 16 + g;
            const int col = n0 + wn + ni * 8 + tg * 2;
            float2 p0; p0.x = acc[mi][ni][0]; p0.y = acc[mi][ni][1];
            float2 p1; p1.x = acc[mi][ni][2]; p1.y = acc[mi][ni][3];
            *reinterpret_cast<float2*>(&Cm[(size_t)row * N + col])       = p0;
            *reinterpret_cast<float2*>(&Cm[(size_t)(row + 8) * N + col]) = p1;
        }
    }
}

// ============================================================================
// Merged QKV projection (uniform K=1024) + fused attention prep. grid (24,64).
// ============================================================================
constexpr int SFS = 130;

__global__ __launch_bounds__(256, 2)
void gemm_qkv_fused_kernel(const __half* __restrict__ A,
                           const __half* __restrict__ Bm)
{
    extern __shared__ char sm[];
    const int tid  = threadIdx.x;
    const int wid  = tid >> 5;
    const int lane = tid & 31;
    const int m0 = blockIdx.y * BM;
    const int n0 = blockIdx.x * BN;          // 0..3071
    const int wm = (wid & 1) * 64;
    const int wn = (wid >> 1) * 32;
    const int region = n0 >> 10;             // 0=Q, 1=K, 2=V

    float acc[4][4][4];
#pragma unroll
    for (int mi = 0; mi < 4; mi++)
#pragma unroll
        for (int ni = 0; ni < 4; ni++)
#pragma unroll
            for (int e = 0; e < 4; e++) acc[mi][ni][e] = 0.f;

    gemm_mainloop(A, Bm, m0, n0, smem_to_u32(sm), tid, wm, wn, lane, acc);

    float* sf = reinterpret_cast<float*>(sm);
    const int g  = lane >> 2;
    const int tg = lane & 3;
#pragma unroll
    for (int mi = 0; mi < 4; mi++) {
#pragma unroll
        for (int ni = 0; ni < 4; ni++) {
            const int row = wm + mi * 16 + g;
            const int col = wn + ni * 8 + tg * 2;
            sf[row * SFS + col]           = acc[mi][ni][0];
            sf[row * SFS + col + 1]       = acc[mi][ni][1];
            sf[(row + 8) * SFS + col]     = acc[mi][ni][2];
            sf[(row + 8) * SFS + col + 1] = acc[mi][ni][3];
        }
    }
    __syncthreads();

    const int h2 = (n0 & 1023) >> 6;
    const int b  = m0 >> 11;
    const int t0 = m0 & 2047;
    const int w  = wid;

    if (region < 2) {
        __half* dst = (region == 0) ? g_qhi : g_khi;
        const float scl = (region == 0) ? 0.125f : 1.0f;
#pragma unroll
        for (int i = 0; i < 16; i++) {
            const int t = w * 16 + i;
#pragma unroll
            for (int hh = 0; hh < 2; hh++) {
                float2 v = *reinterpret_cast<float2*>(&sf[t * SFS + hh * 64 + lane * 2]);
                __half2 hi2 = __floats2half2_rn(v.x * scl, v.y * scl);
                const int bh = b * 16 + h2 + hh;
                const size_t off = ((size_t)bh * T_ + t0 + t) * DH_ + lane * 2;
                *reinterpret_cast<__half2*>(dst + off) = hi2;
            }
        }
    } else {
        // V: transposed [bh][d][t] — paired __half2 stores (coalesced 4B/lane)
#pragma unroll
        for (int i = 0; i < 16; i++) {
            const int fd = w * 16 + i;
            const int hh = fd >> 6;
            const int d  = fd & 63;
            const int bh = b * 16 + h2 + hh;
            const size_t rowbase = ((size_t)bh * DH_ + d) * T_ + t0;
#pragma unroll
            for (int j = 0; j < 2; j++) {
                const int t2 = (lane + 32 * j) * 2;
                __half2 hp = __floats2half2_rn(sf[t2 * SFS + fd],
                                               sf[(t2 + 1) * SFS + fd]);
                *reinterpret_cast<__half2*>(g_vthi + rowbase + t2) = hp;
            }
        }
    }
}

// ============================================================================
// Tensor-core flash attention (causal): single-fp16 QK^T and PV.
// grid (BH, T/128) — blockIdx.y heavy-first => globally heavy-first dispatch.
// smem: Q 16KB + 2 stages x (K 8KB + V 8KB) = 48KB.
// ============================================================================
constexpr int ATT_SMEM = 48 * 1024;
constexpr uint32_t OQ = 0, OKV = 16384, KVSTAGE = 16384;

__global__ __launch_bounds__(256, 2)
void attn_mma_kernel()
{
    extern __shared__ char sm[];
    const uint32_t sb = smem_to_u32(sm);

    const int tid  = threadIdx.x;
    const int w    = tid >> 5;
    const int lane = tid & 31;
    const int g    = lane >> 2;
    const int tq   = lane & 3;

    const int bh = blockIdx.x;               // 0..63
    const int b  = bh >> 4;
    const int h  = bh & 15;
    const int qt = gridDim.y - 1 - blockIdx.y;   // globally heavy-first
    const int q0 = qt * 128;

    const __half* khg = g_khi + (size_t)bh * T_ * DH_;
    const __half* vhg = g_vthi + (size_t)bh * DH_ * T_;

    {
        const __half* qh = g_qhi + (size_t)(bh * T_ + q0) * DH_;
#pragma unroll
        for (int it = 0; it < 4; it++) {
            const int idx = tid + it * 256;
            const int r = idx >> 3;
            const int c = idx & 7;
            const uint32_t so = sw128((uint32_t)(r * 128 + c * 16));
            CP_ASYNC_16(sb + OQ + so, qh + (size_t)r * DH_ + c * 8);
        }
        CP_ASYNC_COMMIT();
    }
    {
        const uint32_t kvb = sb + OKV;
#pragma unroll
        for (int it = 0; it < 2; it++) {
            const int idx = tid + it * 256;
            const int r = idx >> 3;
            const int c = idx & 7;
            const uint32_t so = sw128((uint32_t)(r * 128 + c * 16));
            CP_ASYNC_16(kvb + so,        khg + (size_t)r * DH_ + c * 8);
            CP_ASYNC_16(kvb + 8192 + so, vhg + (size_t)r * T_ + c * 8);
        }
        CP_ASYNC_COMMIT();
    }

    float o[8][4];
#pragma unroll
    for (int ni = 0; ni < 8; ni++)
#pragma unroll
        for (int e = 0; e < 4; e++) o[ni][e] = 0.f;
    float m0 = -1e30f, m1 = -1e30f, l0 = 0.f, l1 = 0.f;

    const int row0 = q0 + 16 * w + g;
    const int kt_max = (q0 + 127) >> 6;

    for (int kt = 0; kt <= kt_max; kt++) {
        const int k0 = kt * 64;

        CP_ASYNC_WAIT_0();
        __syncthreads();

        if (kt + 1 <= kt_max) {
            const int nk0 = (kt + 1) * 64;
            const uint32_t kvb = sb + OKV + ((kt + 1) & 1) * KVSTAGE;
#pragma unroll
            for (int it = 0; it < 2; it++) {
                const int idx = tid + it * 256;
                const int r = idx >> 3;
                const int c = idx & 7;
                const uint32_t so = sw128((uint32_t)(r * 128 + c * 16));
                CP_ASYNC_16(kvb + so,        khg + (size_t)(nk0 + r) * DH_ + c * 8);
                CP_ASYNC_16(kvb + 8192 + so, vhg + (size_t)r * T_ + nk0 + c * 8);
            }
            CP_ASYNC_COMMIT();
        }

        const uint32_t kvb = sb + OKV + (kt & 1) * KVSTAGE;
        const uint32_t okh = kvb, ovh = kvb + 8192;

        const bool active = (k0 <= q0 + 16 * w + 15);
        if (active) {
            float s[8][4];
#pragma unroll
            for (int ni = 0; ni < 8; ni++)
#pragma unroll
                for (int e = 0; e < 4; e++) s[ni][e] = 0.f;

#pragma unroll
            for (int ks = 0; ks < 4; ks++) {
                uint32_t aqh[4];
                {
                    const int qr = 16 * w + (lane & 15);
                    const uint32_t off = sw128(
                        (uint32_t)(qr * 128 + ks * 32 + ((lane >> 4) & 1) * 16));
                    ldsm_x4(aqh, sb + OQ + off);
                }
                uint32_t bkh[8][2];
#pragma unroll
                for (int p = 0; p < 4; p++) {
                    const int kr = p * 16 + ((lane >> 4) & 1) * 8 + (lane & 7);
                    const uint32_t off = sw128(
                        (uint32_t)(kr * 128 + ks * 32 + ((lane >> 3) & 1) * 16));
                    uint32_t r4[4];
                    ldsm_x4(r4, okh + off);
                    bkh[2 * p][0] = r4[0]; bkh[2 * p][1] = r4[1];
                    bkh[2 * p + 1][0] = r4[2]; bkh[2 * p + 1][1] = r4[3];
                }
#pragma unroll
                for (int ni = 0; ni < 8; ni++)
                    mma_f16(s[ni], aqh, bkh[ni]);
            }

            if (k0 + 63 > q0 + 16 * w) {
#pragma unroll
                for (int ni = 0; ni < 8; ni++) {
                    const int kb = k0 + 8 * ni + 2 * tq;
                    if (kb     > row0)     s[ni][0] = -1e30f;
                    if (kb + 1 > row0)     s[ni][1] = -1e30f;
                    if (kb     > row0 + 8) s[ni][2] = -1e30f;
                    if (kb + 1 > row0 + 8) s[ni][3] = -1e30f;
                }
            }

            float mx0 = -1e30f, mx1 = -1e30f;
#pragma unroll
            for (int ni = 0; ni < 8; ni++) {
                mx0 = fmaxf(mx0, fmaxf(s[ni][0], s[ni][1]));
                mx1 = fmaxf(mx1, fmaxf(s[ni][2], s[ni][3]));
            }
            mx0 = fmaxf(mx0, __shfl_xor_sync(0xffffffffu, mx0, 1));
            mx0 = fmaxf(mx0, __shfl_xor_sync(0xffffffffu, mx0, 2));
            mx1 = fmaxf(mx1, __shfl_xor_sync(0xffffffffu, mx1, 1));
            mx1 = fmaxf(mx1, __shfl_xor_sync(0xffffffffu, mx1, 2));

            const float mn0 = fmaxf(m0, mx0);
            const float mn1 = fmaxf(m1, mx1);
            const float sc0 = __expf(m0 - mn0);
            const float sc1 = __expf(m1 - mn1);
            m0 = mn0; m1 = mn1;
            l0 *= sc0; l1 *= sc1;
#pragma unroll
            for (int ni = 0; ni < 8; ni++) {
                o[ni][0] *= sc0; o[ni][1] *= sc0;
                o[ni][2] *= sc1; o[ni][3] *= sc1;
            }

            uint32_t pH01[8], pH23[8];
#pragma unroll
            for (int ni = 0; ni < 8; ni++) {
                float p0 = __expf(s[ni][0] - mn0);
                float p1 = __expf(s[ni][1] - mn0);
                float p2 = __expf(s[ni][2] - mn1);
                float p3 = __expf(s[ni][3] - mn1);
                l0 += p0 + p1;
                l1 += p2 + p3;
                __half2 h01 = __floats2half2_rn(p0, p1);
                __half2 h23 = __floats2half2_rn(p2, p3);
                pH01[ni] = *reinterpret_cast<uint32_t*>(&h01);
                pH23[ni] = *reinterpret_cast<uint32_t*>(&h23);
            }

#pragma unroll
            for (int kg = 0; kg < 4; kg++) {
                uint32_t aph[4];
                aph[0] = pH01[2 * kg];     aph[1] = pH23[2 * kg];
                aph[2] = pH01[2 * kg + 1]; aph[3] = pH23[2 * kg + 1];

                uint32_t bvh[8][2];
#pragma unroll
                for (int p = 0; p < 4; p++) {
                    const int dr = p * 16 + ((lane >> 4) & 1) * 8 + (lane & 7);
                    const uint32_t off = sw128(
                        (uint32_t)(dr * 128 + kg * 32 + ((lane >> 3) & 1) * 16));
                    uint32_t r4[4];
                    ldsm_x4(r4, ovh + off);
                    bvh[2 * p][0] = r4[0]; bvh[2 * p][1] = r4[1];
                    bvh[2 * p + 1][0] = r4[2]; bvh[2 * p + 1][1] = r4[3];
                }
#pragma unroll
                for (int ni = 0; ni < 8; ni++)
                    mma_f16(o[ni], aph, bvh[ni]);
            }
        }
    }

    // ---- finalize: normalize, write single-fp16 att1
    l0 += __shfl_xor_sync(0xffffffffu, l0, 1);
    l0 += __shfl_xor_sync(0xffffffffu, l0, 2);
    l1 += __shfl_xor_sync(0xffffffffu, l1, 1);
    l1 += __shfl_xor_sync(0xffffffffu, l1, 2);
    const float inv0 = 1.f / l0;
    const float inv1 = 1.f / l1;

    const size_t rbase0 = (size_t)(b * T_ + row0) * C_ + h * DH_;
    const size_t rbase1 = rbase0 + (size_t)8 * C_;
#pragma unroll
    for (int ni = 0; ni < 8; ni++) {
        const int col = 8 * ni + 2 * tq;
        __half2 h01 = __floats2half2_rn(o[ni][0] * inv0, o[ni][1] * inv0);
        __half2 h23 = __floats2half2_rn(o[ni][2] * inv1, o[ni][3] * inv1);
        *reinterpret_cast<__half2*>(g_att1 + rbase0 + col) = h01;
        *reinterpret_cast<__half2*>(g_att1 + rbase1 + col) = h23;
    }
}

// ============================================================================
extern "C" void kernel_launch(void* const* d_in, const int* in_sizes, int n_in,
                              void* d_out, int out_size)
{
    const float* x     = (const float*)d_in[0];
    const float* w_qkv = (const float*)d_in[1];
    const float* w_out = (const float*)d_in[2];
    float*       out   = (float*)d_out;

    __half *x1, *att1, *wqkv1, *wout1;
    cudaGetSymbolAddress((void**)&x1,    g_x1);
    cudaGetSymbolAddress((void**)&att1,  g_att1);
    cudaGetSymbolAddress((void**)&wqkv1, g_wqkv1);
    cudaGetSymbolAddress((void**)&wout1, g_wout1);

    cudaFuncSetAttribute(gemm_mma_kernel,
                         cudaFuncAttributeMaxDynamicSharedMemorySize, GEMM_SMEM);
    cudaFuncSetAttribute(gemm_qkv_fused_kernel,
                         cudaFuncAttributeMaxDynamicSharedMemorySize, GEMM_SMEM);
    cudaFuncSetAttribute(attn_mma_kernel,
                         cudaFuncAttributeMaxDynamicSharedMemorySize, ATT_SMEM);

    // 0) single merged convert launch: x, w_qkv, w_out -> fp16
    {
        const int n4x  = (M_ * C_) / 4;
        const int n4wq = (N_QKV * C_) / 4;
        const int n4wo = (C_ * C_) / 4;
        const int total = n4x + n4wq + n4wo;
        convert_all_kernel<<<(total + 255) / 256, 256>>>(
            x, w_qkv, w_out, x1, wqkv1, wout1, n4x, n4wq, n4wo);
    }
    // 1) merged Q/K/V projection (uniform K=1024) + fused attention prep
    {
        dim3 grid(N_QKV / BN, M_ / BM);        // (24, 64)
        gemm_qkv_fused_kernel<<<grid, 256, GEMM_SMEM>>>(x1, wqkv1);
    }
    // 2) tensor-core causal attention -> att1 (globally heavy-first dispatch)
    {
        dim3 grid(BH_, T_ / 128);              // (64, 16)
        attn_mma_kernel<<<grid, 256, ATT_SMEM>>>();
    }
    // 3) output projection (K=1024)
    {
        dim3 grid(C_ / BN, M_ / BM);
        gemm_mma_kernel<<<grid, 256, GEMM_SMEM>>>(att1, wout1, out, M_, C_);
    }
}